// round 2
// baseline (speedup 1.0000x reference)
#include <cuda_runtime.h>
#include <math.h>

// ---------------------------------------------------------------------------
// GVP MPNN layer. B=4, N=2048, K=30.
// h_V: [8192,148]  (v:[3,16] flat c*16+i at [0..48), s:[100] at [48..148))
// h_M: [8192,30,183] (v:[3,17] c*17+i at [0..51), s:[132] at [51..183))
// Pipeline:
//   K1 (persistent, weights in SMEM): per node, loop k: build h_EV,
//      GVP1(33v/232s -> 16v/100s), GVP2, GVP3(no act), mask, mean/30,
//      residual + GVP-LN1 -> g_hv
//   K2: GVP_dh1(16v/100s -> 32v/400s, act) -> g_t
//   K3: GVP_dh2(32v/400s -> 16v/100s, no act) + residual + LN2 + mask -> out
// ---------------------------------------------------------------------------

#define NT 256
constexpr int NODES = 4 * 2048;
constexpr int KNB   = 30;

__device__ float g_hv[NODES * 148];
__device__ float g_t [NODES * 496];

// Generic GVP on shared buffers. Layouts:
//  vcur: [3*NVI] (c*NVI+i), scat: input scalars [0..NSI), vn appended at [NSI..NSI+NH)
//  After call: vcur[0..3*NVO) = output vectors (gated if ACT),
//              scat[0..NSO)   = output scalars (relu'd if ACT)
template<int NVI,int NH,int NSI,int NSO,int NVO,bool ACT>
__device__ __forceinline__ void gvp_block(
    const float* __restrict__ Wh, const float* __restrict__ Ws,
    const float* __restrict__ Bs, const float* __restrict__ Wv,
    float* vcur, float* scat, float* vh, float* sred, float* vraw,
    float* gate, float* snew, int tid)
{
  // vh[c,h] = sum_i vcur[c,i] * Wh[i,h]
  for (int t = tid; t < 3 * NH; t += NT) {
    int c = t / NH, h = t - c * NH;
    float acc = 0.f;
    #pragma unroll
    for (int i = 0; i < NVI; ++i) acc += vcur[c * NVI + i] * Wh[i * NH + h];
    vh[t] = acc;
  }
  __syncthreads();
  // vn -> scat[NSI+h];  vraw[c,o] = sum_h vh[c,h]*Wv[h,o]
  for (int t = tid; t < NH + 3 * NVO; t += NT) {
    if (t < NH) {
      float a = vh[t], b = vh[NH + t], c = vh[2 * NH + t];
      scat[NSI + t] = sqrtf(fmaxf(a * a + b * b + c * c, 1e-8f));
    } else {
      int idx = t - NH; int c = idx / NVO, o = idx - c * NVO;
      float acc = 0.f;
      #pragma unroll
      for (int h = 0; h < NH; ++h) acc += vh[c * NH + h] * Wv[h * NVO + o];
      vraw[idx] = acc;
    }
  }
  __syncthreads();
  // s GEMM: 2-way split over input dim D per output
  constexpr int D  = NSI + NH;
  constexpr int H0 = D / 2;
  for (int t = tid; t < 2 * NSO; t += NT) {
    int o = t >> 1; int half = t & 1;
    int i0 = half ? H0 : 0;
    int i1 = half ? D  : H0;
    float acc = 0.f;
    const float* wp = Ws + o;
    #pragma unroll 4
    for (int i = i0; i < i1; ++i) acc += scat[i] * wp[i * NSO];
    sred[t] = acc;
  }
  __syncthreads();
  // combine + bias (+relu); gate = sigmoid(||vraw col||)
  for (int t = tid; t < NSO + (ACT ? NVO : 0); t += NT) {
    if (t < NSO) {
      float s = sred[2 * t] + sred[2 * t + 1] + Bs[t];
      if (ACT) s = fmaxf(s, 0.f);
      snew[t] = s;
    } else {
      int o = t - NSO;
      float a = vraw[o], b = vraw[NVO + o], c = vraw[2 * NVO + o];
      float n = sqrtf(fmaxf(a * a + b * b + c * c, 1e-8f));
      gate[o] = 1.f / (1.f + expf(-n));
    }
  }
  __syncthreads();
  // writeback into vcur / scat for next stage
  for (int t = tid; t < 3 * NVO + NSO; t += NT) {
    if (t < 3 * NVO) vcur[t] = ACT ? vraw[t] * gate[t % NVO] : vraw[t];
    else             scat[t - 3 * NVO] = snew[t - 3 * NVO];
  }
  __syncthreads();
}

// ------------------------------ K1: edges + mean + LN1 ---------------------
__global__ __launch_bounds__(NT, 1)
void k_edge(const float* __restrict__ hV, const float* __restrict__ hM,
            const int* __restrict__ maskA,
            const float* wh1, const float* ws1, const float* bs1, const float* wv1,
            const float* wh2, const float* ws2, const float* bs2, const float* wv2,
            const float* wh3, const float* ws3, const float* bs3, const float* wv3,
            const float* __restrict__ ln1g, const float* __restrict__ ln1b)
{
  extern __shared__ float sm[];
  float* WH1 = sm;            float* WS1 = WH1 + 1089;  float* WV1 = WS1 + 26500; float* BS1 = WV1 + 528;
  float* WH2 = BS1 + 100;     float* WS2 = WH2 + 256;   float* WV2 = WS2 + 11600; float* BS2 = WV2 + 256;
  float* WH3 = BS2 + 100;     float* WS3 = WH3 + 256;   float* WV3 = WS3 + 11600; float* BS3 = WV3 + 256;
  float* HS  = BS3 + 100;     float* DH  = HS + 148;    float* EB  = DH + 148;
  float* VCUR= EB + 183;      float* VH  = VCUR + 99;   float* SCAT= VH + 99;     float* SRED= SCAT + 265;
  float* VRAW= SRED + 200;    float* GATE= VRAW + 48;   float* SNEW= GATE + 16;   float* MISC= SNEW + 100;
  int tid = threadIdx.x;

  for (int i = tid; i < 1089;  i += NT) WH1[i] = wh1[i];
  for (int i = tid; i < 26500; i += NT) WS1[i] = ws1[i];
  for (int i = tid; i < 528;   i += NT) WV1[i] = wv1[i];
  for (int i = tid; i < 100;   i += NT) BS1[i] = bs1[i];
  for (int i = tid; i < 256;   i += NT) WH2[i] = wh2[i];
  for (int i = tid; i < 11600; i += NT) WS2[i] = ws2[i];
  for (int i = tid; i < 256;   i += NT) WV2[i] = wv2[i];
  for (int i = tid; i < 100;   i += NT) BS2[i] = bs2[i];
  for (int i = tid; i < 256;   i += NT) WH3[i] = wh3[i];
  for (int i = tid; i < 11600; i += NT) WS3[i] = ws3[i];
  for (int i = tid; i < 256;   i += NT) WV3[i] = wv3[i];
  for (int i = tid; i < 100;   i += NT) BS3[i] = bs3[i];
  __syncthreads();

  for (int node = blockIdx.x; node < NODES; node += gridDim.x) {
    for (int t = tid; t < 148; t += NT) { HS[t] = hV[node * 148 + t]; DH[t] = 0.f; }
    __syncthreads();

    for (int k = 0; k < KNB; ++k) {
      const float* ep = hM + (size_t)(node * KNB + k) * 183;
      for (int t = tid; t < 183; t += NT) EB[t] = ep[t];
      __syncthreads();
      // h_EV: v = [v_V(16), v_M(17)] per c; s = [s_V(100), s_M(132)]
      for (int t = tid; t < 99 + 232; t += NT) {
        if (t < 99) {
          int c = t / 33, i = t - c * 33;
          VCUR[t] = (i < 16) ? HS[c * 16 + i] : EB[c * 17 + (i - 16)];
        } else {
          int j = t - 99;
          SCAT[j] = (j < 100) ? HS[48 + j] : EB[51 + (j - 100)];
        }
      }
      __syncthreads();

      gvp_block<33, 33, 232, 100, 16, true >(WH1, WS1, BS1, WV1, VCUR, SCAT, VH, SRED, VRAW, GATE, SNEW, tid);
      gvp_block<16, 16, 100, 100, 16, true >(WH2, WS2, BS2, WV2, VCUR, SCAT, VH, SRED, VRAW, GATE, SNEW, tid);
      gvp_block<16, 16, 100, 100, 16, false>(WH3, WS3, BS3, WV3, VCUR, SCAT, VH, SRED, VRAW, GATE, SNEW, tid);

      float mk = (float)maskA[node * KNB + k];
      for (int t = tid; t < 148; t += NT)
        DH[t] += mk * (t < 48 ? VCUR[t] : SCAT[t - 48]);
      __syncthreads();
    }

    // x = h_V + mean_k(m); GVP-LayerNorm 1
    for (int t = tid; t < 148; t += NT) DH[t] = HS[t] + DH[t] * (1.f / KNB);
    __syncthreads();
    if (tid == 0) {
      float vm = 0.f;
      for (int i = 0; i < 16; ++i) {
        float a = DH[i], b = DH[16 + i], c = DH[32 + i];
        vm += fmaxf(a * a + b * b + c * c, 1e-8f);
      }
      MISC[0] = rsqrtf(vm * (1.f / 16.f));
      float mu = 0.f;
      for (int j = 0; j < 100; ++j) mu += DH[48 + j];
      mu *= 0.01f;
      float var = 0.f;
      for (int j = 0; j < 100; ++j) { float d = DH[48 + j] - mu; var += d * d; }
      var *= 0.01f;
      MISC[1] = mu; MISC[2] = rsqrtf(var + 1e-3f);
    }
    __syncthreads();
    for (int t = tid; t < 148; t += NT) {
      float v;
      if (t < 48) v = DH[t] * MISC[0];
      else { int j = t - 48; v = (DH[t] - MISC[1]) * MISC[2] * ln1g[j] + ln1b[j]; }
      g_hv[node * 148 + t] = v;
    }
    __syncthreads();
  }
}

// ------------------------------ K2: node GVP dh1 ---------------------------
__global__ __launch_bounds__(NT, 1)
void k_dh1(const float* wh, const float* ws, const float* bs, const float* wv)
{
  extern __shared__ float sm[];
  float* WH = sm;          float* WS = WH + 512;    float* BSH = WS + 52800; float* WV = BSH + 400;
  float* VCUR = WV + 1024; float* VH = VCUR + 96;   float* SCAT = VH + 96;   float* SRED = SCAT + 432;
  float* VRAW = SRED + 800;float* GATE = VRAW + 96; float* SNEW = GATE + 32;
  int tid = threadIdx.x;
  for (int i = tid; i < 512;   i += NT) WH[i]  = wh[i];
  for (int i = tid; i < 52800; i += NT) WS[i]  = ws[i];
  for (int i = tid; i < 400;   i += NT) BSH[i] = bs[i];
  for (int i = tid; i < 1024;  i += NT) WV[i]  = wv[i];
  __syncthreads();

  for (int node = blockIdx.x; node < NODES; node += gridDim.x) {
    for (int t = tid; t < 148; t += NT) {
      float v = g_hv[node * 148 + t];
      if (t < 48) VCUR[t] = v; else SCAT[t - 48] = v;
    }
    __syncthreads();
    gvp_block<16, 32, 100, 400, 32, true>(WH, WS, BSH, WV, VCUR, SCAT, VH, SRED, VRAW, GATE, SNEW, tid);
    for (int t = tid; t < 496; t += NT)
      g_t[node * 496 + t] = (t < 96) ? VCUR[t] : SCAT[t - 96];
    __syncthreads();
  }
}

// ------------------------------ K3: node GVP dh2 + LN2 + mask --------------
__global__ __launch_bounds__(NT, 1)
void k_dh2(const float* wh, const float* ws, const float* bs, const float* wv,
           const float* __restrict__ ln2g, const float* __restrict__ ln2b,
           const int* __restrict__ maskV, float* __restrict__ out)
{
  extern __shared__ float sm[];
  float* WH = sm;           float* WS = WH + 1024;  float* BSH = WS + 43200; float* WV = BSH + 100;
  float* HVB = WV + 512;    float* VCUR = HVB + 148;float* VH = VCUR + 96;   float* SCAT = VH + 96;
  float* SRED = SCAT + 432; float* VRAW = SRED + 200;float* GATE = VRAW + 48; float* SNEW = GATE + 16;
  float* MISC = SNEW + 100;
  int tid = threadIdx.x;
  for (int i = tid; i < 1024;  i += NT) WH[i]  = wh[i];
  for (int i = tid; i < 43200; i += NT) WS[i]  = ws[i];
  for (int i = tid; i < 100;   i += NT) BSH[i] = bs[i];
  for (int i = tid; i < 512;   i += NT) WV[i]  = wv[i];
  __syncthreads();

  for (int node = blockIdx.x; node < NODES; node += gridDim.x) {
    for (int t = tid; t < 148; t += NT) HVB[t] = g_hv[node * 148 + t];
    for (int t = tid; t < 496; t += NT) {
      float v = g_t[node * 496 + t];
      if (t < 96) VCUR[t] = v; else SCAT[t - 96] = v;
    }
    __syncthreads();
    gvp_block<32, 32, 400, 100, 16, false>(WH, WS, BSH, WV, VCUR, SCAT, VH, SRED, VRAW, GATE, SNEW, tid);
    for (int t = tid; t < 148; t += NT)
      HVB[t] += (t < 48) ? VCUR[t] : SCAT[t - 48];
    __syncthreads();
    if (tid == 0) {
      float vm = 0.f;
      for (int i = 0; i < 16; ++i) {
        float a = HVB[i], b = HVB[16 + i], c = HVB[32 + i];
        vm += fmaxf(a * a + b * b + c * c, 1e-8f);
      }
      MISC[0] = rsqrtf(vm * (1.f / 16.f));
      float mu = 0.f;
      for (int j = 0; j < 100; ++j) mu += HVB[48 + j];
      mu *= 0.01f;
      float var = 0.f;
      for (int j = 0; j < 100; ++j) { float d = HVB[48 + j] - mu; var += d * d; }
      var *= 0.01f;
      MISC[1] = mu; MISC[2] = rsqrtf(var + 1e-3f);
    }
    __syncthreads();
    float mk = (float)maskV[node];
    for (int t = tid; t < 148; t += NT) {
      float v;
      if (t < 48) v = HVB[t] * MISC[0];
      else { int j = t - 48; v = (HVB[t] - MISC[1]) * MISC[2] * ln2g[j] + ln2b[j]; }
      out[node * 148 + t] = mk * v;
    }
    __syncthreads();
  }
}

// ---------------------------------------------------------------------------
extern "C" void kernel_launch(void* const* d_in, const int* in_sizes, int n_in,
                              void* d_out, int out_size)
{
  const float* hV     = (const float*)d_in[0];
  const float* hM     = (const float*)d_in[1];
  const int*   maskV  = (const int*)  d_in[2];
  const int*   maskA  = (const int*)  d_in[3];
  const float* wev1_wh = (const float*)d_in[4];
  const float* wev1_ws = (const float*)d_in[5];
  const float* wev1_bs = (const float*)d_in[6];
  const float* wev1_wv = (const float*)d_in[7];
  const float* wev2_wh = (const float*)d_in[8];
  const float* wev2_ws = (const float*)d_in[9];
  const float* wev2_bs = (const float*)d_in[10];
  const float* wev2_wv = (const float*)d_in[11];
  const float* wev3_wh = (const float*)d_in[12];
  const float* wev3_ws = (const float*)d_in[13];
  const float* wev3_bs = (const float*)d_in[14];
  const float* wev3_wv = (const float*)d_in[15];
  const float* wdh1_wh = (const float*)d_in[16];
  const float* wdh1_ws = (const float*)d_in[17];
  const float* wdh1_bs = (const float*)d_in[18];
  const float* wdh1_wv = (const float*)d_in[19];
  const float* wdh2_wh = (const float*)d_in[20];
  const float* wdh2_ws = (const float*)d_in[21];
  const float* wdh2_bs = (const float*)d_in[22];
  const float* wdh2_wv = (const float*)d_in[23];
  const float* ln1g = (const float*)d_in[24];
  const float* ln1b = (const float*)d_in[25];
  const float* ln2g = (const float*)d_in[26];
  const float* ln2b = (const float*)d_in[27];
  float* out = (float*)d_out;

  int dev = 0; cudaGetDevice(&dev);
  int sms = 148;
  cudaDeviceGetAttribute(&sms, cudaDevAttrMultiProcessorCount, dev);

  // SMEM sizes (floats) matching the in-kernel layouts
  const size_t SM1 = (size_t)(52641 + 148 + 148 + 183 + 99 + 99 + 265 + 200 + 48 + 16 + 100 + 8) * sizeof(float);
  const size_t SM2 = (size_t)(54736 + 96 + 96 + 432 + 800 + 96 + 32 + 400) * sizeof(float);
  const size_t SM3 = (size_t)(44836 + 148 + 96 + 96 + 432 + 200 + 48 + 16 + 100 + 8) * sizeof(float);

  cudaFuncSetAttribute(k_edge, cudaFuncAttributeMaxDynamicSharedMemorySize, (int)SM1);
  cudaFuncSetAttribute(k_dh1,  cudaFuncAttributeMaxDynamicSharedMemorySize, (int)SM2);
  cudaFuncSetAttribute(k_dh2,  cudaFuncAttributeMaxDynamicSharedMemorySize, (int)SM3);

  k_edge<<<sms, NT, SM1>>>(hV, hM, maskA,
                           wev1_wh, wev1_ws, wev1_bs, wev1_wv,
                           wev2_wh, wev2_ws, wev2_bs, wev2_wv,
                           wev3_wh, wev3_ws, wev3_bs, wev3_wv,
                           ln1g, ln1b);
  k_dh1<<<sms, NT, SM2>>>(wdh1_wh, wdh1_ws, wdh1_bs, wdh1_wv);
  k_dh2<<<sms, NT, SM3>>>(wdh2_wh, wdh2_ws, wdh2_bs, wdh2_wv,
                          ln2g, ln2b, maskV, out);
}

// round 3
// speedup vs baseline: 3.3475x; 3.3475x over previous
#include <cuda_runtime.h>
#include <math.h>

#define NT 256
constexpr int NODES = 4 * 2048;

__device__ float g_hv[NODES * 148];
__device__ float g_t [NODES * 496];   // [tile of 32 nodes][496 rows][32]

// out[c][rg..rg+3][e] = init + sum_k A[(c*ARS+k)*32+e] * W[k*WSTR + row]
// Thread: 4 rows x 4 edges. eg=(tid&7)*4, g=tid>>3 (+32 stride).
template<int KD,int NROW,int NC,int ARS,int WSTR,bool WG,bool INITF,bool BIASF,bool RELUF>
__device__ __forceinline__ void gemm_rt(
    const float* __restrict__ A, const float* __restrict__ W,
    const float* __restrict__ initv, const float* __restrict__ bias,
    float* __restrict__ O, const int tid)
{
  constexpr int GPC = NROW / 4;
  constexpr int G   = NC * GPC;
  const int eg = (tid & 7) * 4;
  for (int g = tid >> 3; g < G; g += 32) {
    const int c  = g / GPC;
    const int rg = (g - c * GPC) * 4;
    float4 a0, a1, a2, a3;
    if (INITF) {
      const float* iv = initv + c * NROW + rg;
      a0 = make_float4(iv[0], iv[0], iv[0], iv[0]);
      a1 = make_float4(iv[1], iv[1], iv[1], iv[1]);
      a2 = make_float4(iv[2], iv[2], iv[2], iv[2]);
      a3 = make_float4(iv[3], iv[3], iv[3], iv[3]);
    } else {
      a0 = make_float4(0.f,0.f,0.f,0.f); a1 = a0; a2 = a0; a3 = a0;
    }
    const float* ap = A + (size_t)(c * ARS) * 32 + eg;
    const float* wp = W + rg;
    #pragma unroll 4
    for (int k = 0; k < KD; ++k) {
      const float4 av = *(const float4*)(ap + (size_t)k * 32);
      float4 wv4;
      if (WG) wv4 = __ldg(reinterpret_cast<const float4*>(wp + (size_t)k * WSTR));
      else    wv4 = *(const float4*)(wp + (size_t)k * WSTR);
      a0.x += wv4.x*av.x; a0.y += wv4.x*av.y; a0.z += wv4.x*av.z; a0.w += wv4.x*av.w;
      a1.x += wv4.y*av.x; a1.y += wv4.y*av.y; a1.z += wv4.y*av.z; a1.w += wv4.y*av.w;
      a2.x += wv4.z*av.x; a2.y += wv4.z*av.y; a2.z += wv4.z*av.z; a2.w += wv4.z*av.w;
      a3.x += wv4.w*av.x; a3.y += wv4.w*av.y; a3.z += wv4.w*av.z; a3.w += wv4.w*av.w;
    }
    if (BIASF) {
      const float* bp = bias + c * NROW + rg;
      float b0=bp[0], b1=bp[1], b2=bp[2], b3=bp[3];
      a0.x+=b0; a0.y+=b0; a0.z+=b0; a0.w+=b0;
      a1.x+=b1; a1.y+=b1; a1.z+=b1; a1.w+=b1;
      a2.x+=b2; a2.y+=b2; a2.z+=b2; a2.w+=b2;
      a3.x+=b3; a3.y+=b3; a3.z+=b3; a3.w+=b3;
    }
    if (RELUF) {
      a0.x=fmaxf(a0.x,0.f); a0.y=fmaxf(a0.y,0.f); a0.z=fmaxf(a0.z,0.f); a0.w=fmaxf(a0.w,0.f);
      a1.x=fmaxf(a1.x,0.f); a1.y=fmaxf(a1.y,0.f); a1.z=fmaxf(a1.z,0.f); a1.w=fmaxf(a1.w,0.f);
      a2.x=fmaxf(a2.x,0.f); a2.y=fmaxf(a2.y,0.f); a2.z=fmaxf(a2.z,0.f); a2.w=fmaxf(a2.w,0.f);
      a3.x=fmaxf(a3.x,0.f); a3.y=fmaxf(a3.y,0.f); a3.z=fmaxf(a3.z,0.f); a3.w=fmaxf(a3.w,0.f);
    }
    float* op = O + (size_t)(c * NROW + rg) * 32 + eg;
    *(float4*)(op)      = a0;
    *(float4*)(op + 32) = a1;
    *(float4*)(op + 64) = a2;
    *(float4*)(op + 96) = a3;
  }
}

// ------------------------------ K1: edges + mean + LN1 ---------------------
__global__ __launch_bounds__(NT, 1)
void k_edge(const float* __restrict__ hV, const float* __restrict__ hM,
            const int* __restrict__ maskA,
            const float* __restrict__ wh1, const float* __restrict__ ws1,
            const float* __restrict__ bs1, const float* __restrict__ wv1,
            const float* __restrict__ wh2, const float* __restrict__ ws2,
            const float* __restrict__ bs2, const float* __restrict__ wv2,
            const float* __restrict__ wh3, const float* __restrict__ ws3,
            const float* __restrict__ bs3, const float* __restrict__ wv3,
            const float* __restrict__ ln1g, const float* __restrict__ ln1b)
{
  extern __shared__ float sm[];
  float* WH1P = sm;                 // [33][36] padded
  float* WS1  = WH1P + 1188;        // 26500
  float* WV1  = WS1 + 26500;        // 528
  float* BS1s = WV1 + 528;          // 100
  float* WH2s = BS1s + 100;         // 256
  float* WV2s = WH2s + 256;         // 256
  float* BS2s = WV2s + 256;         // 100
  float* WH3s = BS2s + 100;         // 256
  float* WV3s = WH3s + 256;         // 256
  float* BS3s = WV3s + 256;         // 100
  float* LG1  = BS3s + 100;         // 100
  float* LB1  = LG1 + 100;          // 100
  float* HS   = LB1 + 100;          // 148
  float* MK   = HS + 148;           // 32
  float* SB   = MK + 32;            // 100
  float* VB   = SB + 100;           // 108
  float* VC1  = VB + 108;           // 51*32
  float* SC1  = VC1 + 1632;         // 165*32
  float* VHX  = SC1 + 5280;         // 108*32 (also staging alias)
  float* BFA  = VHX + 3456;         // 116*32
  float* BFB  = BFA + 3712;         // 116*32
  float* VOA  = BFB + 3712;         // 48*32
  float* VOB  = VOA + 1536;         // 48*32
  float* DH   = VOB + 1536;         // 148
  float* MISC = DH + 148;           // 8
  float* EB   = VHX;                // staging 5490 (aliases VHX+BFA)
  const int tid = threadIdx.x;

  for (int i = tid; i < 1188; i += NT) { int r = i / 36, c = i - r * 36; WH1P[i] = (c < 33) ? wh1[r * 33 + c] : 0.f; }
  for (int i = tid; i < 26500; i += NT) WS1[i]  = ws1[i];
  for (int i = tid; i < 528;   i += NT) WV1[i]  = wv1[i];
  for (int i = tid; i < 100;   i += NT) { BS1s[i] = bs1[i]; BS2s[i] = bs2[i]; BS3s[i] = bs3[i]; LG1[i] = ln1g[i]; LB1[i] = ln1b[i]; }
  for (int i = tid; i < 256;   i += NT) { WH2s[i] = wh2[i]; WV2s[i] = wv2[i]; WH3s[i] = wh3[i]; WV3s[i] = wv3[i]; }
  // zero-pad edge columns 30,31 (never rewritten)
  for (int i = tid; i < 51 * 2;  i += NT) { int r = i >> 1; VC1[r * 32 + 30 + (i & 1)] = 0.f; }
  for (int i = tid; i < 132 * 2; i += NT) { int r = i >> 1; SC1[r * 32 + 30 + (i & 1)] = 0.f; }
  __syncthreads();

  for (int node = blockIdx.x; node < NODES; node += gridDim.x) {
    const float* mp = hM + (size_t)node * 5490;
    for (int t = tid; t < 5490; t += NT) EB[t] = mp[t];
    for (int t = tid; t < 148; t += NT) HS[t] = hV[node * 148 + t];
    for (int t = tid; t < 32;  t += NT) MK[t] = (t < 30) ? (float)maskA[node * 30 + t] : 0.f;
    __syncthreads();
    // transpose staging -> VC1/SC1 ; hoisted partials SB/VB
    for (int idx = tid; idx < 183 * 32; idx += NT) {
      int j = idx >> 5, e = idx & 31;
      if (e < 30) {
        float v = EB[e * 183 + j];
        if (j < 51) VC1[j * 32 + e] = v;
        else        SC1[(j - 51) * 32 + e] = v;
      }
    }
    for (int t = tid; t < 208; t += NT) {
      if (t < 100) {
        float acc = 0.f;
        #pragma unroll 4
        for (int j = 0; j < 100; ++j) acc += HS[48 + j] * WS1[j * 100 + t];
        SB[t] = acc;
      } else {
        int u = t - 100, c = u / 36, h = u - c * 36;
        float acc = 0.f;
        if (h < 33) {
          #pragma unroll
          for (int i = 0; i < 16; ++i) acc += HS[c * 16 + i] * WH1P[i * 36 + h];
        }
        VB[u] = acc;
      }
    }
    __syncthreads();
    // GVP1
    gemm_rt<17,36,3,17,36,false,true,false,false>(VC1, WH1P + 16 * 36, VB, nullptr, VHX, tid);
    __syncthreads();
    for (int t = tid; t < 33 * 32; t += NT) {
      int h = t >> 5, e = t & 31;
      float a = VHX[h*32+e], b = VHX[(36+h)*32+e], c2 = VHX[(72+h)*32+e];
      SC1[(132 + h) * 32 + e] = sqrtf(fmaxf(a*a + b*b + c2*c2, 1e-8f));
    }
    __syncthreads();
    gemm_rt<165,100,1,0,100,false,true,true,true>(SC1, WS1 + 100 * 100, SB, BS1s, BFA, tid);
    gemm_rt<33,16,3,36,16,false,false,false,false>(VHX, WV1, nullptr, nullptr, VOA, tid);
    __syncthreads();
    for (int t = tid; t < 16 * 32; t += NT) {
      int o = t >> 5, e = t & 31;
      float a = VOA[o*32+e], b = VOA[(16+o)*32+e], c2 = VOA[(32+o)*32+e];
      float n = sqrtf(fmaxf(a*a + b*b + c2*c2, 1e-8f));
      float gt = 1.f / (1.f + expf(-n));
      VOA[o*32+e] = a*gt; VOA[(16+o)*32+e] = b*gt; VOA[(32+o)*32+e] = c2*gt;
    }
    __syncthreads();
    // GVP2
    gemm_rt<16,16,3,16,16,false,false,false,false>(VOA, WH2s, nullptr, nullptr, VHX, tid);
    __syncthreads();
    for (int t = tid; t < 16 * 32; t += NT) {
      int h = t >> 5, e = t & 31;
      float a = VHX[h*32+e], b = VHX[(16+h)*32+e], c2 = VHX[(32+h)*32+e];
      BFA[(100 + h) * 32 + e] = sqrtf(fmaxf(a*a + b*b + c2*c2, 1e-8f));
    }
    __syncthreads();
    gemm_rt<116,100,1,0,100,true,false,true,true>(BFA, ws2, nullptr, BS2s, BFB, tid);
    gemm_rt<16,16,3,16,16,false,false,false,false>(VHX, WV2s, nullptr, nullptr, VOB, tid);
    __syncthreads();
    for (int t = tid; t < 16 * 32; t += NT) {
      int o = t >> 5, e = t & 31;
      float a = VOB[o*32+e], b = VOB[(16+o)*32+e], c2 = VOB[(32+o)*32+e];
      float n = sqrtf(fmaxf(a*a + b*b + c2*c2, 1e-8f));
      float gt = 1.f / (1.f + expf(-n));
      VOB[o*32+e] = a*gt; VOB[(16+o)*32+e] = b*gt; VOB[(32+o)*32+e] = c2*gt;
    }
    __syncthreads();
    // GVP3
    gemm_rt<16,16,3,16,16,false,false,false,false>(VOB, WH3s, nullptr, nullptr, VHX, tid);
    __syncthreads();
    for (int t = tid; t < 16 * 32; t += NT) {
      int h = t >> 5, e = t & 31;
      float a = VHX[h*32+e], b = VHX[(16+h)*32+e], c2 = VHX[(32+h)*32+e];
      BFB[(100 + h) * 32 + e] = sqrtf(fmaxf(a*a + b*b + c2*c2, 1e-8f));
    }
    __syncthreads();
    gemm_rt<116,100,1,0,100,true,false,true,false>(BFB, ws3, nullptr, BS3s, BFA, tid);
    gemm_rt<16,16,3,16,16,false,false,false,false>(VHX, WV3s, nullptr, nullptr, VOA, tid);
    __syncthreads();
    // masked mean + residual
    for (int t = tid; t < 148; t += NT) {
      float acc = 0.f;
      #pragma unroll
      for (int ee = 0; ee < 32; ++ee) {
        int e = (ee + t) & 31;
        float v = (t < 48) ? VOA[t * 32 + e] : BFA[(t - 48) * 32 + e];
        acc += MK[e] * v;
      }
      DH[t] = HS[t] + acc * (1.f / 30.f);
    }
    __syncthreads();
    if (tid < 32) {
      float vm = 0.f;
      if (tid < 16) { float a = DH[tid], b = DH[16+tid], c2 = DH[32+tid]; vm = fmaxf(a*a + b*b + c2*c2, 1e-8f); }
      #pragma unroll
      for (int o = 16; o; o >>= 1) vm += __shfl_xor_sync(0xffffffffu, vm, o);
      float s0 = DH[48+tid], s1 = DH[80+tid], s2v = DH[112+tid];
      float s3v = (tid < 4) ? DH[144+tid] : 0.f;
      float p = s0 + s1 + s2v + s3v;
      #pragma unroll
      for (int o = 16; o; o >>= 1) p += __shfl_xor_sync(0xffffffffu, p, o);
      float mu = p * 0.01f;
      float d0 = s0-mu, d1 = s1-mu, d2 = s2v-mu;
      float q = d0*d0 + d1*d1 + d2*d2;
      if (tid < 4) { float d3 = s3v - mu; q += d3*d3; }
      #pragma unroll
      for (int o = 16; o; o >>= 1) q += __shfl_xor_sync(0xffffffffu, q, o);
      if (tid == 0) { MISC[0] = rsqrtf(vm * (1.f/16.f)); MISC[1] = mu; MISC[2] = rsqrtf(q * 0.01f + 1e-3f); }
    }
    __syncthreads();
    for (int t = tid; t < 148; t += NT) {
      float v;
      if (t < 48) v = DH[t] * MISC[0];
      else { int j = t - 48; v = (DH[t] - MISC[1]) * MISC[2] * LG1[j] + LB1[j]; }
      g_hv[node * 148 + t] = v;
    }
    __syncthreads();
  }
}

// ------------------------------ K2: dh1 over 32-node tiles -----------------
__global__ __launch_bounds__(NT, 1)
void k_dh1(const float* __restrict__ wh, const float* __restrict__ ws,
           const float* __restrict__ bs, const float* __restrict__ wv)
{
  extern __shared__ float sm[];
  float* VC = sm;           // 48*32
  float* SC = VC + 1536;    // 132*32
  float* VH = SC + 4224;    // 96*32
  float* VO = VH + 3072;    // 96*32
  float* SO = VO + 3072;    // 400*32
  const int tid = threadIdx.x;
  const int n0 = blockIdx.x * 32;

  for (int idx = tid; idx < 148 * 32; idx += NT) {
    int r = idx >> 5, e = idx & 31;
    float v = g_hv[(size_t)(n0 + e) * 148 + r];
    if (r < 48) VC[r * 32 + e] = v; else SC[(r - 48) * 32 + e] = v;
  }
  __syncthreads();
  gemm_rt<16,32,3,16,32,true,false,false,false>(VC, wh, nullptr, nullptr, VH, tid);
  __syncthreads();
  for (int t = tid; t < 32 * 32; t += NT) {
    int h = t >> 5, e = t & 31;
    float a = VH[h*32+e], b = VH[(32+h)*32+e], c2 = VH[(64+h)*32+e];
    SC[(100 + h) * 32 + e] = sqrtf(fmaxf(a*a + b*b + c2*c2, 1e-8f));
  }
  __syncthreads();
  gemm_rt<132,400,1,0,400,true,false,true,true>(SC, ws, nullptr, bs, SO, tid);
  gemm_rt<32,32,3,32,32,true,false,false,false>(VH, wv, nullptr, nullptr, VO, tid);
  __syncthreads();
  for (int t = tid; t < 32 * 32; t += NT) {
    int o = t >> 5, e = t & 31;
    float a = VO[o*32+e], b = VO[(32+o)*32+e], c2 = VO[(64+o)*32+e];
    float n = sqrtf(fmaxf(a*a + b*b + c2*c2, 1e-8f));
    float gt = 1.f / (1.f + expf(-n));
    VO[o*32+e] = a*gt; VO[(32+o)*32+e] = b*gt; VO[(64+o)*32+e] = c2*gt;
  }
  __syncthreads();
  float* gout = g_t + (size_t)blockIdx.x * (496 * 32);
  for (int idx = tid; idx < 496 * 32; idx += NT)
    gout[idx] = (idx < 96 * 32) ? VO[idx] : SO[idx - 96 * 32];
}

// ------------------------------ K3: dh2 + LN2 + mask -----------------------
__global__ __launch_bounds__(NT, 1)
void k_dh2(const float* __restrict__ wh, const float* __restrict__ ws,
           const float* __restrict__ bs, const float* __restrict__ wv,
           const float* __restrict__ ln2g, const float* __restrict__ ln2b,
           const int* __restrict__ maskV, float* __restrict__ out)
{
  extern __shared__ float sm[];
  float* VC  = sm;            // 96*32
  float* SC  = VC + 3072;     // 432*32
  float* VH  = SC + 13824;    // 96*32
  float* VO  = VH + 3072;     // 48*32
  float* SO  = VO + 1536;     // 100*32
  float* HVT = SO + 3200;     // 148*33 (padded stride 33)
  float* ST  = HVT + 4884;    // 128
  const int tid = threadIdx.x;
  const int n0 = blockIdx.x * 32;

  const float* gin = g_t + (size_t)blockIdx.x * (496 * 32);
  for (int idx = tid; idx < 496 * 32; idx += NT) {
    if (idx < 96 * 32) VC[idx] = gin[idx];
    else               SC[idx - 96 * 32] = gin[idx];
  }
  for (int idx = tid; idx < 148 * 32; idx += NT) {
    int r = idx >> 5, e = idx & 31;
    HVT[r * 33 + e] = g_hv[(size_t)(n0 + e) * 148 + r];
  }
  if (tid < 32) ST[96 + tid] = (float)maskV[n0 + tid];
  __syncthreads();
  gemm_rt<32,32,3,32,32,true,false,false,false>(VC, wh, nullptr, nullptr, VH, tid);
  __syncthreads();
  for (int t = tid; t < 32 * 32; t += NT) {
    int h = t >> 5, e = t & 31;
    float a = VH[h*32+e], b = VH[(32+h)*32+e], c2 = VH[(64+h)*32+e];
    SC[(400 + h) * 32 + e] = sqrtf(fmaxf(a*a + b*b + c2*c2, 1e-8f));
  }
  __syncthreads();
  gemm_rt<432,100,1,0,100,true,false,true,false>(SC, ws, nullptr, bs, SO, tid);
  gemm_rt<32,16,3,32,16,true,false,false,false>(VH, wv, nullptr, nullptr, VO, tid);
  __syncthreads();
  // residual
  for (int idx = tid; idx < 148 * 32; idx += NT) {
    int r = idx >> 5, e = idx & 31;
    float add = (r < 48) ? VO[r * 32 + e] : SO[(r - 48) * 32 + e];
    HVT[r * 33 + e] += add;
  }
  __syncthreads();
  // LN2 stats per node column
  if (tid < 32) {
    const int e = tid;
    float vm = 0.f;
    #pragma unroll
    for (int i = 0; i < 16; ++i) {
      float a = HVT[i*33+e], b = HVT[(16+i)*33+e], c2 = HVT[(32+i)*33+e];
      vm += fmaxf(a*a + b*b + c2*c2, 1e-8f);
    }
    float mu = 0.f;
    #pragma unroll 4
    for (int j = 0; j < 100; ++j) mu += HVT[(48+j)*33+e];
    mu *= 0.01f;
    float var = 0.f;
    #pragma unroll 4
    for (int j = 0; j < 100; ++j) { float d = HVT[(48+j)*33+e] - mu; var += d*d; }
    var *= 0.01f;
    ST[e] = rsqrtf(vm * (1.f/16.f));
    ST[32+e] = mu;
    ST[64+e] = rsqrtf(var + 1e-3f);
  }
  __syncthreads();
  for (int idx = tid; idx < 32 * 148; idx += NT) {
    int e = idx / 148, r = idx - e * 148;
    float v = HVT[r * 33 + e];
    if (r < 48) v = v * ST[e];
    else { int j = r - 48; v = (v - ST[32+e]) * ST[64+e] * ln2g[j] + ln2b[j]; }
    out[(size_t)(n0 + e) * 148 + r] = ST[96 + e] * v;
  }
}

// ---------------------------------------------------------------------------
extern "C" void kernel_launch(void* const* d_in, const int* in_sizes, int n_in,
                              void* d_out, int out_size)
{
  const float* hV      = (const float*)d_in[0];
  const float* hM      = (const float*)d_in[1];
  const int*   maskV   = (const int*)  d_in[2];
  const int*   maskA   = (const int*)  d_in[3];
  const float* wev1_wh = (const float*)d_in[4];
  const float* wev1_ws = (const float*)d_in[5];
  const float* wev1_bs = (const float*)d_in[6];
  const float* wev1_wv = (const float*)d_in[7];
  const float* wev2_wh = (const float*)d_in[8];
  const float* wev2_ws = (const float*)d_in[9];
  const float* wev2_bs = (const float*)d_in[10];
  const float* wev2_wv = (const float*)d_in[11];
  const float* wev3_wh = (const float*)d_in[12];
  const float* wev3_ws = (const float*)d_in[13];
  const float* wev3_bs = (const float*)d_in[14];
  const float* wev3_wv = (const float*)d_in[15];
  const float* wdh1_wh = (const float*)d_in[16];
  const float* wdh1_ws = (const float*)d_in[17];
  const float* wdh1_bs = (const float*)d_in[18];
  const float* wdh1_wv = (const float*)d_in[19];
  const float* wdh2_wh = (const float*)d_in[20];
  const float* wdh2_ws = (const float*)d_in[21];
  const float* wdh2_bs = (const float*)d_in[22];
  const float* wdh2_wv = (const float*)d_in[23];
  const float* ln1g = (const float*)d_in[24];
  const float* ln1b = (const float*)d_in[25];
  const float* ln2g = (const float*)d_in[26];
  const float* ln2b = (const float*)d_in[27];
  float* out = (float*)d_out;

  int dev = 0; cudaGetDevice(&dev);
  int sms = 148;
  cudaDeviceGetAttribute(&sms, cudaDevAttrMultiProcessorCount, dev);

  const size_t SM1 = 51148u * sizeof(float);
  const size_t SM2 = (1536 + 4224 + 3072 + 3072 + 12800) * sizeof(float);
  const size_t SM3 = (3072 + 13824 + 3072 + 1536 + 3200 + 4884 + 128) * sizeof(float);

  cudaFuncSetAttribute(k_edge, cudaFuncAttributeMaxDynamicSharedMemorySize, (int)SM1);
  cudaFuncSetAttribute(k_dh1,  cudaFuncAttributeMaxDynamicSharedMemorySize, (int)SM2);
  cudaFuncSetAttribute(k_dh2,  cudaFuncAttributeMaxDynamicSharedMemorySize, (int)SM3);

  k_edge<<<sms, NT, SM1>>>(hV, hM, maskA,
                           wev1_wh, wev1_ws, wev1_bs, wev1_wv,
                           wev2_wh, wev2_ws, wev2_bs, wev2_wv,
                           wev3_wh, wev3_ws, wev3_bs, wev3_wv,
                           ln1g, ln1b);
  k_dh1<<<NODES / 32, NT, SM2>>>(wdh1_wh, wdh1_ws, wdh1_bs, wdh1_wv);
  k_dh2<<<NODES / 32, NT, SM3>>>(wdh2_wh, wdh2_ws, wdh2_bs, wdh2_wv,
                                 ln2g, ln2b, maskV, out);
}

// round 4
// speedup vs baseline: 5.8925x; 1.7603x over previous
#include <cuda_runtime.h>
#include <math.h>

#define NT 256
constexpr int NODES = 4 * 2048;

__device__ float g_hv[NODES * 148];
__device__ float g_t [NODES * 496];   // [tile of 32 nodes][496 rows][32]
__device__ float g_sb[NODES * 100];   // hoisted h_V @ ws1[0:100]
__device__ float g_vb[NODES * 108];   // hoisted v_V @ wh1[0:16]  ([3][36] padded)

// out[c][rg..rg+3][e] = init + sum_k A[(c*ARS+k)*32+e] * W[k*WSTR + row]
// Thread: 4 rows x 4 edges. eg=(tid&7)*4, g=tid>>3 (+32 stride).
template<int KD,int NROW,int NC,int ARS,int WSTR,bool WG,bool INITF,bool BIASF,bool RELUF>
__device__ __forceinline__ void gemm_rt(
    const float* __restrict__ A, const float* __restrict__ W,
    const float* __restrict__ initv, const float* __restrict__ bias,
    float* __restrict__ O, const int tid)
{
  constexpr int GPC = NROW / 4;
  constexpr int G   = NC * GPC;
  const int eg = (tid & 7) * 4;
  for (int g = tid >> 3; g < G; g += 32) {
    const int c  = g / GPC;
    const int rg = (g - c * GPC) * 4;
    float4 a0, a1, a2, a3;
    if (INITF) {
      const float* iv = initv + c * NROW + rg;
      a0 = make_float4(iv[0], iv[0], iv[0], iv[0]);
      a1 = make_float4(iv[1], iv[1], iv[1], iv[1]);
      a2 = make_float4(iv[2], iv[2], iv[2], iv[2]);
      a3 = make_float4(iv[3], iv[3], iv[3], iv[3]);
    } else {
      a0 = make_float4(0.f,0.f,0.f,0.f); a1 = a0; a2 = a0; a3 = a0;
    }
    const float* ap = A + (size_t)(c * ARS) * 32 + eg;
    const float* wp = W + rg;
    #pragma unroll 4
    for (int k = 0; k < KD; ++k) {
      const float4 av = *(const float4*)(ap + (size_t)k * 32);
      float4 wv4;
      if (WG) wv4 = __ldg(reinterpret_cast<const float4*>(wp + (size_t)k * WSTR));
      else    wv4 = *(const float4*)(wp + (size_t)k * WSTR);
      a0.x += wv4.x*av.x; a0.y += wv4.x*av.y; a0.z += wv4.x*av.z; a0.w += wv4.x*av.w;
      a1.x += wv4.y*av.x; a1.y += wv4.y*av.y; a1.z += wv4.y*av.z; a1.w += wv4.y*av.w;
      a2.x += wv4.z*av.x; a2.y += wv4.z*av.y; a2.z += wv4.z*av.z; a2.w += wv4.z*av.w;
      a3.x += wv4.w*av.x; a3.y += wv4.w*av.y; a3.z += wv4.w*av.z; a3.w += wv4.w*av.w;
    }
    if (BIASF) {
      const float* bp = bias + c * NROW + rg;
      float b0=bp[0], b1=bp[1], b2=bp[2], b3=bp[3];
      a0.x+=b0; a0.y+=b0; a0.z+=b0; a0.w+=b0;
      a1.x+=b1; a1.y+=b1; a1.z+=b1; a1.w+=b1;
      a2.x+=b2; a2.y+=b2; a2.z+=b2; a2.w+=b2;
      a3.x+=b3; a3.y+=b3; a3.z+=b3; a3.w+=b3;
    }
    if (RELUF) {
      a0.x=fmaxf(a0.x,0.f); a0.y=fmaxf(a0.y,0.f); a0.z=fmaxf(a0.z,0.f); a0.w=fmaxf(a0.w,0.f);
      a1.x=fmaxf(a1.x,0.f); a1.y=fmaxf(a1.y,0.f); a1.z=fmaxf(a1.z,0.f); a1.w=fmaxf(a1.w,0.f);
      a2.x=fmaxf(a2.x,0.f); a2.y=fmaxf(a2.y,0.f); a2.z=fmaxf(a2.z,0.f); a2.w=fmaxf(a2.w,0.f);
      a3.x=fmaxf(a3.x,0.f); a3.y=fmaxf(a3.y,0.f); a3.z=fmaxf(a3.z,0.f); a3.w=fmaxf(a3.w,0.f);
    }
    float* op = O + (size_t)(c * NROW + rg) * 32 + eg;
    *(float4*)(op)      = a0;
    *(float4*)(op + 32) = a1;
    *(float4*)(op + 64) = a2;
    *(float4*)(op + 96) = a3;
  }
}

// ------------------------------ K0: hoisted per-node partials --------------
__global__ __launch_bounds__(NT)
void k_pre(const float* __restrict__ hV,
           const float* __restrict__ ws1, const float* __restrict__ wh1)
{
  __shared__ float W[10000];   // ws1 rows 0..99
  __shared__ float WH[528];    // wh1 rows 0..15 ([16][33])
  __shared__ float HSv[148];
  const int tid = threadIdx.x;
  for (int i = tid; i < 10000; i += NT) W[i]  = ws1[i];
  for (int i = tid; i < 528;   i += NT) WH[i] = wh1[i];
  __syncthreads();
  for (int node = blockIdx.x; node < NODES; node += gridDim.x) {
    for (int t = tid; t < 148; t += NT) HSv[t] = hV[node * 148 + t];
    __syncthreads();
    for (int t = tid; t < 208; t += NT) {
      if (t < 100) {
        float acc = 0.f;
        #pragma unroll 4
        for (int j = 0; j < 100; ++j) acc += HSv[48 + j] * W[j * 100 + t];
        g_sb[node * 100 + t] = acc;
      } else {
        int u = t - 100, c = u / 36, h = u - c * 36;
        float acc = 0.f;
        if (h < 33) {
          #pragma unroll
          for (int i = 0; i < 16; ++i) acc += HSv[c * 16 + i] * WH[i * 33 + h];
        }
        g_vb[node * 108 + u] = acc;
      }
    }
    __syncthreads();
  }
}

// ------------------------------ K1: edges + mean + LN1 ---------------------
__global__ __launch_bounds__(NT, 2)
void k_edge(const float* __restrict__ hV, const float* __restrict__ hM,
            const int* __restrict__ maskA,
            const float* __restrict__ wh1, const float* __restrict__ ws1,
            const float* __restrict__ bs1, const float* __restrict__ wv1,
            const float* __restrict__ wh2, const float* __restrict__ ws2,
            const float* __restrict__ bs2, const float* __restrict__ wv2,
            const float* __restrict__ wh3, const float* __restrict__ ws3,
            const float* __restrict__ bs3, const float* __restrict__ wv3,
            const float* __restrict__ ln1g, const float* __restrict__ ln1b)
{
  extern __shared__ float sm[];
  float* WH1P = sm;                 // [33][36] padded (only rows 16..32 used by GEMM)
  float* WV1  = WH1P + 1188;        // 528
  float* BS1s = WV1 + 528;          // 100
  float* WH2s = BS1s + 100;         // 256
  float* WV2s = WH2s + 256;         // 256
  float* BS2s = WV2s + 256;         // 100
  float* WH3s = BS2s + 100;         // 256
  float* WV3s = WH3s + 256;         // 256
  float* BS3s = WV3s + 256;         // 100
  float* LG1  = BS3s + 100;         // 100
  float* LB1  = LG1 + 100;          // 100
  float* HS   = LB1 + 100;          // 148
  float* MK   = HS + 148;           // 32
  float* SB   = MK + 32;            // 100
  float* VB   = SB + 100;           // 108
  float* VC1  = VB + 108;           // 51*32
  float* SC1  = VC1 + 1632;         // 165*32
  float* VHX  = SC1 + 5280;         // 108*32
  float* BFA  = VHX + 3456;         // 116*32
  float* BFB  = BFA + 3712;         // 116*32
  float* VOA  = BFB + 3712;         // 48*32
  float* VOB  = VOA + 1536;         // 48*32
  float* DH   = VOB + 1536;         // 148
  float* MISC = DH + 148;           // 8
  float* EB   = VHX;                // staging 5490 (aliases VHX+BFA, 7168)
  const int tid = threadIdx.x;

  for (int i = tid; i < 1188; i += NT) { int r = i / 36, c = i - r * 36; WH1P[i] = (c < 33) ? wh1[r * 33 + c] : 0.f; }
  for (int i = tid; i < 528;  i += NT) WV1[i]  = wv1[i];
  for (int i = tid; i < 100;  i += NT) { BS1s[i] = bs1[i]; BS2s[i] = bs2[i]; BS3s[i] = bs3[i]; LG1[i] = ln1g[i]; LB1[i] = ln1b[i]; }
  for (int i = tid; i < 256;  i += NT) { WH2s[i] = wh2[i]; WV2s[i] = wv2[i]; WH3s[i] = wh3[i]; WV3s[i] = wv3[i]; }
  for (int i = tid; i < 51 * 2;  i += NT) { int r = i >> 1; VC1[r * 32 + 30 + (i & 1)] = 0.f; }
  for (int i = tid; i < 132 * 2; i += NT) { int r = i >> 1; SC1[r * 32 + 30 + (i & 1)] = 0.f; }
  __syncthreads();

  for (int node = blockIdx.x; node < NODES; node += gridDim.x) {
    const float* mp = hM + (size_t)node * 5490;
    for (int t = tid; t < 5490; t += NT) EB[t] = mp[t];
    for (int t = tid; t < 148; t += NT) HS[t] = hV[node * 148 + t];
    for (int t = tid; t < 100; t += NT) SB[t] = g_sb[node * 100 + t];
    for (int t = tid; t < 108; t += NT) VB[t] = g_vb[node * 108 + t];
    for (int t = tid; t < 32;  t += NT) MK[t] = (t < 30) ? (float)maskA[node * 30 + t] : 0.f;
    __syncthreads();
    // transpose staging -> VC1/SC1
    for (int idx = tid; idx < 183 * 32; idx += NT) {
      int j = idx >> 5, e = idx & 31;
      if (e < 30) {
        float v = EB[e * 183 + j];
        if (j < 51) VC1[j * 32 + e] = v;
        else        SC1[(j - 51) * 32 + e] = v;
      }
    }
    __syncthreads();
    // GVP1
    gemm_rt<17,36,3,17,36,false,true,false,false>(VC1, WH1P + 16 * 36, VB, nullptr, VHX, tid);
    __syncthreads();
    for (int t = tid; t < 33 * 32; t += NT) {
      int h = t >> 5, e = t & 31;
      float a = VHX[h*32+e], b = VHX[(36+h)*32+e], c2 = VHX[(72+h)*32+e];
      SC1[(132 + h) * 32 + e] = sqrtf(fmaxf(a*a + b*b + c2*c2, 1e-8f));
    }
    __syncthreads();
    gemm_rt<165,100,1,0,100,true,true,true,true>(SC1, ws1 + 100 * 100, SB, BS1s, BFA, tid);
    gemm_rt<33,16,3,36,16,false,false,false,false>(VHX, WV1, nullptr, nullptr, VOA, tid);
    __syncthreads();
    for (int t = tid; t < 16 * 32; t += NT) {
      int o = t >> 5, e = t & 31;
      float a = VOA[o*32+e], b = VOA[(16+o)*32+e], c2 = VOA[(32+o)*32+e];
      float n = sqrtf(fmaxf(a*a + b*b + c2*c2, 1e-8f));
      float gt = 1.f / (1.f + expf(-n));
      VOA[o*32+e] = a*gt; VOA[(16+o)*32+e] = b*gt; VOA[(32+o)*32+e] = c2*gt;
    }
    __syncthreads();
    // GVP2
    gemm_rt<16,16,3,16,16,false,false,false,false>(VOA, WH2s, nullptr, nullptr, VHX, tid);
    __syncthreads();
    for (int t = tid; t < 16 * 32; t += NT) {
      int h = t >> 5, e = t & 31;
      float a = VHX[h*32+e], b = VHX[(16+h)*32+e], c2 = VHX[(32+h)*32+e];
      BFA[(100 + h) * 32 + e] = sqrtf(fmaxf(a*a + b*b + c2*c2, 1e-8f));
    }
    __syncthreads();
    gemm_rt<116,100,1,0,100,true,false,true,true>(BFA, ws2, nullptr, BS2s, BFB, tid);
    gemm_rt<16,16,3,16,16,false,false,false,false>(VHX, WV2s, nullptr, nullptr, VOB, tid);
    __syncthreads();
    for (int t = tid; t < 16 * 32; t += NT) {
      int o = t >> 5, e = t & 31;
      float a = VOB[o*32+e], b = VOB[(16+o)*32+e], c2 = VOB[(32+o)*32+e];
      float n = sqrtf(fmaxf(a*a + b*b + c2*c2, 1e-8f));
      float gt = 1.f / (1.f + expf(-n));
      VOB[o*32+e] = a*gt; VOB[(16+o)*32+e] = b*gt; VOB[(32+o)*32+e] = c2*gt;
    }
    __syncthreads();
    // GVP3
    gemm_rt<16,16,3,16,16,false,false,false,false>(VOB, WH3s, nullptr, nullptr, VHX, tid);
    __syncthreads();
    for (int t = tid; t < 16 * 32; t += NT) {
      int h = t >> 5, e = t & 31;
      float a = VHX[h*32+e], b = VHX[(16+h)*32+e], c2 = VHX[(32+h)*32+e];
      BFB[(100 + h) * 32 + e] = sqrtf(fmaxf(a*a + b*b + c2*c2, 1e-8f));
    }
    __syncthreads();
    gemm_rt<116,100,1,0,100,true,false,true,false>(BFB, ws3, nullptr, BS3s, BFA, tid);
    gemm_rt<16,16,3,16,16,false,false,false,false>(VHX, WV3s, nullptr, nullptr, VOA, tid);
    __syncthreads();
    // masked mean + residual
    for (int t = tid; t < 148; t += NT) {
      float acc = 0.f;
      #pragma unroll
      for (int ee = 0; ee < 32; ++ee) {
        int e = (ee + t) & 31;
        float v = (t < 48) ? VOA[t * 32 + e] : BFA[(t - 48) * 32 + e];
        acc += MK[e] * v;
      }
      DH[t] = HS[t] + acc * (1.f / 30.f);
    }
    __syncthreads();
    if (tid < 32) {
      float vm = 0.f;
      if (tid < 16) { float a = DH[tid], b = DH[16+tid], c2 = DH[32+tid]; vm = fmaxf(a*a + b*b + c2*c2, 1e-8f); }
      #pragma unroll
      for (int o = 16; o; o >>= 1) vm += __shfl_xor_sync(0xffffffffu, vm, o);
      float s0 = DH[48+tid], s1 = DH[80+tid], s2v = DH[112+tid];
      float s3v = (tid < 4) ? DH[144+tid] : 0.f;
      float p = s0 + s1 + s2v + s3v;
      #pragma unroll
      for (int o = 16; o; o >>= 1) p += __shfl_xor_sync(0xffffffffu, p, o);
      float mu = p * 0.01f;
      float d0 = s0-mu, d1 = s1-mu, d2 = s2v-mu;
      float q = d0*d0 + d1*d1 + d2*d2;
      if (tid < 4) { float d3 = s3v - mu; q += d3*d3; }
      #pragma unroll
      for (int o = 16; o; o >>= 1) q += __shfl_xor_sync(0xffffffffu, q, o);
      if (tid == 0) { MISC[0] = rsqrtf(vm * (1.f/16.f)); MISC[1] = mu; MISC[2] = rsqrtf(q * 0.01f + 1e-3f); }
    }
    __syncthreads();
    for (int t = tid; t < 148; t += NT) {
      float v;
      if (t < 48) v = DH[t] * MISC[0];
      else { int j = t - 48; v = (DH[t] - MISC[1]) * MISC[2] * LG1[j] + LB1[j]; }
      g_hv[node * 148 + t] = v;
    }
    __syncthreads();
  }
}

// ------------------------------ K2: dh1 over 32-node tiles -----------------
__global__ __launch_bounds__(NT, 2)
void k_dh1(const float* __restrict__ wh, const float* __restrict__ ws,
           const float* __restrict__ bs, const float* __restrict__ wv)
{
  extern __shared__ float sm[];
  float* VC = sm;           // 48*32
  float* SC = VC + 1536;    // 132*32
  float* VH = SC + 4224;    // 96*32
  float* VO = VH + 3072;    // 96*32
  float* SO = VO + 3072;    // 400*32
  const int tid = threadIdx.x;
  const int n0 = blockIdx.x * 32;

  for (int idx = tid; idx < 148 * 32; idx += NT) {
    int r = idx >> 5, e = idx & 31;
    float v = g_hv[(size_t)(n0 + e) * 148 + r];
    if (r < 48) VC[r * 32 + e] = v; else SC[(r - 48) * 32 + e] = v;
  }
  __syncthreads();
  gemm_rt<16,32,3,16,32,true,false,false,false>(VC, wh, nullptr, nullptr, VH, tid);
  __syncthreads();
  for (int t = tid; t < 32 * 32; t += NT) {
    int h = t >> 5, e = t & 31;
    float a = VH[h*32+e], b = VH[(32+h)*32+e], c2 = VH[(64+h)*32+e];
    SC[(100 + h) * 32 + e] = sqrtf(fmaxf(a*a + b*b + c2*c2, 1e-8f));
  }
  __syncthreads();
  gemm_rt<132,400,1,0,400,true,false,true,true>(SC, ws, nullptr, bs, SO, tid);
  gemm_rt<32,32,3,32,32,true,false,false,false>(VH, wv, nullptr, nullptr, VO, tid);
  __syncthreads();
  for (int t = tid; t < 32 * 32; t += NT) {
    int o = t >> 5, e = t & 31;
    float a = VO[o*32+e], b = VO[(32+o)*32+e], c2 = VO[(64+o)*32+e];
    float n = sqrtf(fmaxf(a*a + b*b + c2*c2, 1e-8f));
    float gt = 1.f / (1.f + expf(-n));
    VO[o*32+e] = a*gt; VO[(32+o)*32+e] = b*gt; VO[(64+o)*32+e] = c2*gt;
  }
  __syncthreads();
  float* gout = g_t + (size_t)blockIdx.x * (496 * 32);
  for (int idx = tid; idx < 496 * 32; idx += NT)
    gout[idx] = (idx < 96 * 32) ? VO[idx] : SO[idx - 96 * 32];
}

// ------------------------------ K3: dh2 + LN2 + mask -----------------------
__global__ __launch_bounds__(NT)
void k_dh2(const float* __restrict__ wh, const float* __restrict__ ws,
           const float* __restrict__ bs, const float* __restrict__ wv,
           const float* __restrict__ ln2g, const float* __restrict__ ln2b,
           const int* __restrict__ maskV, float* __restrict__ out)
{
  extern __shared__ float sm[];
  float* VC  = sm;            // 96*32
  float* SC  = VC + 3072;     // 432*32
  float* VH  = SC + 13824;    // 96*32
  float* VO  = VH + 3072;     // 48*32
  float* SO  = VO + 1536;     // 100*32
  float* HVT = SO + 3200;     // 148*33
  float* ST  = HVT + 4884;    // 128
  const int tid = threadIdx.x;
  const int n0 = blockIdx.x * 32;

  const float* gin = g_t + (size_t)blockIdx.x * (496 * 32);
  for (int idx = tid; idx < 496 * 32; idx += NT) {
    if (idx < 96 * 32) VC[idx] = gin[idx];
    else               SC[idx - 96 * 32] = gin[idx];
  }
  for (int idx = tid; idx < 148 * 32; idx += NT) {
    int r = idx >> 5, e = idx & 31;
    HVT[r * 33 + e] = g_hv[(size_t)(n0 + e) * 148 + r];
  }
  if (tid < 32) ST[96 + tid] = (float)maskV[n0 + tid];
  __syncthreads();
  gemm_rt<32,32,3,32,32,true,false,false,false>(VC, wh, nullptr, nullptr, VH, tid);
  __syncthreads();
  for (int t = tid; t < 32 * 32; t += NT) {
    int h = t >> 5, e = t & 31;
    float a = VH[h*32+e], b = VH[(32+h)*32+e], c2 = VH[(64+h)*32+e];
    SC[(400 + h) * 32 + e] = sqrtf(fmaxf(a*a + b*b + c2*c2, 1e-8f));
  }
  __syncthreads();
  gemm_rt<432,100,1,0,100,true,false,true,false>(SC, ws, nullptr, bs, SO, tid);
  gemm_rt<32,16,3,32,16,true,false,false,false>(VH, wv, nullptr, nullptr, VO, tid);
  __syncthreads();
  for (int idx = tid; idx < 148 * 32; idx += NT) {
    int r = idx >> 5, e = idx & 31;
    float add = (r < 48) ? VO[r * 32 + e] : SO[(r - 48) * 32 + e];
    HVT[r * 33 + e] += add;
  }
  __syncthreads();
  if (tid < 32) {
    const int e = tid;
    float vm = 0.f;
    #pragma unroll
    for (int i = 0; i < 16; ++i) {
      float a = HVT[i*33+e], b = HVT[(16+i)*33+e], c2 = HVT[(32+i)*33+e];
      vm += fmaxf(a*a + b*b + c2*c2, 1e-8f);
    }
    float mu = 0.f;
    #pragma unroll 4
    for (int j = 0; j < 100; ++j) mu += HVT[(48+j)*33+e];
    mu *= 0.01f;
    float var = 0.f;
    #pragma unroll 4
    for (int j = 0; j < 100; ++j) { float d = HVT[(48+j)*33+e] - mu; var += d*d; }
    var *= 0.01f;
    ST[e] = rsqrtf(vm * (1.f/16.f));
    ST[32+e] = mu;
    ST[64+e] = rsqrtf(var + 1e-3f);
  }
  __syncthreads();
  for (int idx = tid; idx < 32 * 148; idx += NT) {
    int e = idx / 148, r = idx - e * 148;
    float v = HVT[r * 33 + e];
    if (r < 48) v = v * ST[e];
    else { int j = r - 48; v = (v - ST[32+e]) * ST[64+e] * ln2g[j] + ln2b[j]; }
    out[(size_t)(n0 + e) * 148 + r] = ST[96 + e] * v;
  }
}

// ---------------------------------------------------------------------------
extern "C" void kernel_launch(void* const* d_in, const int* in_sizes, int n_in,
                              void* d_out, int out_size)
{
  const float* hV      = (const float*)d_in[0];
  const float* hM      = (const float*)d_in[1];
  const int*   maskV   = (const int*)  d_in[2];
  const int*   maskA   = (const int*)  d_in[3];
  const float* wev1_wh = (const float*)d_in[4];
  const float* wev1_ws = (const float*)d_in[5];
  const float* wev1_bs = (const float*)d_in[6];
  const float* wev1_wv = (const float*)d_in[7];
  const float* wev2_wh = (const float*)d_in[8];
  const float* wev2_ws = (const float*)d_in[9];
  const float* wev2_bs = (const float*)d_in[10];
  const float* wev2_wv = (const float*)d_in[11];
  const float* wev3_wh = (const float*)d_in[12];
  const float* wev3_ws = (const float*)d_in[13];
  const float* wev3_bs = (const float*)d_in[14];
  const float* wev3_wv = (const float*)d_in[15];
  const float* wdh1_wh = (const float*)d_in[16];
  const float* wdh1_ws = (const float*)d_in[17];
  const float* wdh1_bs = (const float*)d_in[18];
  const float* wdh1_wv = (const float*)d_in[19];
  const float* wdh2_wh = (const float*)d_in[20];
  const float* wdh2_ws = (const float*)d_in[21];
  const float* wdh2_bs = (const float*)d_in[22];
  const float* wdh2_wv = (const float*)d_in[23];
  const float* ln1g = (const float*)d_in[24];
  const float* ln1b = (const float*)d_in[25];
  const float* ln2g = (const float*)d_in[26];
  const float* ln2b = (const float*)d_in[27];
  float* out = (float*)d_out;

  int dev = 0; cudaGetDevice(&dev);
  int sms = 148;
  cudaDeviceGetAttribute(&sms, cudaDevAttrMultiProcessorCount, dev);

  const size_t SM1 = 24648u * sizeof(float);                          // ~98.6 KB
  const size_t SM2 = (1536 + 4224 + 3072 + 3072 + 12800) * sizeof(float);
  const size_t SM3 = (3072 + 13824 + 3072 + 1536 + 3200 + 4884 + 128) * sizeof(float);

  cudaFuncSetAttribute(k_edge, cudaFuncAttributeMaxDynamicSharedMemorySize, (int)SM1);
  cudaFuncSetAttribute(k_dh1,  cudaFuncAttributeMaxDynamicSharedMemorySize, (int)SM2);
  cudaFuncSetAttribute(k_dh2,  cudaFuncAttributeMaxDynamicSharedMemorySize, (int)SM3);

  k_pre <<<sms, NT>>>(hV, wev1_ws, wev1_wh);
  k_edge<<<2 * sms, NT, SM1>>>(hV, hM, maskA,
                               wev1_wh, wev1_ws, wev1_bs, wev1_wv,
                               wev2_wh, wev2_ws, wev2_bs, wev2_wv,
                               wev3_wh, wev3_ws, wev3_bs, wev3_wv,
                               ln1g, ln1b);
  k_dh1<<<NODES / 32, NT, SM2>>>(wdh1_wh, wdh1_ws, wdh1_bs, wdh1_wv);
  k_dh2<<<NODES / 32, NT, SM3>>>(wdh2_wh, wdh2_ws, wdh2_bs, wdh2_wv,
                                 ln2g, ln2b, maskV, out);
}

// round 5
// speedup vs baseline: 7.4265x; 1.2603x over previous
#include <cuda_runtime.h>
#include <cuda_pipeline.h>
#include <math.h>

#define NT 256
constexpr int NODES = 4 * 2048;

__device__ float g_hv[NODES * 148];
__device__ float g_t [NODES * 496];   // [tile of 32 nodes][496 rows][32]
__device__ float g_sb[NODES * 100];   // hoisted h_V @ ws1[0:100]
__device__ float g_vb[NODES * 108];   // hoisted v_V @ wh1[0:16]  ([3][36] padded)

// ---------------- register-tiled GEMM, weights in SMEM ----------------------
// out[c][rg..rg+3][e] = init + sum_k A[(c*ARS+k)*32+e] * W[k*WSTR + row]
template<int KD,int NROW,int NC,int ARS,int WSTR,bool INITF,bool BIASF,bool RELUF>
__device__ __forceinline__ void gemm_rt(
    const float* __restrict__ A, const float* __restrict__ W,
    const float* __restrict__ initv, const float* __restrict__ bias,
    float* __restrict__ O, const int tid)
{
  constexpr int GPC = NROW / 4;
  constexpr int G   = NC * GPC;
  const int eg = (tid & 7) * 4;
  for (int g = tid >> 3; g < G; g += 32) {
    const int c  = g / GPC;
    const int rg = (g - c * GPC) * 4;
    float4 a0, a1, a2, a3;
    if (INITF) {
      const float* iv = initv + c * NROW + rg;
      a0 = make_float4(iv[0], iv[0], iv[0], iv[0]);
      a1 = make_float4(iv[1], iv[1], iv[1], iv[1]);
      a2 = make_float4(iv[2], iv[2], iv[2], iv[2]);
      a3 = make_float4(iv[3], iv[3], iv[3], iv[3]);
    } else {
      a0 = make_float4(0.f,0.f,0.f,0.f); a1 = a0; a2 = a0; a3 = a0;
    }
    const float* ap = A + (size_t)(c * ARS) * 32 + eg;
    const float* wp = W + rg;
    #pragma unroll 4
    for (int k = 0; k < KD; ++k) {
      const float4 av = *(const float4*)(ap + (size_t)k * 32);
      const float4 wv4 = *(const float4*)(wp + (size_t)k * WSTR);
      a0.x += wv4.x*av.x; a0.y += wv4.x*av.y; a0.z += wv4.x*av.z; a0.w += wv4.x*av.w;
      a1.x += wv4.y*av.x; a1.y += wv4.y*av.y; a1.z += wv4.y*av.z; a1.w += wv4.y*av.w;
      a2.x += wv4.z*av.x; a2.y += wv4.z*av.y; a2.z += wv4.z*av.z; a2.w += wv4.z*av.w;
      a3.x += wv4.w*av.x; a3.y += wv4.w*av.y; a3.z += wv4.w*av.z; a3.w += wv4.w*av.w;
    }
    if (BIASF) {
      const float* bp = bias + c * NROW + rg;
      float b0=bp[0], b1=bp[1], b2=bp[2], b3=bp[3];
      a0.x+=b0; a0.y+=b0; a0.z+=b0; a0.w+=b0;
      a1.x+=b1; a1.y+=b1; a1.z+=b1; a1.w+=b1;
      a2.x+=b2; a2.y+=b2; a2.z+=b2; a2.w+=b2;
      a3.x+=b3; a3.y+=b3; a3.z+=b3; a3.w+=b3;
    }
    if (RELUF) {
      a0.x=fmaxf(a0.x,0.f); a0.y=fmaxf(a0.y,0.f); a0.z=fmaxf(a0.z,0.f); a0.w=fmaxf(a0.w,0.f);
      a1.x=fmaxf(a1.x,0.f); a1.y=fmaxf(a1.y,0.f); a1.z=fmaxf(a1.z,0.f); a1.w=fmaxf(a1.w,0.f);
      a2.x=fmaxf(a2.x,0.f); a2.y=fmaxf(a2.y,0.f); a2.z=fmaxf(a2.z,0.f); a2.w=fmaxf(a2.w,0.f);
      a3.x=fmaxf(a3.x,0.f); a3.y=fmaxf(a3.y,0.f); a3.z=fmaxf(a3.z,0.f); a3.w=fmaxf(a3.w,0.f);
    }
    float* op = O + (size_t)(c * NROW + rg) * 32 + eg;
    *(float4*)(op)      = a0;
    *(float4*)(op + 32) = a1;
    *(float4*)(op + 64) = a2;
    *(float4*)(op + 96) = a3;
  }
}

// ------- chunked GEMM: W streamed global->SMEM via cp.async double buffer ---
// A smem [KD][32]; Wg global [KD][NROW]; O smem [NROW][32]; wbuf smem [2][CH*NROW]
// Contains internal __syncthreads (all 256 threads must call).
template<int KD,int NROW,int CH,bool INITF,bool BIASF,bool RELUF>
__device__ __forceinline__ void gemm_st(
    const float* __restrict__ A, const float* __restrict__ Wg,
    const float* __restrict__ initv, const float* __restrict__ bias,
    float* __restrict__ O, float* __restrict__ wbuf, const int tid)
{
  constexpr int G    = NROW / 4;
  constexpr int GMAX = (G + 31) / 32;
  constexpr int NCH  = (KD + CH - 1) / CH;
  const int eg = (tid & 7) * 4;
  const int g0 = tid >> 3;

  float4 acc[GMAX][4];
  #pragma unroll
  for (int j = 0; j < GMAX; ++j) {
    int g = g0 + 32 * j;
    if (g < G) {
      int rg = g * 4;
      #pragma unroll
      for (int r = 0; r < 4; ++r) {
        float iv = INITF ? initv[rg + r] : 0.f;
        acc[j][r] = make_float4(iv, iv, iv, iv);
      }
    }
  }
  // prologue: chunk 0
  {
    int rows = (KD < CH) ? KD : CH;
    int cnt = rows * NROW / 4;
    for (int i = tid; i < cnt; i += NT)
      __pipeline_memcpy_async(wbuf + i * 4, Wg + i * 4, 16);
    __pipeline_commit();
  }
  for (int c = 0; c < NCH; ++c) {
    if (c + 1 < NCH) {
      int base = (c + 1) * CH;
      int rows = ((KD - base) < CH) ? (KD - base) : CH;
      int cnt = rows * NROW / 4;
      float* db = wbuf + ((c + 1) & 1) * (CH * NROW);
      const float* sp = Wg + (size_t)base * NROW;
      for (int i = tid; i < cnt; i += NT)
        __pipeline_memcpy_async(db + i * 4, sp + i * 4, 16);
      __pipeline_commit();
      __pipeline_wait_prior(1);
    } else {
      __pipeline_wait_prior(0);
    }
    __syncthreads();
    const float* wb = wbuf + (c & 1) * (CH * NROW);
    const int kmax = ((KD - c * CH) < CH) ? (KD - c * CH) : CH;
    const float* ap = A + (size_t)(c * CH) * 32 + eg;
    #pragma unroll
    for (int j = 0; j < GMAX; ++j) {
      int g = g0 + 32 * j;
      if (g < G) {
        const float* wp = wb + g * 4;
        #pragma unroll 4
        for (int k = 0; k < kmax; ++k) {
          const float4 av = *(const float4*)(ap + k * 32);
          const float4 wv = *(const float4*)(wp + (size_t)k * NROW);
          acc[j][0].x += wv.x*av.x; acc[j][0].y += wv.x*av.y; acc[j][0].z += wv.x*av.z; acc[j][0].w += wv.x*av.w;
          acc[j][1].x += wv.y*av.x; acc[j][1].y += wv.y*av.y; acc[j][1].z += wv.y*av.z; acc[j][1].w += wv.y*av.w;
          acc[j][2].x += wv.z*av.x; acc[j][2].y += wv.z*av.y; acc[j][2].z += wv.z*av.z; acc[j][2].w += wv.z*av.w;
          acc[j][3].x += wv.w*av.x; acc[j][3].y += wv.w*av.y; acc[j][3].z += wv.w*av.z; acc[j][3].w += wv.w*av.w;
        }
      }
    }
    __syncthreads();
  }
  // epilogue
  #pragma unroll
  for (int j = 0; j < GMAX; ++j) {
    int g = g0 + 32 * j;
    if (g < G) {
      int rg = g * 4;
      #pragma unroll
      for (int r = 0; r < 4; ++r) {
        float4 a = acc[j][r];
        if (BIASF) { float b = bias[rg + r]; a.x += b; a.y += b; a.z += b; a.w += b; }
        if (RELUF) { a.x=fmaxf(a.x,0.f); a.y=fmaxf(a.y,0.f); a.z=fmaxf(a.z,0.f); a.w=fmaxf(a.w,0.f); }
        *(float4*)(O + (size_t)(rg + r) * 32 + eg) = a;
      }
    }
  }
}

// ------------------------------ K0: hoisted per-node partials --------------
__global__ __launch_bounds__(NT)
void k_pre(const float* __restrict__ hV,
           const float* __restrict__ ws1, const float* __restrict__ wh1)
{
  __shared__ float W[10000];
  __shared__ float WH[528];
  __shared__ float HSv[148];
  const int tid = threadIdx.x;
  for (int i = tid; i < 10000; i += NT) W[i]  = ws1[i];
  for (int i = tid; i < 528;   i += NT) WH[i] = wh1[i];
  __syncthreads();
  for (int node = blockIdx.x; node < NODES; node += gridDim.x) {
    for (int t = tid; t < 148; t += NT) HSv[t] = hV[node * 148 + t];
    __syncthreads();
    for (int t = tid; t < 208; t += NT) {
      if (t < 100) {
        float acc = 0.f;
        #pragma unroll 4
        for (int j = 0; j < 100; ++j) acc += HSv[48 + j] * W[j * 100 + t];
        g_sb[node * 100 + t] = acc;
      } else {
        int u = t - 100, c = u / 36, h = u - c * 36;
        float acc = 0.f;
        if (h < 33) {
          #pragma unroll
          for (int i = 0; i < 16; ++i) acc += HSv[c * 16 + i] * WH[i * 33 + h];
        }
        g_vb[node * 108 + u] = acc;
      }
    }
    __syncthreads();
  }
}

// ------------------------------ K1: edges + mean + LN1 ---------------------
#define ECH 26
__global__ __launch_bounds__(NT, 2)
void k_edge(const float* __restrict__ hV, const float* __restrict__ hM,
            const int* __restrict__ maskA,
            const float* __restrict__ wh1, const float* __restrict__ ws1,
            const float* __restrict__ bs1, const float* __restrict__ wv1,
            const float* __restrict__ wh2, const float* __restrict__ ws2,
            const float* __restrict__ bs2, const float* __restrict__ wv2,
            const float* __restrict__ wh3, const float* __restrict__ ws3,
            const float* __restrict__ bs3, const float* __restrict__ wv3,
            const float* __restrict__ ln1g, const float* __restrict__ ln1b)
{
  extern __shared__ float sm[];
  float* WH1P = sm;                 // 1188
  float* WV1  = WH1P + 1188;        // 528
  float* BS1s = WV1 + 528;          // 100
  float* WH2s = BS1s + 100;         // 256
  float* WV2s = WH2s + 256;         // 256
  float* BS2s = WV2s + 256;         // 100
  float* WH3s = BS2s + 100;         // 256
  float* WV3s = WH3s + 256;         // 256
  float* BS3s = WV3s + 256;         // 100
  float* LG1  = BS3s + 100;         // 100
  float* LB1  = LG1 + 100;          // 100
  float* HS   = LB1 + 100;          // 148
  float* MK   = HS + 148;           // 32
  float* SB   = MK + 32;            // 100
  float* VB   = SB + 100;           // 108
  float* VC1  = VB + 108;           // 1632
  float* SC1  = VC1 + 1632;         // 5280
  float* VHX  = SC1 + 5280;         // 3456
  float* BFA  = VHX + 3456;         // 3712
  float* BFB  = BFA + 3712;         // 3712
  float* VOA  = BFB + 3712;         // 1536
  float* DH   = VOA + 1536;         // 148
  float* MISC = DH + 148;           // 8
  float* WBUF = MISC + 8;           // 2*ECH*100 = 5200
  float* EB   = VHX;                // staging 5490 (aliases VHX+BFA)
  const int tid = threadIdx.x;

  for (int i = tid; i < 1188; i += NT) { int r = i / 36, c = i - r * 36; WH1P[i] = (c < 33) ? wh1[r * 33 + c] : 0.f; }
  for (int i = tid; i < 528;  i += NT) WV1[i]  = wv1[i];
  for (int i = tid; i < 100;  i += NT) { BS1s[i] = bs1[i]; BS2s[i] = bs2[i]; BS3s[i] = bs3[i]; LG1[i] = ln1g[i]; LB1[i] = ln1b[i]; }
  for (int i = tid; i < 256;  i += NT) { WH2s[i] = wh2[i]; WV2s[i] = wv2[i]; WH3s[i] = wh3[i]; WV3s[i] = wv3[i]; }
  for (int i = tid; i < 51 * 2;  i += NT) { int r = i >> 1; VC1[r * 32 + 30 + (i & 1)] = 0.f; }
  for (int i = tid; i < 132 * 2; i += NT) { int r = i >> 1; SC1[r * 32 + 30 + (i & 1)] = 0.f; }
  __syncthreads();

  for (int node = blockIdx.x; node < NODES; node += gridDim.x) {
    const float* mp = hM + (size_t)node * 5490;
    for (int t = tid; t < 5490; t += NT) EB[t] = mp[t];
    for (int t = tid; t < 148; t += NT) HS[t] = hV[node * 148 + t];
    for (int t = tid; t < 100; t += NT) SB[t] = g_sb[node * 100 + t];
    for (int t = tid; t < 108; t += NT) VB[t] = g_vb[node * 108 + t];
    for (int t = tid; t < 32;  t += NT) MK[t] = (t < 30) ? (float)maskA[node * 30 + t] : 0.f;
    __syncthreads();
    for (int idx = tid; idx < 183 * 32; idx += NT) {
      int j = idx >> 5, e = idx & 31;
      if (e < 30) {
        float v = EB[e * 183 + j];
        if (j < 51) VC1[j * 32 + e] = v;
        else        SC1[(j - 51) * 32 + e] = v;
      }
    }
    __syncthreads();
    // GVP1
    gemm_rt<17,36,3,17,36,true,false,false>(VC1, WH1P + 16 * 36, VB, nullptr, VHX, tid);
    __syncthreads();
    for (int t = tid; t < 33 * 32; t += NT) {
      int h = t >> 5, e = t & 31;
      float a = VHX[h*32+e], b = VHX[(36+h)*32+e], c2 = VHX[(72+h)*32+e];
      SC1[(132 + h) * 32 + e] = sqrtf(fmaxf(a*a + b*b + c2*c2, 1e-8f));
    }
    gemm_rt<33,16,3,36,16,false,false,false>(VHX, WV1, nullptr, nullptr, VOA, tid);
    gemm_st<165,100,ECH,true,true,true>(SC1, ws1 + 10000, SB, BS1s, BFA, WBUF, tid);
    __syncthreads();
    for (int t = tid; t < 16 * 32; t += NT) {
      int o = t >> 5, e = t & 31;
      float a = VOA[o*32+e], b = VOA[(16+o)*32+e], c2 = VOA[(32+o)*32+e];
      float n = sqrtf(fmaxf(a*a + b*b + c2*c2, 1e-8f));
      float gt = 1.f / (1.f + expf(-n));
      VOA[o*32+e] = a*gt; VOA[(16+o)*32+e] = b*gt; VOA[(32+o)*32+e] = c2*gt;
    }
    __syncthreads();
    // GVP2
    gemm_rt<16,16,3,16,16,false,false,false>(VOA, WH2s, nullptr, nullptr, VHX, tid);
    __syncthreads();
    for (int t = tid; t < 16 * 32; t += NT) {
      int h = t >> 5, e = t & 31;
      float a = VHX[h*32+e], b = VHX[(16+h)*32+e], c2 = VHX[(32+h)*32+e];
      BFA[(100 + h) * 32 + e] = sqrtf(fmaxf(a*a + b*b + c2*c2, 1e-8f));
    }
    gemm_rt<16,16,3,16,16,false,false,false>(VHX, WV2s, nullptr, nullptr, VOA, tid);
    gemm_st<116,100,ECH,false,true,true>(BFA, ws2, nullptr, BS2s, BFB, WBUF, tid);
    __syncthreads();
    for (int t = tid; t < 16 * 32; t += NT) {
      int o = t >> 5, e = t & 31;
      float a = VOA[o*32+e], b = VOA[(16+o)*32+e], c2 = VOA[(32+o)*32+e];
      float n = sqrtf(fmaxf(a*a + b*b + c2*c2, 1e-8f));
      float gt = 1.f / (1.f + expf(-n));
      VOA[o*32+e] = a*gt; VOA[(16+o)*32+e] = b*gt; VOA[(32+o)*32+e] = c2*gt;
    }
    __syncthreads();
    // GVP3
    gemm_rt<16,16,3,16,16,false,false,false>(VOA, WH3s, nullptr, nullptr, VHX, tid);
    __syncthreads();
    for (int t = tid; t < 16 * 32; t += NT) {
      int h = t >> 5, e = t & 31;
      float a = VHX[h*32+e], b = VHX[(16+h)*32+e], c2 = VHX[(32+h)*32+e];
      BFB[(100 + h) * 32 + e] = sqrtf(fmaxf(a*a + b*b + c2*c2, 1e-8f));
    }
    gemm_rt<16,16,3,16,16,false,false,false>(VHX, WV3s, nullptr, nullptr, VOA, tid);
    gemm_st<116,100,ECH,false,true,false>(BFB, ws3, nullptr, BS3s, BFA, WBUF, tid);
    __syncthreads();
    // masked mean + residual
    for (int t = tid; t < 148; t += NT) {
      float acc = 0.f;
      #pragma unroll
      for (int ee = 0; ee < 32; ++ee) {
        int e = (ee + t) & 31;
        float v = (t < 48) ? VOA[t * 32 + e] : BFA[(t - 48) * 32 + e];
        acc += MK[e] * v;
      }
      DH[t] = HS[t] + acc * (1.f / 30.f);
    }
    __syncthreads();
    if (tid < 32) {
      float vm = 0.f;
      if (tid < 16) { float a = DH[tid], b = DH[16+tid], c2 = DH[32+tid]; vm = fmaxf(a*a + b*b + c2*c2, 1e-8f); }
      #pragma unroll
      for (int o = 16; o; o >>= 1) vm += __shfl_xor_sync(0xffffffffu, vm, o);
      float s0 = DH[48+tid], s1 = DH[80+tid], s2v = DH[112+tid];
      float s3v = (tid < 4) ? DH[144+tid] : 0.f;
      float p = s0 + s1 + s2v + s3v;
      #pragma unroll
      for (int o = 16; o; o >>= 1) p += __shfl_xor_sync(0xffffffffu, p, o);
      float mu = p * 0.01f;
      float d0 = s0-mu, d1 = s1-mu, d2 = s2v-mu;
      float q = d0*d0 + d1*d1 + d2*d2;
      if (tid < 4) { float d3 = s3v - mu; q += d3*d3; }
      #pragma unroll
      for (int o = 16; o; o >>= 1) q += __shfl_xor_sync(0xffffffffu, q, o);
      if (tid == 0) { MISC[0] = rsqrtf(vm * (1.f/16.f)); MISC[1] = mu; MISC[2] = rsqrtf(q * 0.01f + 1e-3f); }
    }
    __syncthreads();
    for (int t = tid; t < 148; t += NT) {
      float v;
      if (t < 48) v = DH[t] * MISC[0];
      else { int j = t - 48; v = (DH[t] - MISC[1]) * MISC[2] * LG1[j] + LB1[j]; }
      g_hv[node * 148 + t] = v;
    }
    __syncthreads();
  }
}

// ------------------------------ K2: dh1 over 32-node tiles -----------------
__global__ __launch_bounds__(NT)
void k_dh1(const float* __restrict__ wh, const float* __restrict__ ws,
           const float* __restrict__ bs, const float* __restrict__ wv)
{
  extern __shared__ float sm[];
  float* VC   = sm;            // 48*32  = 1536
  float* SC   = VC + 1536;     // 132*32 = 4224
  float* VH   = SC + 4224;     // 96*32  = 3072
  float* VO   = VH + 3072;     // 96*32  = 3072
  float* SO   = VO + 3072;     // 400*32 = 12800
  float* WHs  = SO + 12800;    // 512
  float* WVs  = WHs + 512;     // 1024
  float* BSs  = WVs + 1024;    // 400
  float* WBUF = BSs + 400;     // 2*12*400 = 9600
  const int tid = threadIdx.x;
  const int n0 = blockIdx.x * 32;

  for (int i = tid; i < 512;  i += NT) WHs[i] = wh[i];
  for (int i = tid; i < 1024; i += NT) WVs[i] = wv[i];
  for (int i = tid; i < 400;  i += NT) BSs[i] = bs[i];
  for (int idx = tid; idx < 148 * 32; idx += NT) {
    int r = idx >> 5, e = idx & 31;
    float v = g_hv[(size_t)(n0 + e) * 148 + r];
    if (r < 48) VC[r * 32 + e] = v; else SC[(r - 48) * 32 + e] = v;
  }
  __syncthreads();
  gemm_rt<16,32,3,16,32,false,false,false>(VC, WHs, nullptr, nullptr, VH, tid);
  __syncthreads();
  for (int t = tid; t < 32 * 32; t += NT) {
    int h = t >> 5, e = t & 31;
    float a = VH[h*32+e], b = VH[(32+h)*32+e], c2 = VH[(64+h)*32+e];
    SC[(100 + h) * 32 + e] = sqrtf(fmaxf(a*a + b*b + c2*c2, 1e-8f));
  }
  gemm_rt<32,32,3,32,32,false,false,false>(VH, WVs, nullptr, nullptr, VO, tid);
  gemm_st<132,400,12,false,true,true>(SC, ws, nullptr, BSs, SO, WBUF, tid);
  __syncthreads();
  for (int t = tid; t < 32 * 32; t += NT) {
    int o = t >> 5, e = t & 31;
    float a = VO[o*32+e], b = VO[(32+o)*32+e], c2 = VO[(64+o)*32+e];
    float n = sqrtf(fmaxf(a*a + b*b + c2*c2, 1e-8f));
    float gt = 1.f / (1.f + expf(-n));
    VO[o*32+e] = a*gt; VO[(32+o)*32+e] = b*gt; VO[(64+o)*32+e] = c2*gt;
  }
  __syncthreads();
  float* gout = g_t + (size_t)blockIdx.x * (496 * 32);
  for (int idx = tid; idx < 496 * 32; idx += NT)
    gout[idx] = (idx < 96 * 32) ? VO[idx] : SO[idx - 96 * 32];
}

// ------------------------------ K3: dh2 + LN2 + mask -----------------------
__global__ __launch_bounds__(NT)
void k_dh2(const float* __restrict__ wh, const float* __restrict__ ws,
           const float* __restrict__ bs, const float* __restrict__ wv,
           const float* __restrict__ ln2g, const float* __restrict__ ln2b,
           const int* __restrict__ maskV, float* __restrict__ out)
{
  extern __shared__ float sm[];
  float* VC   = sm;            // 96*32  = 3072
  float* SC   = VC + 3072;     // 432*32 = 13824
  float* VH   = SC + 13824;    // 96*32  = 3072
  float* VO   = VH + 3072;     // 48*32  = 1536
  float* SO   = VO + 1536;     // 100*32 = 3200
  float* HVT  = SO + 3200;     // 148*33 = 4884
  float* ST   = HVT + 4884;    // 128
  float* WHs  = ST + 128;      // 1024
  float* WVs  = WHs + 1024;    // 512
  float* BSs  = WVs + 512;     // 100
  float* WBUF = BSs + 100;     // 2*36*100 = 7200
  const int tid = threadIdx.x;
  const int n0 = blockIdx.x * 32;

  for (int i = tid; i < 1024; i += NT) WHs[i] = wh[i];
  for (int i = tid; i < 512;  i += NT) WVs[i] = wv[i];
  for (int i = tid; i < 100;  i += NT) BSs[i] = bs[i];
  const float* gin = g_t + (size_t)blockIdx.x * (496 * 32);
  for (int idx = tid; idx < 496 * 32; idx += NT) {
    if (idx < 96 * 32) VC[idx] = gin[idx];
    else               SC[idx - 96 * 32] = gin[idx];
  }
  for (int idx = tid; idx < 148 * 32; idx += NT) {
    int r = idx >> 5, e = idx & 31;
    HVT[r * 33 + e] = g_hv[(size_t)(n0 + e) * 148 + r];
  }
  if (tid < 32) ST[96 + tid] = (float)maskV[n0 + tid];
  __syncthreads();
  gemm_rt<32,32,3,32,32,false,false,false>(VC, WHs, nullptr, nullptr, VH, tid);
  __syncthreads();
  for (int t = tid; t < 32 * 32; t += NT) {
    int h = t >> 5, e = t & 31;
    float a = VH[h*32+e], b = VH[(32+h)*32+e], c2 = VH[(64+h)*32+e];
    SC[(400 + h) * 32 + e] = sqrtf(fmaxf(a*a + b*b + c2*c2, 1e-8f));
  }
  gemm_rt<32,16,3,32,16,false,false,false>(VH, WVs, nullptr, nullptr, VO, tid);
  gemm_st<432,100,36,false,true,false>(SC, ws, nullptr, BSs, SO, WBUF, tid);
  __syncthreads();
  for (int idx = tid; idx < 148 * 32; idx += NT) {
    int r = idx >> 5, e = idx & 31;
    float add = (r < 48) ? VO[r * 32 + e] : SO[(r - 48) * 32 + e];
    HVT[r * 33 + e] += add;
  }
  __syncthreads();
  if (tid < 32) {
    const int e = tid;
    float vm = 0.f;
    #pragma unroll
    for (int i = 0; i < 16; ++i) {
      float a = HVT[i*33+e], b = HVT[(16+i)*33+e], c2 = HVT[(32+i)*33+e];
      vm += fmaxf(a*a + b*b + c2*c2, 1e-8f);
    }
    float mu = 0.f;
    #pragma unroll 4
    for (int j = 0; j < 100; ++j) mu += HVT[(48+j)*33+e];
    mu *= 0.01f;
    float var = 0.f;
    #pragma unroll 4
    for (int j = 0; j < 100; ++j) { float d = HVT[(48+j)*33+e] - mu; var += d*d; }
    var *= 0.01f;
    ST[e] = rsqrtf(vm * (1.f/16.f));
    ST[32+e] = mu;
    ST[64+e] = rsqrtf(var + 1e-3f);
  }
  __syncthreads();
  for (int idx = tid; idx < 32 * 148; idx += NT) {
    int e = idx / 148, r = idx - e * 148;
    float v = HVT[r * 33 + e];
    if (r < 48) v = v * ST[e];
    else { int j = r - 48; v = (v - ST[32+e]) * ST[64+e] * ln2g[j] + ln2b[j]; }
    out[(size_t)(n0 + e) * 148 + r] = ST[96 + e] * v;
  }
}

// ---------------------------------------------------------------------------
extern "C" void kernel_launch(void* const* d_in, const int* in_sizes, int n_in,
                              void* d_out, int out_size)
{
  const float* hV      = (const float*)d_in[0];
  const float* hM      = (const float*)d_in[1];
  const int*   maskV   = (const int*)  d_in[2];
  const int*   maskA   = (const int*)  d_in[3];
  const float* wev1_wh = (const float*)d_in[4];
  const float* wev1_ws = (const float*)d_in[5];
  const float* wev1_bs = (const float*)d_in[6];
  const float* wev1_wv = (const float*)d_in[7];
  const float* wev2_wh = (const float*)d_in[8];
  const float* wev2_ws = (const float*)d_in[9];
  const float* wev2_bs = (const float*)d_in[10];
  const float* wev2_wv = (const float*)d_in[11];
  const float* wev3_wh = (const float*)d_in[12];
  const float* wev3_ws = (const float*)d_in[13];
  const float* wev3_bs = (const float*)d_in[14];
  const float* wev3_wv = (const float*)d_in[15];
  const float* wdh1_wh = (const float*)d_in[16];
  const float* wdh1_ws = (const float*)d_in[17];
  const float* wdh1_bs = (const float*)d_in[18];
  const float* wdh1_wv = (const float*)d_in[19];
  const float* wdh2_wh = (const float*)d_in[20];
  const float* wdh2_ws = (const float*)d_in[21];
  const float* wdh2_bs = (const float*)d_in[22];
  const float* wdh2_wv = (const float*)d_in[23];
  const float* ln1g = (const float*)d_in[24];
  const float* ln1b = (const float*)d_in[25];
  const float* ln2g = (const float*)d_in[26];
  const float* ln2b = (const float*)d_in[27];
  float* out = (float*)d_out;

  int dev = 0; cudaGetDevice(&dev);
  int sms = 148;
  cudaDeviceGetAttribute(&sms, cudaDevAttrMultiProcessorCount, dev);

  const size_t SM1 = (size_t)(23112 + 2 * ECH * 100) * sizeof(float);                 // ~113.2 KB
  const size_t SM2 = (size_t)(1536+4224+3072+3072+12800+512+1024+400+9600) * sizeof(float);
  const size_t SM3 = (size_t)(3072+13824+3072+1536+3200+4884+128+1024+512+100+7200) * sizeof(float);

  cudaFuncSetAttribute(k_edge, cudaFuncAttributeMaxDynamicSharedMemorySize, (int)SM1);
  cudaFuncSetAttribute(k_dh1,  cudaFuncAttributeMaxDynamicSharedMemorySize, (int)SM2);
  cudaFuncSetAttribute(k_dh2,  cudaFuncAttributeMaxDynamicSharedMemorySize, (int)SM3);

  k_pre <<<sms, NT>>>(hV, wev1_ws, wev1_wh);
  k_edge<<<2 * sms, NT, SM1>>>(hV, hM, maskA,
                               wev1_wh, wev1_ws, wev1_bs, wev1_wv,
                               wev2_wh, wev2_ws, wev2_bs, wev2_wv,
                               wev3_wh, wev3_ws, wev3_bs, wev3_wv,
                               ln1g, ln1b);
  k_dh1<<<NODES / 32, NT, SM2>>>(wdh1_wh, wdh1_ws, wdh1_bs, wdh1_wv);
  k_dh2<<<NODES / 32, NT, SM3>>>(wdh2_wh, wdh2_ws, wdh2_bs, wdh2_wv,
                                 ln2g, ln2b, maskV, out);
}

// round 6
// speedup vs baseline: 9.4787x; 1.2763x over previous
#include <cuda_runtime.h>
#include <cuda_pipeline.h>
#include <math.h>
#include <stdint.h>

#define NT 256
constexpr int NODES = 4 * 2048;

__device__ float g_hv[NODES * 148];
__device__ float g_t [NODES * 496];
__device__ float g_sb[NODES * 100];
__device__ float g_vb[NODES * 108];

// ---------------- register-tiled GEMM, weights in SMEM ----------------------
template<int KD,int NROW,int NC,int ARS,int WSTR,bool INITF,bool BIASF,bool RELUF>
__device__ __forceinline__ void gemm_rt(
    const float* __restrict__ A, const float* __restrict__ W,
    const float* __restrict__ initv, const float* __restrict__ bias,
    float* __restrict__ O, const int tid)
{
  constexpr int GPC = NROW / 4;
  constexpr int G   = NC * GPC;
  const int eg = (tid & 7) * 4;
  for (int g = tid >> 3; g < G; g += 32) {
    const int c  = g / GPC;
    const int rg = (g - c * GPC) * 4;
    float4 a0, a1, a2, a3;
    if (INITF) {
      const float* iv = initv + c * NROW + rg;
      a0 = make_float4(iv[0], iv[0], iv[0], iv[0]);
      a1 = make_float4(iv[1], iv[1], iv[1], iv[1]);
      a2 = make_float4(iv[2], iv[2], iv[2], iv[2]);
      a3 = make_float4(iv[3], iv[3], iv[3], iv[3]);
    } else {
      a0 = make_float4(0.f,0.f,0.f,0.f); a1 = a0; a2 = a0; a3 = a0;
    }
    const float* ap = A + (size_t)(c * ARS) * 32 + eg;
    const float* wp = W + rg;
    #pragma unroll 4
    for (int k = 0; k < KD; ++k) {
      const float4 av = *(const float4*)(ap + (size_t)k * 32);
      const float4 wv4 = *(const float4*)(wp + (size_t)k * WSTR);
      a0.x += wv4.x*av.x; a0.y += wv4.x*av.y; a0.z += wv4.x*av.z; a0.w += wv4.x*av.w;
      a1.x += wv4.y*av.x; a1.y += wv4.y*av.y; a1.z += wv4.y*av.z; a1.w += wv4.y*av.w;
      a2.x += wv4.z*av.x; a2.y += wv4.z*av.y; a2.z += wv4.z*av.z; a2.w += wv4.z*av.w;
      a3.x += wv4.w*av.x; a3.y += wv4.w*av.y; a3.z += wv4.w*av.z; a3.w += wv4.w*av.w;
    }
    if (BIASF) {
      const float* bp = bias + c * NROW + rg;
      float b0=bp[0], b1=bp[1], b2=bp[2], b3=bp[3];
      a0.x+=b0; a0.y+=b0; a0.z+=b0; a0.w+=b0;
      a1.x+=b1; a1.y+=b1; a1.z+=b1; a1.w+=b1;
      a2.x+=b2; a2.y+=b2; a2.z+=b2; a2.w+=b2;
      a3.x+=b3; a3.y+=b3; a3.z+=b3; a3.w+=b3;
    }
    if (RELUF) {
      a0.x=fmaxf(a0.x,0.f); a0.y=fmaxf(a0.y,0.f); a0.z=fmaxf(a0.z,0.f); a0.w=fmaxf(a0.w,0.f);
      a1.x=fmaxf(a1.x,0.f); a1.y=fmaxf(a1.y,0.f); a1.z=fmaxf(a1.z,0.f); a1.w=fmaxf(a1.w,0.f);
      a2.x=fmaxf(a2.x,0.f); a2.y=fmaxf(a2.y,0.f); a2.z=fmaxf(a2.z,0.f); a2.w=fmaxf(a2.w,0.f);
      a3.x=fmaxf(a3.x,0.f); a3.y=fmaxf(a3.y,0.f); a3.z=fmaxf(a3.z,0.f); a3.w=fmaxf(a3.w,0.f);
    }
    float* op = O + (size_t)(c * NROW + rg) * 32 + eg;
    *(float4*)(op)      = a0;
    *(float4*)(op + 32) = a1;
    *(float4*)(op + 64) = a2;
    *(float4*)(op + 96) = a3;
  }
}

// ------- chunked scalar GEMM with cp.async weight staging (dh kernels) -----
template<int KD,int NROW,int CH,bool INITF,bool BIASF,bool RELUF>
__device__ __forceinline__ void gemm_st(
    const float* __restrict__ A, const float* __restrict__ Wg,
    const float* __restrict__ initv, const float* __restrict__ bias,
    float* __restrict__ O, float* __restrict__ wbuf, const int tid)
{
  constexpr int G    = NROW / 4;
  constexpr int GMAX = (G + 31) / 32;
  constexpr int NCH  = (KD + CH - 1) / CH;
  const int eg = (tid & 7) * 4;
  const int g0 = tid >> 3;

  float4 acc[GMAX][4];
  #pragma unroll
  for (int j = 0; j < GMAX; ++j) {
    int g = g0 + 32 * j;
    if (g < G) {
      int rg = g * 4;
      #pragma unroll
      for (int r = 0; r < 4; ++r) {
        float iv = INITF ? initv[rg + r] : 0.f;
        acc[j][r] = make_float4(iv, iv, iv, iv);
      }
    }
  }
  {
    int rows = (KD < CH) ? KD : CH;
    int cnt = rows * NROW / 4;
    for (int i = tid; i < cnt; i += NT)
      __pipeline_memcpy_async(wbuf + i * 4, Wg + i * 4, 16);
    __pipeline_commit();
  }
  for (int c = 0; c < NCH; ++c) {
    if (c + 1 < NCH) {
      int base = (c + 1) * CH;
      int rows = ((KD - base) < CH) ? (KD - base) : CH;
      int cnt = rows * NROW / 4;
      float* db = wbuf + ((c + 1) & 1) * (CH * NROW);
      const float* sp = Wg + (size_t)base * NROW;
      for (int i = tid; i < cnt; i += NT)
        __pipeline_memcpy_async(db + i * 4, sp + i * 4, 16);
      __pipeline_commit();
      __pipeline_wait_prior(1);
    } else {
      __pipeline_wait_prior(0);
    }
    __syncthreads();
    const float* wb = wbuf + (c & 1) * (CH * NROW);
    const int kmax = ((KD - c * CH) < CH) ? (KD - c * CH) : CH;
    const float* ap = A + (size_t)(c * CH) * 32 + eg;
    #pragma unroll
    for (int j = 0; j < GMAX; ++j) {
      int g = g0 + 32 * j;
      if (g < G) {
        const float* wp = wb + g * 4;
        #pragma unroll 4
        for (int k = 0; k < kmax; ++k) {
          const float4 av = *(const float4*)(ap + k * 32);
          const float4 wv = *(const float4*)(wp + (size_t)k * NROW);
          acc[j][0].x += wv.x*av.x; acc[j][0].y += wv.x*av.y; acc[j][0].z += wv.x*av.z; acc[j][0].w += wv.x*av.w;
          acc[j][1].x += wv.y*av.x; acc[j][1].y += wv.y*av.y; acc[j][1].z += wv.y*av.z; acc[j][1].w += wv.y*av.w;
          acc[j][2].x += wv.z*av.x; acc[j][2].y += wv.z*av.y; acc[j][2].z += wv.z*av.z; acc[j][2].w += wv.z*av.w;
          acc[j][3].x += wv.w*av.x; acc[j][3].y += wv.w*av.y; acc[j][3].z += wv.w*av.z; acc[j][3].w += wv.w*av.w;
        }
      }
    }
    __syncthreads();
  }
  #pragma unroll
  for (int j = 0; j < GMAX; ++j) {
    int g = g0 + 32 * j;
    if (g < G) {
      int rg = g * 4;
      #pragma unroll
      for (int r = 0; r < 4; ++r) {
        float4 a = acc[j][r];
        if (BIASF) { float b = bias[rg + r]; a.x += b; a.y += b; a.z += b; a.w += b; }
        if (RELUF) { a.x=fmaxf(a.x,0.f); a.y=fmaxf(a.y,0.f); a.z=fmaxf(a.z,0.f); a.w=fmaxf(a.w,0.f); }
        *(float4*)(O + (size_t)(rg + r) * 32 + eg) = a;
      }
    }
  }
}

// -------------------- tf32 mma helpers -------------------------------------
__device__ __forceinline__ uint32_t f2tf(float x){
  uint32_t r; asm("cvt.rna.tf32.f32 %0, %1;" : "=r"(r) : "f"(x)); return r;
}
__device__ __forceinline__ void mma8(float* c, uint32_t a0,uint32_t a1,uint32_t a2,uint32_t a3,
                                     uint32_t b0,uint32_t b1){
  asm volatile("mma.sync.aligned.m16n8k8.row.col.f32.tf32.tf32.f32 "
    "{%0,%1,%2,%3}, {%4,%5,%6,%7}, {%8,%9}, {%0,%1,%2,%3};"
    : "+f"(c[0]),"+f"(c[1]),"+f"(c[2]),"+f"(c[3])
    : "r"(a0),"r"(a1),"r"(a2),"r"(a3),"r"(b0),"r"(b1));
}

// tf32 MMA GEMM: C^T[32 edges][100 outs] = As[32][KPAD] * W[KREAL][100]
// As: smem, row stride ASTR (>=KPAD). W: global, staged to smem stride 104.
// OT: smem out, row=edge stride OSTR, only cols m<100 written.
// All 256 threads must call (internal syncthreads).
template<int KPAD,int KREAL,int CH,int ASTR,int OSTR,bool INITF,bool RELUF>
__device__ __forceinline__ void gemm_mma(
    const float* __restrict__ As, const float* __restrict__ Wg,
    const float* __restrict__ initv, const float* __restrict__ bias,
    float* __restrict__ OT, float* __restrict__ wbuf, const int tid)
{
  constexpr int WS  = 104;
  constexpr int NCH = KPAD / CH;
  static_assert(KPAD % CH == 0 && CH % 8 == 0, "pad");
  const int lane = tid & 31;
  const int warp = tid >> 5;
  const int g  = lane >> 2;
  const int tq = lane & 3;
  const int mt = warp >> 2;        // m-tile: edges mt*16..mt*16+15
  const int q  = warp & 3;         // n-tiles q, q+4, q+8 [, 12 if q==0]
  const int jn = (q == 0) ? 4 : 3; // 13 n-tiles over 4 warps
  float acc[4][4];
  #pragma unroll
  for (int j=0;j<4;++j){acc[j][0]=0.f;acc[j][1]=0.f;acc[j][2]=0.f;acc[j][3]=0.f;}

  // stage chunk 0 (rows >= KREAL zero-filled)
  for (int i = tid; i < CH*25; i += NT) {
    int r = i / 25, c4 = i - r*25;
    if (r < KREAL) __pipeline_memcpy_async(wbuf + r*WS + c4*4, Wg + (size_t)r*100 + c4*4, 16);
    else { float4 z = make_float4(0.f,0.f,0.f,0.f); *(float4*)(wbuf + r*WS + c4*4) = z; }
  }
  __pipeline_commit();

  for (int ch = 0; ch < NCH; ++ch) {
    if (ch + 1 < NCH) {
      int base = (ch + 1) * CH;
      float* db = wbuf + ((ch + 1) & 1) * (CH * WS);
      for (int i = tid; i < CH*25; i += NT) {
        int r = i / 25, c4 = i - r*25;
        int kr = base + r;
        if (kr < KREAL) __pipeline_memcpy_async(db + r*WS + c4*4, Wg + (size_t)kr*100 + c4*4, 16);
        else { float4 z = make_float4(0.f,0.f,0.f,0.f); *(float4*)(db + r*WS + c4*4) = z; }
      }
      __pipeline_commit();
      __pipeline_wait_prior(1);
    } else {
      __pipeline_wait_prior(0);
    }
    __syncthreads();
    const float* wb = wbuf + (ch & 1) * (CH * WS);
    const float* arow = As + (size_t)(mt*16 + g) * ASTR + ch*CH;
    #pragma unroll
    for (int k8 = 0; k8 < CH/8; ++k8) {
      const float* ar = arow + k8*8;
      uint32_t a0 = f2tf(ar[tq]);
      uint32_t a1 = f2tf(ar[8*ASTR + tq]);
      uint32_t a2 = f2tf(ar[tq + 4]);
      uint32_t a3 = f2tf(ar[8*ASTR + tq + 4]);
      const float* wrow = wb + (k8*8 + tq)*WS + g;
      #pragma unroll
      for (int j = 0; j < 4; ++j) {
        if (j < jn) {
          const float* wr = wrow + (q + 4*j)*8;
          uint32_t b0 = f2tf(wr[0]);
          uint32_t b1 = f2tf(wr[4*WS]);
          mma8(acc[j], a0,a1,a2,a3, b0,b1);
        }
      }
    }
    __syncthreads();
  }
  // epilogue: c0=(e=g, m=2tq), c1=(g, 2tq+1), c2=(g+8, 2tq), c3=(g+8, 2tq+1)
  const int e0 = mt*16 + g;
  #pragma unroll
  for (int j = 0; j < 4; ++j) {
    if (j < jn) {
      int mb = (q + 4*j)*8 + 2*tq;
      #pragma unroll
      for (int hf = 0; hf < 2; ++hf) {
        int m = mb + hf;
        if (m < 100) {
          float add = (INITF ? initv[m] : 0.f) + bias[m];
          float v0 = acc[j][hf]   + add;
          float v1 = acc[j][2+hf] + add;
          if (RELUF) { v0 = fmaxf(v0, 0.f); v1 = fmaxf(v1, 0.f); }
          OT[(size_t)e0 * OSTR + m]       = v0;
          OT[(size_t)(e0+8) * OSTR + m]   = v1;
        }
      }
    }
  }
}

// ------------------------------ K0: hoisted per-node partials --------------
__global__ __launch_bounds__(NT)
void k_pre(const float* __restrict__ hV,
           const float* __restrict__ ws1, const float* __restrict__ wh1)
{
  __shared__ float W[10000];
  __shared__ float WH[528];
  __shared__ float HSv[148];
  const int tid = threadIdx.x;
  for (int i = tid; i < 10000; i += NT) W[i]  = ws1[i];
  for (int i = tid; i < 528;   i += NT) WH[i] = wh1[i];
  __syncthreads();
  for (int node = blockIdx.x; node < NODES; node += gridDim.x) {
    for (int t = tid; t < 148; t += NT) HSv[t] = hV[node * 148 + t];
    __syncthreads();
    for (int t = tid; t < 208; t += NT) {
      if (t < 100) {
        float acc = 0.f;
        #pragma unroll 4
        for (int j = 0; j < 100; ++j) acc += HSv[48 + j] * W[j * 100 + t];
        g_sb[node * 100 + t] = acc;
      } else {
        int u = t - 100, c = u / 36, h = u - c * 36;
        float acc = 0.f;
        if (h < 33) {
          #pragma unroll
          for (int i = 0; i < 16; ++i) acc += HSv[c * 16 + i] * WH[i * 33 + h];
        }
        g_vb[node * 108 + u] = acc;
      }
    }
    __syncthreads();
  }
}

// ------------------------------ K1: edges + mean + LN1 ---------------------
// SMEM float offsets
#define O_WH1P 0
#define O_WV1  1188
#define O_BS1  1716
#define O_WH2  1816
#define O_WV2  2072
#define O_BS2  2328
#define O_WH3  2428
#define O_WV3  2684
#define O_BS3  2940
#define O_LG1  3040
#define O_LB1  3140
#define O_HS   3240
#define O_MK   3388
#define O_SB   3420
#define O_VB   3520
#define O_VC1  3628
#define O_SC1T 5260   /* [32][172] */
#define O_VHX  10764  /* [108][32]; EB staging alias (with BFAT) */
#define O_BFAT 14220  /* [32][124] */
#define O_VOA  18188  /* [48][32] */
#define O_DH   19724
#define O_MISC 19872
#define O_WBUF 19880  /* 2*24*104 = 4992 */
#define SM1_FLOATS 24872

__global__ __launch_bounds__(NT, 2)
void k_edge(const float* __restrict__ hV, const float* __restrict__ hM,
            const int* __restrict__ maskA,
            const float* __restrict__ wh1, const float* __restrict__ ws1,
            const float* __restrict__ bs1, const float* __restrict__ wv1,
            const float* __restrict__ wh2, const float* __restrict__ ws2,
            const float* __restrict__ bs2, const float* __restrict__ wv2,
            const float* __restrict__ wh3, const float* __restrict__ ws3,
            const float* __restrict__ bs3, const float* __restrict__ wv3,
            const float* __restrict__ ln1g, const float* __restrict__ ln1b)
{
  extern __shared__ float sm[];
  float* WH1P = sm + O_WH1P;
  float* WV1  = sm + O_WV1;
  float* BS1s = sm + O_BS1;
  float* WH2s = sm + O_WH2;
  float* WV2s = sm + O_WV2;
  float* BS2s = sm + O_BS2;
  float* WH3s = sm + O_WH3;
  float* WV3s = sm + O_WV3;
  float* BS3s = sm + O_BS3;
  float* LG1  = sm + O_LG1;
  float* LB1  = sm + O_LB1;
  float* HS   = sm + O_HS;
  float* MK   = sm + O_MK;
  float* SB   = sm + O_SB;
  float* VB   = sm + O_VB;
  float* VC1  = sm + O_VC1;
  float* SC1T = sm + O_SC1T;   // GVP1 A operand [32][172]
  float* VHX  = sm + O_VHX;
  float* BFAT = sm + O_BFAT;   // GVP2 A / GVP3 out [32][124]
  float* BFBT = sm + O_SC1T;   // GVP3 A (aliases SC1T region) [32][124]
  float* VOA  = sm + O_VOA;
  float* DH   = sm + O_DH;
  float* MISC = sm + O_MISC;
  float* WBUF = sm + O_WBUF;
  float* EB   = sm + O_VHX;    // staging 5490 floats (VHX+BFAT region)
  const int tid = threadIdx.x;

  // ---- weight/LN staging + one-time zero init (NaN protection) ----
  for (int i = tid; i < 1188; i += NT) { int r = i / 36, c = i - r * 36; WH1P[i] = (c < 33) ? wh1[r * 33 + c] : 0.f; }
  for (int i = tid; i < 528;  i += NT) WV1[i]  = wv1[i];
  for (int i = tid; i < 100;  i += NT) { BS1s[i] = bs1[i]; BS2s[i] = bs2[i]; BS3s[i] = bs3[i]; LG1[i] = ln1g[i]; LB1[i] = ln1b[i]; }
  for (int i = tid; i < 256;  i += NT) { WH2s[i] = wh2[i]; WV2s[i] = wv2[i]; WH3s[i] = wh3[i]; WV3s[i] = wv3[i]; }
  for (int i = tid; i < 1632; i += NT) VC1[i]  = 0.f;
  for (int i = tid; i < 5504; i += NT) SC1T[i] = 0.f;
  for (int i = tid; i < 3968; i += NT) BFAT[i] = 0.f;
  for (int i = tid; i < 4992; i += NT) WBUF[i] = 0.f;
  __syncthreads();

  for (int node = blockIdx.x; node < NODES; node += gridDim.x) {
    const float* mp = hM + (size_t)node * 5490;
    for (int t = tid; t < 5490; t += NT) EB[t] = mp[t];
    for (int t = tid; t < 148; t += NT) HS[t] = hV[node * 148 + t];
    for (int t = tid; t < 100; t += NT) SB[t] = g_sb[node * 100 + t];
    for (int t = tid; t < 108; t += NT) VB[t] = g_vb[node * 108 + t];
    for (int t = tid; t < 32;  t += NT) MK[t] = (t < 30) ? (float)maskA[node * 30 + t] : 0.f;
    __syncthreads();
    // vectors -> VC1 [51][32] (j-major, e<30)
    for (int idx = tid; idx < 51 * 32; idx += NT) {
      int j = idx >> 5, e = idx & 31;
      if (e < 30) VC1[j * 32 + e] = EB[e * 183 + j];
    }
    // scalars -> SC1T [e][0..131] (e-major, conflict-free)
    for (int idx = tid; idx < 30 * 132; idx += NT) {
      int e = idx / 132, j = idx - e * 132;
      SC1T[e * 172 + j] = EB[e * 183 + 51 + j];
    }
    __syncthreads();
    // GVP1 vector hidden
    gemm_rt<17,36,3,17,36,true,false,false>(VC1, WH1P + 16 * 36, VB, nullptr, VHX, tid);
    __syncthreads();
    // vn1 -> SC1T cols 132..164
    for (int t = tid; t < 33 * 32; t += NT) {
      int h = t >> 5, e = t & 31;
      float a = VHX[h*32+e], b = VHX[(36+h)*32+e], c2 = VHX[(72+h)*32+e];
      SC1T[e * 172 + 132 + h] = sqrtf(fmaxf(a*a + b*b + c2*c2, 1e-8f));
    }
    gemm_rt<33,16,3,36,16,false,false,false>(VHX, WV1, nullptr, nullptr, VOA, tid);
    // GVP1 s-GEMM (tf32 mma): K=165 pad 168
    gemm_mma<168,165,24,172,124,true,true>(SC1T, ws1 + 10000, SB, BS1s, BFAT, WBUF, tid);
    // gate1
    for (int t = tid; t < 16 * 32; t += NT) {
      int o = t >> 5, e = t & 31;
      float a = VOA[o*32+e], b = VOA[(16+o)*32+e], c2 = VOA[(32+o)*32+e];
      float n = sqrtf(fmaxf(a*a + b*b + c2*c2, 1e-8f));
      float gt = 1.f / (1.f + expf(-n));
      VOA[o*32+e] = a*gt; VOA[(16+o)*32+e] = b*gt; VOA[(32+o)*32+e] = c2*gt;
    }
    __syncthreads();
    // GVP2
    gemm_rt<16,16,3,16,16,false,false,false>(VOA, WH2s, nullptr, nullptr, VHX, tid);
    __syncthreads();
    for (int t = tid; t < 16 * 32; t += NT) {
      int h = t >> 5, e = t & 31;
      float a = VHX[h*32+e], b = VHX[(16+h)*32+e], c2 = VHX[(32+h)*32+e];
      BFAT[e * 124 + 100 + h] = sqrtf(fmaxf(a*a + b*b + c2*c2, 1e-8f));
    }
    gemm_rt<16,16,3,16,16,false,false,false>(VHX, WV2s, nullptr, nullptr, VOA, tid);
    gemm_mma<120,116,24,124,124,false,true>(BFAT, ws2, nullptr, BS2s, BFBT, WBUF, tid);
    // gate2
    for (int t = tid; t < 16 * 32; t += NT) {
      int o = t >> 5, e = t & 31;
      float a = VOA[o*32+e], b = VOA[(16+o)*32+e], c2 = VOA[(32+o)*32+e];
      float n = sqrtf(fmaxf(a*a + b*b + c2*c2, 1e-8f));
      float gt = 1.f / (1.f + expf(-n));
      VOA[o*32+e] = a*gt; VOA[(16+o)*32+e] = b*gt; VOA[(32+o)*32+e] = c2*gt;
    }
    __syncthreads();
    // GVP3
    gemm_rt<16,16,3,16,16,false,false,false>(VOA, WH3s, nullptr, nullptr, VHX, tid);
    __syncthreads();
    for (int t = tid; t < 16 * 32; t += NT) {
      int h = t >> 5, e = t & 31;
      float a = VHX[h*32+e], b = VHX[(16+h)*32+e], c2 = VHX[(32+h)*32+e];
      BFBT[e * 124 + 100 + h] = sqrtf(fmaxf(a*a + b*b + c2*c2, 1e-8f));
    }
    gemm_rt<16,16,3,16,16,false,false,false>(VHX, WV3s, nullptr, nullptr, VOA, tid);
    gemm_mma<120,116,24,124,124,false,false>(BFBT, ws3, nullptr, BS3s, BFAT, WBUF, tid);
    __syncthreads();
    // masked mean + residual (scalars read from transposed BFAT)
    for (int t = tid; t < 148; t += NT) {
      float acc = 0.f;
      if (t < 48) {
        #pragma unroll
        for (int ee = 0; ee < 32; ++ee) {
          int e = (ee + t) & 31;
          acc += MK[e] * VOA[t * 32 + e];
        }
      } else {
        int r = t - 48;
        #pragma unroll 8
        for (int e = 0; e < 30; ++e) acc += MK[e] * BFAT[e * 124 + r];
      }
      DH[t] = HS[t] + acc * (1.f / 30.f);
    }
    __syncthreads();
    if (tid < 32) {
      float vm = 0.f;
      if (tid < 16) { float a = DH[tid], b = DH[16+tid], c2 = DH[32+tid]; vm = fmaxf(a*a + b*b + c2*c2, 1e-8f); }
      #pragma unroll
      for (int o = 16; o; o >>= 1) vm += __shfl_xor_sync(0xffffffffu, vm, o);
      float s0 = DH[48+tid], s1 = DH[80+tid], s2v = DH[112+tid];
      float s3v = (tid < 4) ? DH[144+tid] : 0.f;
      float p = s0 + s1 + s2v + s3v;
      #pragma unroll
      for (int o = 16; o; o >>= 1) p += __shfl_xor_sync(0xffffffffu, p, o);
      float mu = p * 0.01f;
      float d0 = s0-mu, d1 = s1-mu, d2 = s2v-mu;
      float q = d0*d0 + d1*d1 + d2*d2;
      if (tid < 4) { float d3 = s3v - mu; q += d3*d3; }
      #pragma unroll
      for (int o = 16; o; o >>= 1) q += __shfl_xor_sync(0xffffffffu, q, o);
      if (tid == 0) { MISC[0] = rsqrtf(vm * (1.f/16.f)); MISC[1] = mu; MISC[2] = rsqrtf(q * 0.01f + 1e-3f); }
    }
    __syncthreads();
    for (int t = tid; t < 148; t += NT) {
      float v;
      if (t < 48) v = DH[t] * MISC[0];
      else { int j = t - 48; v = (DH[t] - MISC[1]) * MISC[2] * LG1[j] + LB1[j]; }
      g_hv[node * 148 + t] = v;
    }
    __syncthreads();
  }
}

// ------------------------------ K2: dh1 over 32-node tiles -----------------
__global__ __launch_bounds__(NT)
void k_dh1(const float* __restrict__ wh, const float* __restrict__ ws,
           const float* __restrict__ bs, const float* __restrict__ wv)
{
  extern __shared__ float sm[];
  float* VC   = sm;            // 1536
  float* SC   = VC + 1536;     // 4224
  float* VH   = SC + 4224;     // 3072
  float* VO   = VH + 3072;     // 3072
  float* SO   = VO + 3072;     // 12800
  float* WHs  = SO + 12800;    // 512
  float* WVs  = WHs + 512;     // 1024
  float* BSs  = WVs + 1024;    // 400
  float* WBUF = BSs + 400;     // 9600
  const int tid = threadIdx.x;
  const int n0 = blockIdx.x * 32;

  for (int i = tid; i < 512;  i += NT) WHs[i] = wh[i];
  for (int i = tid; i < 1024; i += NT) WVs[i] = wv[i];
  for (int i = tid; i < 400;  i += NT) BSs[i] = bs[i];
  for (int idx = tid; idx < 148 * 32; idx += NT) {
    int r = idx >> 5, e = idx & 31;
    float v = g_hv[(size_t)(n0 + e) * 148 + r];
    if (r < 48) VC[r * 32 + e] = v; else SC[(r - 48) * 32 + e] = v;
  }
  __syncthreads();
  gemm_rt<16,32,3,16,32,false,false,false>(VC, WHs, nullptr, nullptr, VH, tid);
  __syncthreads();
  for (int t = tid; t < 32 * 32; t += NT) {
    int h = t >> 5, e = t & 31;
    float a = VH[h*32+e], b = VH[(32+h)*32+e], c2 = VH[(64+h)*32+e];
    SC[(100 + h) * 32 + e] = sqrtf(fmaxf(a*a + b*b + c2*c2, 1e-8f));
  }
  gemm_rt<32,32,3,32,32,false,false,false>(VH, WVs, nullptr, nullptr, VO, tid);
  gemm_st<132,400,12,false,true,true>(SC, ws, nullptr, BSs, SO, WBUF, tid);
  __syncthreads();
  for (int t = tid; t < 32 * 32; t += NT) {
    int o = t >> 5, e = t & 31;
    float a = VO[o*32+e], b = VO[(32+o)*32+e], c2 = VO[(64+o)*32+e];
    float n = sqrtf(fmaxf(a*a + b*b + c2*c2, 1e-8f));
    float gt = 1.f / (1.f + expf(-n));
    VO[o*32+e] = a*gt; VO[(32+o)*32+e] = b*gt; VO[(64+o)*32+e] = c2*gt;
  }
  __syncthreads();
  float* gout = g_t + (size_t)blockIdx.x * (496 * 32);
  for (int idx = tid; idx < 496 * 32; idx += NT)
    gout[idx] = (idx < 96 * 32) ? VO[idx] : SO[idx - 96 * 32];
}

// ------------------------------ K3: dh2 + LN2 + mask -----------------------
__global__ __launch_bounds__(NT)
void k_dh2(const float* __restrict__ wh, const float* __restrict__ ws,
           const float* __restrict__ bs, const float* __restrict__ wv,
           const float* __restrict__ ln2g, const float* __restrict__ ln2b,
           const int* __restrict__ maskV, float* __restrict__ out)
{
  extern __shared__ float sm[];
  float* VC   = sm;            // 3072
  float* SC   = VC + 3072;     // 13824
  float* VH   = SC + 13824;    // 3072
  float* VO   = VH + 3072;     // 1536
  float* SO   = VO + 1536;     // 3200
  float* HVT  = SO + 3200;     // 4884
  float* ST   = HVT + 4884;    // 128
  float* WHs  = ST + 128;      // 1024
  float* WVs  = WHs + 1024;    // 512
  float* BSs  = WVs + 512;     // 100
  float* WBUF = BSs + 100;     // 7200
  const int tid = threadIdx.x;
  const int n0 = blockIdx.x * 32;

  for (int i = tid; i < 1024; i += NT) WHs[i] = wh[i];
  for (int i = tid; i < 512;  i += NT) WVs[i] = wv[i];
  for (int i = tid; i < 100;  i += NT) BSs[i] = bs[i];
  const float* gin = g_t + (size_t)blockIdx.x * (496 * 32);
  for (int idx = tid; idx < 496 * 32; idx += NT) {
    if (idx < 96 * 32) VC[idx] = gin[idx];
    else               SC[idx - 96 * 32] = gin[idx];
  }
  for (int idx = tid; idx < 148 * 32; idx += NT) {
    int r = idx >> 5, e = idx & 31;
    HVT[r * 33 + e] = g_hv[(size_t)(n0 + e) * 148 + r];
  }
  if (tid < 32) ST[96 + tid] = (float)maskV[n0 + tid];
  __syncthreads();
  gemm_rt<32,32,3,32,32,false,false,false>(VC, WHs, nullptr, nullptr, VH, tid);
  __syncthreads();
  for (int t = tid; t < 32 * 32; t += NT) {
    int h = t >> 5, e = t & 31;
    float a = VH[h*32+e], b = VH[(32+h)*32+e], c2 = VH[(64+h)*32+e];
    SC[(400 + h) * 32 + e] = sqrtf(fmaxf(a*a + b*b + c2*c2, 1e-8f));
  }
  gemm_rt<32,16,3,32,16,false,false,false>(VH, WVs, nullptr, nullptr, VO, tid);
  gemm_st<432,100,36,false,true,false>(SC, ws, nullptr, BSs, SO, WBUF, tid);
  __syncthreads();
  for (int idx = tid; idx < 148 * 32; idx += NT) {
    int r = idx >> 5, e = idx & 31;
    float add = (r < 48) ? VO[r * 32 + e] : SO[(r - 48) * 32 + e];
    HVT[r * 33 + e] += add;
  }
  __syncthreads();
  if (tid < 32) {
    const int e = tid;
    float vm = 0.f;
    #pragma unroll
    for (int i = 0; i < 16; ++i) {
      float a = HVT[i*33+e], b = HVT[(16+i)*33+e], c2 = HVT[(32+i)*33+e];
      vm += fmaxf(a*a + b*b + c2*c2, 1e-8f);
    }
    float mu = 0.f;
    #pragma unroll 4
    for (int j = 0; j < 100; ++j) mu += HVT[(48+j)*33+e];
    mu *= 0.01f;
    float var = 0.f;
    #pragma unroll 4
    for (int j = 0; j < 100; ++j) { float d = HVT[(48+j)*33+e] - mu; var += d*d; }
    var *= 0.01f;
    ST[e] = rsqrtf(vm * (1.f/16.f));
    ST[32+e] = mu;
    ST[64+e] = rsqrtf(var + 1e-3f);
  }
  __syncthreads();
  for (int idx = tid; idx < 32 * 148; idx += NT) {
    int e = idx / 148, r = idx - e * 148;
    float v = HVT[r * 33 + e];
    if (r < 48) v = v * ST[e];
    else { int j = r - 48; v = (v - ST[32+e]) * ST[64+e] * ln2g[j] + ln2b[j]; }
    out[(size_t)(n0 + e) * 148 + r] = ST[96 + e] * v;
  }
}

// ---------------------------------------------------------------------------
extern "C" void kernel_launch(void* const* d_in, const int* in_sizes, int n_in,
                              void* d_out, int out_size)
{
  const float* hV      = (const float*)d_in[0];
  const float* hM      = (const float*)d_in[1];
  const int*   maskV   = (const int*)  d_in[2];
  const int*   maskA   = (const int*)  d_in[3];
  const float* wev1_wh = (const float*)d_in[4];
  const float* wev1_ws = (const float*)d_in[5];
  const float* wev1_bs = (const float*)d_in[6];
  const float* wev1_wv = (const float*)d_in[7];
  const float* wev2_wh = (const float*)d_in[8];
  const float* wev2_ws = (const float*)d_in[9];
  const float* wev2_bs = (const float*)d_in[10];
  const float* wev2_wv = (const float*)d_in[11];
  const float* wev3_wh = (const float*)d_in[12];
  const float* wev3_ws = (const float*)d_in[13];
  const float* wev3_bs = (const float*)d_in[14];
  const float* wev3_wv = (const float*)d_in[15];
  const float* wdh1_wh = (const float*)d_in[16];
  const float* wdh1_ws = (const float*)d_in[17];
  const float* wdh1_bs = (const float*)d_in[18];
  const float* wdh1_wv = (const float*)d_in[19];
  const float* wdh2_wh = (const float*)d_in[20];
  const float* wdh2_ws = (const float*)d_in[21];
  const float* wdh2_bs = (const float*)d_in[22];
  const float* wdh2_wv = (const float*)d_in[23];
  const float* ln1g = (const float*)d_in[24];
  const float* ln1b = (const float*)d_in[25];
  const float* ln2g = (const float*)d_in[26];
  const float* ln2b = (const float*)d_in[27];
  float* out = (float*)d_out;

  int dev = 0; cudaGetDevice(&dev);
  int sms = 148;
  cudaDeviceGetAttribute(&sms, cudaDevAttrMultiProcessorCount, dev);

  const size_t SM1 = (size_t)SM1_FLOATS * sizeof(float);   // ~97.2 KB -> 2 blocks/SM
  const size_t SM2 = (size_t)(1536+4224+3072+3072+12800+512+1024+400+9600) * sizeof(float);
  const size_t SM3 = (size_t)(3072+13824+3072+1536+3200+4884+128+1024+512+100+7200) * sizeof(float);

  cudaFuncSetAttribute(k_edge, cudaFuncAttributeMaxDynamicSharedMemorySize, (int)SM1);
  cudaFuncSetAttribute(k_dh1,  cudaFuncAttributeMaxDynamicSharedMemorySize, (int)SM2);
  cudaFuncSetAttribute(k_dh2,  cudaFuncAttributeMaxDynamicSharedMemorySize, (int)SM3);

  k_pre <<<sms, NT>>>(hV, wev1_ws, wev1_wh);
  k_edge<<<2 * sms, NT, SM1>>>(hV, hM, maskA,
                               wev1_wh, wev1_ws, wev1_bs, wev1_wv,
                               wev2_wh, wev2_ws, wev2_bs, wev2_wv,
                               wev3_wh, wev3_ws, wev3_bs, wev3_wv,
                               ln1g, ln1b);
  k_dh1<<<NODES / 32, NT, SM2>>>(wdh1_wh, wdh1_ws, wdh1_bs, wdh1_wv);
  k_dh2<<<NODES / 32, NT, SM3>>>(wdh2_wh, wdh2_ws, wdh2_bs, wdh2_wv,
                                 ln2g, ln2b, maskV, out);
}

// round 7
// speedup vs baseline: 9.5702x; 1.0096x over previous
#include <cuda_runtime.h>
#include <cuda_pipeline.h>
#include <math.h>
#include <stdint.h>

#define NT 256
constexpr int NODES = 4 * 2048;

__device__ float g_hv[NODES * 148];
__device__ float g_t [NODES * 496];   // per node: [0..95]=vectors(row r), [96..495]=scalars
__device__ float g_sb[NODES * 100];
__device__ float g_vb[NODES * 108];

// ---------------- register-tiled GEMM, weights in SMEM ----------------------
template<int KD,int NROW,int NC,int ARS,int WSTR,bool INITF,bool BIASF,bool RELUF>
__device__ __forceinline__ void gemm_rt(
    const float* __restrict__ A, const float* __restrict__ W,
    const float* __restrict__ initv, const float* __restrict__ bias,
    float* __restrict__ O, const int tid)
{
  constexpr int GPC = NROW / 4;
  constexpr int G   = NC * GPC;
  const int eg = (tid & 7) * 4;
  for (int g = tid >> 3; g < G; g += 32) {
    const int c  = g / GPC;
    const int rg = (g - c * GPC) * 4;
    float4 a0, a1, a2, a3;
    if (INITF) {
      const float* iv = initv + c * NROW + rg;
      a0 = make_float4(iv[0], iv[0], iv[0], iv[0]);
      a1 = make_float4(iv[1], iv[1], iv[1], iv[1]);
      a2 = make_float4(iv[2], iv[2], iv[2], iv[2]);
      a3 = make_float4(iv[3], iv[3], iv[3], iv[3]);
    } else {
      a0 = make_float4(0.f,0.f,0.f,0.f); a1 = a0; a2 = a0; a3 = a0;
    }
    const float* ap = A + (size_t)(c * ARS) * 32 + eg;
    const float* wp = W + rg;
    #pragma unroll 4
    for (int k = 0; k < KD; ++k) {
      const float4 av = *(const float4*)(ap + (size_t)k * 32);
      const float4 wv4 = *(const float4*)(wp + (size_t)k * WSTR);
      a0.x += wv4.x*av.x; a0.y += wv4.x*av.y; a0.z += wv4.x*av.z; a0.w += wv4.x*av.w;
      a1.x += wv4.y*av.x; a1.y += wv4.y*av.y; a1.z += wv4.y*av.z; a1.w += wv4.y*av.w;
      a2.x += wv4.z*av.x; a2.y += wv4.z*av.y; a2.z += wv4.z*av.z; a2.w += wv4.z*av.w;
      a3.x += wv4.w*av.x; a3.y += wv4.w*av.y; a3.z += wv4.w*av.z; a3.w += wv4.w*av.w;
    }
    if (BIASF) {
      const float* bp = bias + c * NROW + rg;
      float b0=bp[0], b1=bp[1], b2=bp[2], b3=bp[3];
      a0.x+=b0; a0.y+=b0; a0.z+=b0; a0.w+=b0;
      a1.x+=b1; a1.y+=b1; a1.z+=b1; a1.w+=b1;
      a2.x+=b2; a2.y+=b2; a2.z+=b2; a2.w+=b2;
      a3.x+=b3; a3.y+=b3; a3.z+=b3; a3.w+=b3;
    }
    if (RELUF) {
      a0.x=fmaxf(a0.x,0.f); a0.y=fmaxf(a0.y,0.f); a0.z=fmaxf(a0.z,0.f); a0.w=fmaxf(a0.w,0.f);
      a1.x=fmaxf(a1.x,0.f); a1.y=fmaxf(a1.y,0.f); a1.z=fmaxf(a1.z,0.f); a1.w=fmaxf(a1.w,0.f);
      a2.x=fmaxf(a2.x,0.f); a2.y=fmaxf(a2.y,0.f); a2.z=fmaxf(a2.z,0.f); a2.w=fmaxf(a2.w,0.f);
      a3.x=fmaxf(a3.x,0.f); a3.y=fmaxf(a3.y,0.f); a3.z=fmaxf(a3.z,0.f); a3.w=fmaxf(a3.w,0.f);
    }
    float* op = O + (size_t)(c * NROW + rg) * 32 + eg;
    *(float4*)(op)      = a0;
    *(float4*)(op + 32) = a1;
    *(float4*)(op + 64) = a2;
    *(float4*)(op + 96) = a3;
  }
}

// -------------------- tf32 mma helpers -------------------------------------
__device__ __forceinline__ uint32_t f2tf(float x){
  uint32_t r; asm("cvt.rna.tf32.f32 %0, %1;" : "=r"(r) : "f"(x)); return r;
}
__device__ __forceinline__ void mma8(float* c, uint32_t a0,uint32_t a1,uint32_t a2,uint32_t a3,
                                     uint32_t b0,uint32_t b1){
  asm volatile("mma.sync.aligned.m16n8k8.row.col.f32.tf32.tf32.f32 "
    "{%0,%1,%2,%3}, {%4,%5,%6,%7}, {%8,%9}, {%0,%1,%2,%3};"
    : "+f"(c[0]),"+f"(c[1]),"+f"(c[2]),"+f"(c[3])
    : "r"(a0),"r"(a1),"r"(a2),"r"(a3),"r"(b0),"r"(b1));
}

// tf32 MMA GEMM, N=100: C^T[32][100] = As[32][KPAD] * W[KREAL][100]
// W global row stride WSRC. One __syncthreads per chunk.
template<int KPAD,int KREAL,int CH,int ASTR,int OSTR,int WSRC,bool INITF,bool RELUF>
__device__ __forceinline__ void gemm_mma(
    const float* __restrict__ As, const float* __restrict__ Wg,
    const float* __restrict__ initv, const float* __restrict__ bias,
    float* __restrict__ OT, float* __restrict__ wbuf, const int tid)
{
  constexpr int WS  = 104;
  constexpr int NCH = KPAD / CH;
  static_assert(KPAD % CH == 0 && CH % 8 == 0, "pad");
  const int lane = tid & 31;
  const int warp = tid >> 5;
  const int g  = lane >> 2;
  const int tq = lane & 3;
  const int mt = warp >> 2;
  const int q  = warp & 3;
  const int jn = (q == 0) ? 4 : 3;
  float acc[4][4];
  #pragma unroll
  for (int j=0;j<4;++j){acc[j][0]=0.f;acc[j][1]=0.f;acc[j][2]=0.f;acc[j][3]=0.f;}

  auto stage = [&](int ch){
    float* db = wbuf + (ch & 1) * (CH * WS);
    const int base = ch * CH;
    for (int i = tid; i < CH*25; i += NT) {
      int r = i / 25, c4 = i - r*25;
      int kr = base + r;
      if (kr < KREAL) __pipeline_memcpy_async(db + r*WS + c4*4, Wg + (size_t)kr*WSRC + c4*4, 16);
      else { float4 z = make_float4(0.f,0.f,0.f,0.f); *(float4*)(db + r*WS + c4*4) = z; }
    }
    __pipeline_commit();
  };
  stage(0);
  for (int ch = 0; ch < NCH; ++ch) {
    __pipeline_wait_prior(0);
    __syncthreads();
    if (ch + 1 < NCH) stage(ch + 1);
    const float* wb = wbuf + (ch & 1) * (CH * WS);
    const float* arow = As + (size_t)(mt*16 + g) * ASTR + ch*CH;
    #pragma unroll
    for (int k8 = 0; k8 < CH/8; ++k8) {
      const float* ar = arow + k8*8;
      uint32_t a0 = f2tf(ar[tq]);
      uint32_t a1 = f2tf(ar[8*ASTR + tq]);
      uint32_t a2 = f2tf(ar[tq + 4]);
      uint32_t a3 = f2tf(ar[8*ASTR + tq + 4]);
      const float* wrow = wb + (k8*8 + tq)*WS + g;
      #pragma unroll
      for (int j = 0; j < 4; ++j) {
        if (j < jn) {
          const float* wr = wrow + (q + 4*j)*8;
          uint32_t b0 = f2tf(wr[0]);
          uint32_t b1 = f2tf(wr[4*WS]);
          mma8(acc[j], a0,a1,a2,a3, b0,b1);
        }
      }
    }
  }
  const int e0 = mt*16 + g;
  #pragma unroll
  for (int j = 0; j < 4; ++j) {
    if (j < jn) {
      int mb = (q + 4*j)*8 + 2*tq;
      #pragma unroll
      for (int hf = 0; hf < 2; ++hf) {
        int m = mb + hf;
        if (m < 100) {
          float add = (INITF ? initv[m] : 0.f) + bias[m];
          float v0 = acc[j][hf]   + add;
          float v1 = acc[j][2+hf] + add;
          if (RELUF) { v0 = fmaxf(v0, 0.f); v1 = fmaxf(v1, 0.f); }
          OT[(size_t)e0 * OSTR + m]     = v0;
          OT[(size_t)(e0+8) * OSTR + m] = v1;
        }
      }
    }
  }
}

// tf32 MMA GEMM, wide N: C^T[32][N] = As[32][KPAD] * W[KREAL][N] (W stride N)
template<int KPAD,int KREAL,int CH,int ASTR,int OSTR,int N,bool RELUF>
__device__ __forceinline__ void gemm_mmaW(
    const float* __restrict__ As, const float* __restrict__ Wg,
    const float* __restrict__ bias,
    float* __restrict__ OT, float* __restrict__ wbuf, const int tid)
{
  constexpr int WS  = N + 8;
  constexpr int NCH = KPAD / CH;
  constexpr int T   = N / 8;
  constexpr int JMAX = (T + 3) / 4;
  static_assert(KPAD % CH == 0 && CH % 8 == 0 && N % 8 == 0, "pad");
  const int lane = tid & 31;
  const int warp = tid >> 5;
  const int g  = lane >> 2;
  const int tq = lane & 3;
  const int mt = warp >> 2;
  const int q  = warp & 3;
  float acc[JMAX][4];
  #pragma unroll
  for (int j=0;j<JMAX;++j){acc[j][0]=0.f;acc[j][1]=0.f;acc[j][2]=0.f;acc[j][3]=0.f;}

  auto stage = [&](int ch){
    float* db = wbuf + (ch & 1) * (CH * WS);
    const int base = ch * CH;
    constexpr int Q4 = N / 4;
    for (int i = tid; i < CH*Q4; i += NT) {
      int r = i / Q4, c4 = i - r*Q4;
      int kr = base + r;
      if (kr < KREAL) __pipeline_memcpy_async(db + r*WS + c4*4, Wg + (size_t)kr*N + c4*4, 16);
      else { float4 z = make_float4(0.f,0.f,0.f,0.f); *(float4*)(db + r*WS + c4*4) = z; }
    }
    __pipeline_commit();
  };
  stage(0);
  for (int ch = 0; ch < NCH; ++ch) {
    __pipeline_wait_prior(0);
    __syncthreads();
    if (ch + 1 < NCH) stage(ch + 1);
    const float* wb = wbuf + (ch & 1) * (CH * WS);
    const float* arow = As + (size_t)(mt*16 + g) * ASTR + ch*CH;
    #pragma unroll
    for (int k8 = 0; k8 < CH/8; ++k8) {
      const float* ar = arow + k8*8;
      uint32_t a0 = f2tf(ar[tq]);
      uint32_t a1 = f2tf(ar[8*ASTR + tq]);
      uint32_t a2 = f2tf(ar[tq + 4]);
      uint32_t a3 = f2tf(ar[8*ASTR + tq + 4]);
      const float* wrow = wb + (k8*8 + tq)*WS + g;
      #pragma unroll
      for (int j = 0; j < JMAX; ++j) {
        int tile = q + 4*j;
        if (tile < T) {
          const float* wr = wrow + tile*8;
          uint32_t b0 = f2tf(wr[0]);
          uint32_t b1 = f2tf(wr[4*WS]);
          mma8(acc[j], a0,a1,a2,a3, b0,b1);
        }
      }
    }
  }
  const int e0 = mt*16 + g;
  #pragma unroll
  for (int j = 0; j < JMAX; ++j) {
    int tile = q + 4*j;
    if (tile < T) {
      int mb = tile*8 + 2*tq;
      #pragma unroll
      for (int hf = 0; hf < 2; ++hf) {
        int m = mb + hf;
        float b = bias[m];
        float v0 = acc[j][hf]   + b;
        float v1 = acc[j][2+hf] + b;
        if (RELUF) { v0 = fmaxf(v0, 0.f); v1 = fmaxf(v1, 0.f); }
        OT[(size_t)e0 * OSTR + m]     = v0;
        OT[(size_t)(e0+8) * OSTR + m] = v1;
      }
    }
  }
}

// ------------------------------ K0: hoisted per-node partials --------------
__global__ __launch_bounds__(NT)
void k_pre(const float* __restrict__ hV,
           const float* __restrict__ ws1, const float* __restrict__ wh1)
{
  __shared__ float W[10000];
  __shared__ float WH[528];
  __shared__ float HSv[148];
  const int tid = threadIdx.x;
  for (int i = tid; i < 10000; i += NT) W[i]  = ws1[i];
  for (int i = tid; i < 528;   i += NT) WH[i] = wh1[i];
  __syncthreads();
  for (int node = blockIdx.x; node < NODES; node += gridDim.x) {
    for (int t = tid; t < 148; t += NT) HSv[t] = hV[node * 148 + t];
    __syncthreads();
    for (int t = tid; t < 208; t += NT) {
      if (t < 100) {
        float acc = 0.f;
        #pragma unroll 4
        for (int j = 0; j < 100; ++j) acc += HSv[48 + j] * W[j * 100 + t];
        g_sb[node * 100 + t] = acc;
      } else {
        int u = t - 100, c = u / 36, h = u - c * 36;
        float acc = 0.f;
        if (h < 33) {
          #pragma unroll
          for (int i = 0; i < 16; ++i) acc += HSv[c * 16 + i] * WH[i * 33 + h];
        }
        g_vb[node * 108 + u] = acc;
      }
    }
    __syncthreads();
  }
}

// ------------------------------ K1: edges + mean + LN1 ---------------------
#define O_WH1P 0
#define O_WV1  1188
#define O_BS1  1716
#define O_WH2  1816
#define O_WV2  2072
#define O_BS2  2328
#define O_WH3  2428
#define O_WV3  2684
#define O_BS3  2940
#define O_LG1  3040
#define O_LB1  3140
#define O_HS   3240
#define O_MK   3388
#define O_SB   3420
#define O_VB   3520
#define O_VC1  3628
#define O_SC1T 5260   /* [32][172] */
#define O_VHX  10764  /* [108][32]; EBV staging alias */
#define O_BFAT 14220  /* [32][124] */
#define O_VOA  18188  /* [48][32] */
#define O_DH   19724
#define O_MISC 19872
#define O_WBUF 19880  /* 2*24*104 = 4992 */
#define SM1_FLOATS 24872

__global__ __launch_bounds__(NT, 2)
void k_edge(const float* __restrict__ hV, const float* __restrict__ hM,
            const int* __restrict__ maskA,
            const float* __restrict__ wh1, const float* __restrict__ ws1,
            const float* __restrict__ bs1, const float* __restrict__ wv1,
            const float* __restrict__ wh2, const float* __restrict__ ws2,
            const float* __restrict__ bs2, const float* __restrict__ wv2,
            const float* __restrict__ wh3, const float* __restrict__ ws3,
            const float* __restrict__ bs3, const float* __restrict__ wv3,
            const float* __restrict__ ln1g, const float* __restrict__ ln1b)
{
  extern __shared__ float sm[];
  float* WH1P = sm + O_WH1P;
  float* WV1  = sm + O_WV1;
  float* BS1s = sm + O_BS1;
  float* WH2s = sm + O_WH2;
  float* WV2s = sm + O_WV2;
  float* BS2s = sm + O_BS2;
  float* WH3s = sm + O_WH3;
  float* WV3s = sm + O_WV3;
  float* BS3s = sm + O_BS3;
  float* LG1  = sm + O_LG1;
  float* LB1  = sm + O_LB1;
  float* HS   = sm + O_HS;
  float* MK   = sm + O_MK;
  float* SB   = sm + O_SB;
  float* VB   = sm + O_VB;
  float* VC1  = sm + O_VC1;
  float* SC1T = sm + O_SC1T;
  float* VHX  = sm + O_VHX;
  float* BFAT = sm + O_BFAT;
  float* BFBT = sm + O_SC1T;   // aliases SC1T region
  float* VOA  = sm + O_VOA;
  float* DH   = sm + O_DH;
  float* MISC = sm + O_MISC;
  float* WBUF = sm + O_WBUF;
  float* EBV  = sm + O_VHX;    // vector staging [30][51] = 1530 floats
  const int tid = threadIdx.x;

  for (int i = tid; i < 1188; i += NT) { int r = i / 36, c = i - r * 36; WH1P[i] = (c < 33) ? wh1[r * 33 + c] : 0.f; }
  for (int i = tid; i < 528;  i += NT) WV1[i]  = wv1[i];
  for (int i = tid; i < 100;  i += NT) { BS1s[i] = bs1[i]; BS2s[i] = bs2[i]; BS3s[i] = bs3[i]; LG1[i] = ln1g[i]; LB1[i] = ln1b[i]; }
  for (int i = tid; i < 256;  i += NT) { WH2s[i] = wh2[i]; WV2s[i] = wv2[i]; WH3s[i] = wh3[i]; WV3s[i] = wv3[i]; }
  for (int i = tid; i < 1632; i += NT) VC1[i]  = 0.f;
  for (int i = tid; i < 5504; i += NT) SC1T[i] = 0.f;
  for (int i = tid; i < 3968; i += NT) BFAT[i] = 0.f;
  for (int i = tid; i < 4992; i += NT) WBUF[i] = 0.f;
  __syncthreads();

  for (int node = blockIdx.x; node < NODES; node += gridDim.x) {
    const float* mp = hM + (size_t)node * 5490;
    // scalars direct -> SC1T (coalesced 132-runs)
    for (int idx = tid; idx < 30 * 132; idx += NT) {
      int e = idx / 132, j = idx - e * 132;
      SC1T[e * 172 + j] = mp[e * 183 + 51 + j];
    }
    // vectors staged
    for (int idx = tid; idx < 30 * 51; idx += NT) {
      int e = idx / 51, j = idx - e * 51;
      EBV[e * 51 + j] = mp[e * 183 + j];
    }
    for (int t = tid; t < 148; t += NT) HS[t] = hV[node * 148 + t];
    for (int t = tid; t < 100; t += NT) SB[t] = g_sb[node * 100 + t];
    for (int t = tid; t < 108; t += NT) VB[t] = g_vb[node * 108 + t];
    for (int t = tid; t < 32;  t += NT) MK[t] = (t < 30) ? (float)maskA[node * 30 + t] : 0.f;
    __syncthreads();
    for (int idx = tid; idx < 51 * 32; idx += NT) {
      int j = idx >> 5, e = idx & 31;
      if (e < 30) VC1[j * 32 + e] = EBV[e * 51 + j];
    }
    __syncthreads();
    // GVP1
    gemm_rt<17,36,3,17,36,true,false,false>(VC1, WH1P + 16 * 36, VB, nullptr, VHX, tid);
    __syncthreads();
    for (int t = tid; t < 33 * 32; t += NT) {
      int h = t >> 5, e = t & 31;
      float a = VHX[h*32+e], b = VHX[(36+h)*32+e], c2 = VHX[(72+h)*32+e];
      SC1T[e * 172 + 132 + h] = sqrtf(fmaxf(a*a + b*b + c2*c2, 1e-8f));
    }
    gemm_rt<33,16,3,36,16,false,false,false>(VHX, WV1, nullptr, nullptr, VOA, tid);
    gemm_mma<168,165,24,172,124,100,true,true>(SC1T, ws1 + 10000, SB, BS1s, BFAT, WBUF, tid);
    for (int t = tid; t < 16 * 32; t += NT) {
      int o = t >> 5, e = t & 31;
      float a = VOA[o*32+e], b = VOA[(16+o)*32+e], c2 = VOA[(32+o)*32+e];
      float n = sqrtf(fmaxf(a*a + b*b + c2*c2, 1e-8f));
      float gt = 1.f / (1.f + expf(-n));
      VOA[o*32+e] = a*gt; VOA[(16+o)*32+e] = b*gt; VOA[(32+o)*32+e] = c2*gt;
    }
    __syncthreads();
    // GVP2
    gemm_rt<16,16,3,16,16,false,false,false>(VOA, WH2s, nullptr, nullptr, VHX, tid);
    __syncthreads();
    for (int t = tid; t < 16 * 32; t += NT) {
      int h = t >> 5, e = t & 31;
      float a = VHX[h*32+e], b = VHX[(16+h)*32+e], c2 = VHX[(32+h)*32+e];
      BFAT[e * 124 + 100 + h] = sqrtf(fmaxf(a*a + b*b + c2*c2, 1e-8f));
    }
    gemm_rt<16,16,3,16,16,false,false,false>(VHX, WV2s, nullptr, nullptr, VOA, tid);
    gemm_mma<120,116,24,124,124,100,false,true>(BFAT, ws2, nullptr, BS2s, BFBT, WBUF, tid);
    for (int t = tid; t < 16 * 32; t += NT) {
      int o = t >> 5, e = t & 31;
      float a = VOA[o*32+e], b = VOA[(16+o)*32+e], c2 = VOA[(32+o)*32+e];
      float n = sqrtf(fmaxf(a*a + b*b + c2*c2, 1e-8f));
      float gt = 1.f / (1.f + expf(-n));
      VOA[o*32+e] = a*gt; VOA[(16+o)*32+e] = b*gt; VOA[(32+o)*32+e] = c2*gt;
    }
    __syncthreads();
    // GVP3
    gemm_rt<16,16,3,16,16,false,false,false>(VOA, WH3s, nullptr, nullptr, VHX, tid);
    __syncthreads();
    for (int t = tid; t < 16 * 32; t += NT) {
      int h = t >> 5, e = t & 31;
      float a = VHX[h*32+e], b = VHX[(16+h)*32+e], c2 = VHX[(32+h)*32+e];
      BFBT[e * 124 + 100 + h] = sqrtf(fmaxf(a*a + b*b + c2*c2, 1e-8f));
    }
    gemm_rt<16,16,3,16,16,false,false,false>(VHX, WV3s, nullptr, nullptr, VOA, tid);
    gemm_mma<120,116,24,124,124,100,false,false>(BFBT, ws3, nullptr, BS3s, BFAT, WBUF, tid);
    __syncthreads();
    // masked mean + residual
    for (int t = tid; t < 148; t += NT) {
      float acc = 0.f;
      if (t < 48) {
        #pragma unroll
        for (int ee = 0; ee < 32; ++ee) {
          int e = (ee + t) & 31;
          acc += MK[e] * VOA[t * 32 + e];
        }
      } else {
        int r = t - 48;
        #pragma unroll 8
        for (int e = 0; e < 30; ++e) acc += MK[e] * BFAT[e * 124 + r];
      }
      DH[t] = HS[t] + acc * (1.f / 30.f);
    }
    __syncthreads();
    if (tid < 32) {
      float vm = 0.f;
      if (tid < 16) { float a = DH[tid], b = DH[16+tid], c2 = DH[32+tid]; vm = fmaxf(a*a + b*b + c2*c2, 1e-8f); }
      #pragma unroll
      for (int o = 16; o; o >>= 1) vm += __shfl_xor_sync(0xffffffffu, vm, o);
      float s0 = DH[48+tid], s1 = DH[80+tid], s2v = DH[112+tid];
      float s3v = (tid < 4) ? DH[144+tid] : 0.f;
      float p = s0 + s1 + s2v + s3v;
      #pragma unroll
      for (int o = 16; o; o >>= 1) p += __shfl_xor_sync(0xffffffffu, p, o);
      float mu = p * 0.01f;
      float d0 = s0-mu, d1 = s1-mu, d2 = s2v-mu;
      float q = d0*d0 + d1*d1 + d2*d2;
      if (tid < 4) { float d3 = s3v - mu; q += d3*d3; }
      #pragma unroll
      for (int o = 16; o; o >>= 1) q += __shfl_xor_sync(0xffffffffu, q, o);
      if (tid == 0) { MISC[0] = rsqrtf(vm * (1.f/16.f)); MISC[1] = mu; MISC[2] = rsqrtf(q * 0.01f + 1e-3f); }
    }
    __syncthreads();
    for (int t = tid; t < 148; t += NT) {
      float v;
      if (t < 48) v = DH[t] * MISC[0];
      else { int j = t - 48; v = (DH[t] - MISC[1]) * MISC[2] * LG1[j] + LB1[j]; }
      g_hv[node * 148 + t] = v;
    }
    __syncthreads();
  }
}

// ------------------------------ K2: dh1 (tf32 MMA, 32-node tiles) ----------
__global__ __launch_bounds__(NT)
void k_dh1(const float* __restrict__ wh, const float* __restrict__ ws,
           const float* __restrict__ bs, const float* __restrict__ wv)
{
  extern __shared__ float sm[];
  float* VC1  = sm;             // 48*32  = 1536
  float* SC1T = VC1 + 1536;     // 32*148 = 4736
  float* VH   = SC1T + 4736;    // 96*32  = 3072
  float* VO   = VH + 3072;      // 96*32  = 3072
  float* SOT  = VO + 3072;      // 32*408 = 13056
  float* WHs  = SOT + 13056;    // 512
  float* WVs  = WHs + 512;      // 1024
  float* BSs  = WVs + 1024;     // 400
  float* WBUF = BSs + 400;      // 2*24*408 = 19584
  const int tid = threadIdx.x;
  const int n0 = blockIdx.x * 32;

  for (int i = tid; i < 512;  i += NT) WHs[i] = wh[i];
  for (int i = tid; i < 1024; i += NT) WVs[i] = wv[i];
  for (int i = tid; i < 400;  i += NT) BSs[i] = bs[i];
  for (int idx = tid; idx < 48 * 32; idx += NT) {
    int r = idx >> 5, e = idx & 31;
    VC1[r * 32 + e] = g_hv[(size_t)(n0 + e) * 148 + r];
  }
  for (int idx = tid; idx < 32 * 148; idx += NT) {
    int e = idx / 148, j = idx - e * 148;
    SC1T[idx] = (j < 100) ? g_hv[(size_t)(n0 + e) * 148 + 48 + j] : 0.f;
  }
  __syncthreads();
  gemm_rt<16,32,3,16,32,false,false,false>(VC1, WHs, nullptr, nullptr, VH, tid);
  __syncthreads();
  for (int t = tid; t < 32 * 32; t += NT) {
    int h = t >> 5, e = t & 31;
    float a = VH[h*32+e], b = VH[(32+h)*32+e], c2 = VH[(64+h)*32+e];
    SC1T[e * 148 + 100 + h] = sqrtf(fmaxf(a*a + b*b + c2*c2, 1e-8f));
  }
  gemm_rt<32,32,3,32,32,false,false,false>(VH, WVs, nullptr, nullptr, VO, tid);
  gemm_mmaW<144,132,24,148,408,400,true>(SC1T, ws, BSs, SOT, WBUF, tid);
  __syncthreads();
  for (int t = tid; t < 32 * 32; t += NT) {
    int o = t >> 5, e = t & 31;
    float a = VO[o*32+e], b = VO[(32+o)*32+e], c2 = VO[(64+o)*32+e];
    float n = sqrtf(fmaxf(a*a + b*b + c2*c2, 1e-8f));
    float gt = 1.f / (1.f + expf(-n));
    VO[o*32+e] = a*gt; VO[(32+o)*32+e] = b*gt; VO[(64+o)*32+e] = c2*gt;
  }
  __syncthreads();
  // g_t per node: [0..95] vectors, [96..495] scalars
  for (int idx = tid; idx < 32 * 496; idx += NT) {
    int e = idx / 496, r = idx - e * 496;
    float v = (r < 96) ? VO[r * 32 + e] : SOT[e * 408 + (r - 96)];
    g_t[(size_t)(n0 + e) * 496 + r] = v;
  }
}

// ------------------------------ K3: dh2 (tf32 MMA) + LN2 + mask ------------
__global__ __launch_bounds__(NT)
void k_dh2(const float* __restrict__ wh, const float* __restrict__ ws,
           const float* __restrict__ bs, const float* __restrict__ wv,
           const float* __restrict__ ln2g, const float* __restrict__ ln2b,
           const int* __restrict__ maskV, float* __restrict__ out)
{
  extern __shared__ float sm[];
  float* VC   = sm;             // 96*32  = 3072
  float* SCT  = VC + 3072;      // 32*436 = 13952
  float* VH   = SCT + 13952;    // 96*32  = 3072
  float* VO   = VH + 3072;      // 48*32  = 1536
  float* OT   = VO + 1536;      // 32*104 = 3328
  float* HVT  = OT + 3328;      // 148*33 = 4884
  float* ST   = HVT + 4884;     // 128
  float* WHs  = ST + 128;       // 1024
  float* WVs  = WHs + 1024;     // 512
  float* BSs  = WVs + 512;      // 100
  float* WBUF = BSs + 100;      // 2*72*104 = 14976
  const int tid = threadIdx.x;
  const int n0 = blockIdx.x * 32;

  for (int i = tid; i < 1024; i += NT) WHs[i] = wh[i];
  for (int i = tid; i < 512;  i += NT) WVs[i] = wv[i];
  for (int i = tid; i < 100;  i += NT) BSs[i] = bs[i];
  for (int idx = tid; idx < 96 * 32; idx += NT) {
    int r = idx >> 5, e = idx & 31;
    VC[r * 32 + e] = g_t[(size_t)(n0 + e) * 496 + r];
  }
  for (int idx = tid; idx < 32 * 400; idx += NT) {
    int e = idx / 400, m = idx - e * 400;
    SCT[e * 436 + m] = g_t[(size_t)(n0 + e) * 496 + 96 + m];
  }
  for (int idx = tid; idx < 148 * 32; idx += NT) {
    int r = idx >> 5, e = idx & 31;
    HVT[r * 33 + e] = g_hv[(size_t)(n0 + e) * 148 + r];
  }
  if (tid < 32) ST[96 + tid] = (float)maskV[n0 + tid];
  __syncthreads();
  gemm_rt<32,32,3,32,32,false,false,false>(VC, WHs, nullptr, nullptr, VH, tid);
  __syncthreads();
  for (int t = tid; t < 32 * 32; t += NT) {
    int h = t >> 5, e = t & 31;
    float a = VH[h*32+e], b = VH[(32+h)*32+e], c2 = VH[(64+h)*32+e];
    SCT[e * 436 + 400 + h] = sqrtf(fmaxf(a*a + b*b + c2*c2, 1e-8f));
  }
  gemm_rt<32,16,3,32,16,false,false,false>(VH, WVs, nullptr, nullptr, VO, tid);
  gemm_mma<432,432,72,436,104,100,false,false>(SCT, ws, nullptr, BSs, OT, WBUF, tid);
  __syncthreads();
  for (int idx = tid; idx < 148 * 32; idx += NT) {
    int r = idx >> 5, e = idx & 31;
    float add = (r < 48) ? VO[r * 32 + e] : OT[e * 104 + (r - 48)];
    HVT[r * 33 + e] += add;
  }
  __syncthreads();
  if (tid < 32) {
    const int e = tid;
    float vm = 0.f;
    #pragma unroll
    for (int i = 0; i < 16; ++i) {
      float a = HVT[i*33+e], b = HVT[(16+i)*33+e], c2 = HVT[(32+i)*33+e];
      vm += fmaxf(a*a + b*b + c2*c2, 1e-8f);
    }
    float mu = 0.f;
    #pragma unroll 4
    for (int j = 0; j < 100; ++j) mu += HVT[(48+j)*33+e];
    mu *= 0.01f;
    float var = 0.f;
    #pragma unroll 4
    for (int j = 0; j < 100; ++j) { float d = HVT[(48+j)*33+e] - mu; var += d*d; }
    var *= 0.01f;
    ST[e] = rsqrtf(vm * (1.f/16.f));
    ST[32+e] = mu;
    ST[64+e] = rsqrtf(var + 1e-3f);
  }
  __syncthreads();
  for (int idx = tid; idx < 32 * 148; idx += NT) {
    int e = idx / 148, r = idx - e * 148;
    float v = HVT[r * 33 + e];
    if (r < 48) v = v * ST[e];
    else { int j = r - 48; v = (v - ST[32+e]) * ST[64+e] * ln2g[j] + ln2b[j]; }
    out[(size_t)(n0 + e) * 148 + r] = ST[96 + e] * v;
  }
}

// ---------------------------------------------------------------------------
extern "C" void kernel_launch(void* const* d_in, const int* in_sizes, int n_in,
                              void* d_out, int out_size)
{
  const float* hV      = (const float*)d_in[0];
  const float* hM      = (const float*)d_in[1];
  const int*   maskV   = (const int*)  d_in[2];
  const int*   maskA   = (const int*)  d_in[3];
  const float* wev1_wh = (const float*)d_in[4];
  const float* wev1_ws = (const float*)d_in[5];
  const float* wev1_bs = (const float*)d_in[6];
  const float* wev1_wv = (const float*)d_in[7];
  const float* wev2_wh = (const float*)d_in[8];
  const float* wev2_ws = (const float*)d_in[9];
  const float* wev2_bs = (const float*)d_in[10];
  const float* wev2_wv = (const float*)d_in[11];
  const float* wev3_wh = (const float*)d_in[12];
  const float* wev3_ws = (const float*)d_in[13];
  const float* wev3_bs = (const float*)d_in[14];
  const float* wev3_wv = (const float*)d_in[15];
  const float* wdh1_wh = (const float*)d_in[16];
  const float* wdh1_ws = (const float*)d_in[17];
  const float* wdh1_bs = (const float*)d_in[18];
  const float* wdh1_wv = (const float*)d_in[19];
  const float* wdh2_wh = (const float*)d_in[20];
  const float* wdh2_ws = (const float*)d_in[21];
  const float* wdh2_bs = (const float*)d_in[22];
  const float* wdh2_wv = (const float*)d_in[23];
  const float* ln1g = (const float*)d_in[24];
  const float* ln1b = (const float*)d_in[25];
  const float* ln2g = (const float*)d_in[26];
  const float* ln2b = (const float*)d_in[27];
  float* out = (float*)d_out;

  int dev = 0; cudaGetDevice(&dev);
  int sms = 148;
  cudaDeviceGetAttribute(&sms, cudaDevAttrMultiProcessorCount, dev);

  const size_t SM1 = (size_t)SM1_FLOATS * sizeof(float);   // ~97.2 KB
  const size_t SM2 = (size_t)(1536+4736+3072+3072+13056+512+1024+400+19584) * sizeof(float); // ~187 KB
  const size_t SM3 = (size_t)(3072+13952+3072+1536+3328+4884+128+1024+512+100+14976) * sizeof(float); // ~186 KB

  cudaFuncSetAttribute(k_edge, cudaFuncAttributeMaxDynamicSharedMemorySize, (int)SM1);
  cudaFuncSetAttribute(k_dh1,  cudaFuncAttributeMaxDynamicSharedMemorySize, (int)SM2);
  cudaFuncSetAttribute(k_dh2,  cudaFuncAttributeMaxDynamicSharedMemorySize, (int)SM3);

  k_pre <<<sms, NT>>>(hV, wev1_ws, wev1_wh);
  k_edge<<<2 * sms, NT, SM1>>>(hV, hM, maskA,
                               wev1_wh, wev1_ws, wev1_bs, wev1_wv,
                               wev2_wh, wev2_ws, wev2_bs, wev2_wv,
                               wev3_wh, wev3_ws, wev3_bs, wev3_wv,
                               ln1g, ln1b);
  k_dh1<<<NODES / 32, NT, SM2>>>(wdh1_wh, wdh1_ws, wdh1_bs, wdh1_wv);
  k_dh2<<<NODES / 32, NT, SM3>>>(wdh2_wh, wdh2_ws, wdh2_bs, wdh2_wv,
                                 ln2g, ln2b, maskV, out);
}

// round 9
// speedup vs baseline: 9.9060x; 1.0351x over previous
#include <cuda_runtime.h>
#include <cuda_pipeline.h>
#include <math.h>
#include <stdint.h>

#define NT 256
constexpr int NODES = 4 * 2048;

__device__ float g_hv[NODES * 148];
__device__ float g_sb[NODES * 100];
__device__ float g_vb[NODES * 108];

// ---------------- register-tiled GEMM, weights in SMEM ----------------------
// A [NC*ARS rows][COLS], O [NC*NROW rows][COLS]
template<int NTT,int COLS,int KD,int NROW,int NC,int ARS,int WSTR,bool INITF,bool BIASF,bool RELUF>
__device__ __forceinline__ void gemm_rt(
    const float* __restrict__ A, const float* __restrict__ W,
    const float* __restrict__ initv, const float* __restrict__ bias,
    float* __restrict__ O, const int tid)
{
  constexpr int GPC = NROW / 4;
  constexpr int G   = NC * GPC;
  constexpr int TPG = COLS / 4;
  const int eg = (tid & (TPG - 1)) * 4;
  for (int g = tid / TPG; g < G; g += NTT / TPG) {
    const int c  = g / GPC;
    const int rg = (g - c * GPC) * 4;
    float4 a0, a1, a2, a3;
    if (INITF) {
      const float* iv = initv + c * NROW + rg;
      a0 = make_float4(iv[0], iv[0], iv[0], iv[0]);
      a1 = make_float4(iv[1], iv[1], iv[1], iv[1]);
      a2 = make_float4(iv[2], iv[2], iv[2], iv[2]);
      a3 = make_float4(iv[3], iv[3], iv[3], iv[3]);
    } else {
      a0 = make_float4(0.f,0.f,0.f,0.f); a1 = a0; a2 = a0; a3 = a0;
    }
    const float* ap = A + (size_t)(c * ARS) * COLS + eg;
    const float* wp = W + rg;
    #pragma unroll 4
    for (int k = 0; k < KD; ++k) {
      const float4 av = *(const float4*)(ap + (size_t)k * COLS);
      const float4 wv4 = *(const float4*)(wp + (size_t)k * WSTR);
      a0.x += wv4.x*av.x; a0.y += wv4.x*av.y; a0.z += wv4.x*av.z; a0.w += wv4.x*av.w;
      a1.x += wv4.y*av.x; a1.y += wv4.y*av.y; a1.z += wv4.y*av.z; a1.w += wv4.y*av.w;
      a2.x += wv4.z*av.x; a2.y += wv4.z*av.y; a2.z += wv4.z*av.z; a2.w += wv4.z*av.w;
      a3.x += wv4.w*av.x; a3.y += wv4.w*av.y; a3.z += wv4.w*av.z; a3.w += wv4.w*av.w;
    }
    if (BIASF) {
      const float* bp = bias + c * NROW + rg;
      float b0=bp[0], b1=bp[1], b2=bp[2], b3=bp[3];
      a0.x+=b0; a0.y+=b0; a0.z+=b0; a0.w+=b0;
      a1.x+=b1; a1.y+=b1; a1.z+=b1; a1.w+=b1;
      a2.x+=b2; a2.y+=b2; a2.z+=b2; a2.w+=b2;
      a3.x+=b3; a3.y+=b3; a3.z+=b3; a3.w+=b3;
    }
    if (RELUF) {
      a0.x=fmaxf(a0.x,0.f); a0.y=fmaxf(a0.y,0.f); a0.z=fmaxf(a0.z,0.f); a0.w=fmaxf(a0.w,0.f);
      a1.x=fmaxf(a1.x,0.f); a1.y=fmaxf(a1.y,0.f); a1.z=fmaxf(a1.z,0.f); a1.w=fmaxf(a1.w,0.f);
      a2.x=fmaxf(a2.x,0.f); a2.y=fmaxf(a2.y,0.f); a2.z=fmaxf(a2.z,0.f); a2.w=fmaxf(a2.w,0.f);
      a3.x=fmaxf(a3.x,0.f); a3.y=fmaxf(a3.y,0.f); a3.z=fmaxf(a3.z,0.f); a3.w=fmaxf(a3.w,0.f);
    }
    float* op = O + (size_t)(c * NROW + rg) * COLS + eg;
    *(float4*)(op)          = a0;
    *(float4*)(op + COLS)   = a1;
    *(float4*)(op + 2*COLS) = a2;
    *(float4*)(op + 3*COLS) = a3;
  }
}

// -------------------- tf32 mma helpers -------------------------------------
__device__ __forceinline__ uint32_t f2tf(float x){
  uint32_t r; asm("cvt.rna.tf32.f32 %0, %1;" : "=r"(r) : "f"(x)); return r;
}
__device__ __forceinline__ void mma8(float* c, uint32_t a0,uint32_t a1,uint32_t a2,uint32_t a3,
                                     uint32_t b0,uint32_t b1){
  asm volatile("mma.sync.aligned.m16n8k8.row.col.f32.tf32.tf32.f32 "
    "{%0,%1,%2,%3}, {%4,%5,%6,%7}, {%8,%9}, {%0,%1,%2,%3};"
    : "+f"(c[0]),"+f"(c[1]),"+f"(c[2]),"+f"(c[3])
    : "r"(a0),"r"(a1),"r"(a2),"r"(a3),"r"(b0),"r"(b1));
}

// tf32 MMA GEMM, N=100: C^T[M][100] = As[M][KPAD] * W[KREAL][100]
// NQ warps per m-tile; M = 16 * (warps/NQ). One __syncthreads per chunk.
template<int NTT,int NQ,int KPAD,int KREAL,int CH,int ASTR,int OSTR,int WSRC,bool INITF,bool RELUF>
__device__ __forceinline__ void gemm_mma(
    const float* __restrict__ As, const float* __restrict__ Wg,
    const float* __restrict__ initv, const float* __restrict__ bias,
    float* __restrict__ OT, float* __restrict__ wbuf, const int tid)
{
  constexpr int WS  = 104;
  constexpr int NCH = KPAD / CH;
  constexpr int T   = 13;
  constexpr int JMAX = (T + NQ - 1) / NQ;
  static_assert(KPAD % CH == 0 && CH % 8 == 0, "pad");
  const int lane = tid & 31;
  const int warp = tid >> 5;
  const int g  = lane >> 2;
  const int tq = lane & 3;
  const int mt = warp / NQ;
  const int q  = warp % NQ;
  float acc[JMAX][4];
  #pragma unroll
  for (int j=0;j<JMAX;++j){acc[j][0]=0.f;acc[j][1]=0.f;acc[j][2]=0.f;acc[j][3]=0.f;}

  auto stage = [&](int ch){
    float* db = wbuf + (ch & 1) * (CH * WS);
    const int base = ch * CH;
    for (int i = tid; i < CH*25; i += NTT) {
      int r = i / 25, c4 = i - r*25;
      int kr = base + r;
      if (kr < KREAL) __pipeline_memcpy_async(db + r*WS + c4*4, Wg + (size_t)kr*WSRC + c4*4, 16);
      else { float4 z = make_float4(0.f,0.f,0.f,0.f); *(float4*)(db + r*WS + c4*4) = z; }
    }
    __pipeline_commit();
  };
  stage(0);
  for (int ch = 0; ch < NCH; ++ch) {
    __pipeline_wait_prior(0);
    __syncthreads();
    if (ch + 1 < NCH) stage(ch + 1);
    const float* wb = wbuf + (ch & 1) * (CH * WS);
    const float* arow = As + (size_t)(mt*16 + g) * ASTR + ch*CH;
    #pragma unroll
    for (int k8 = 0; k8 < CH/8; ++k8) {
      const float* ar = arow + k8*8;
      uint32_t a0 = f2tf(ar[tq]);
      uint32_t a1 = f2tf(ar[8*ASTR + tq]);
      uint32_t a2 = f2tf(ar[tq + 4]);
      uint32_t a3 = f2tf(ar[8*ASTR + tq + 4]);
      const float* wrow = wb + (k8*8 + tq)*WS + g;
      #pragma unroll
      for (int j = 0; j < JMAX; ++j) {
        int tile = q + NQ*j;
        if (tile < T) {
          const float* wr = wrow + tile*8;
          uint32_t b0 = f2tf(wr[0]);
          uint32_t b1 = f2tf(wr[4*WS]);
          mma8(acc[j], a0,a1,a2,a3, b0,b1);
        }
      }
    }
  }
  const int e0 = mt*16 + g;
  #pragma unroll
  for (int j = 0; j < JMAX; ++j) {
    int tile = q + NQ*j;
    if (tile < T) {
      int mb = tile*8 + 2*tq;
      #pragma unroll
      for (int hf = 0; hf < 2; ++hf) {
        int m = mb + hf;
        if (m < 100) {
          float add = (INITF ? initv[m] : 0.f) + bias[m];
          float v0 = acc[j][hf]   + add;
          float v1 = acc[j][2+hf] + add;
          if (RELUF) { v0 = fmaxf(v0, 0.f); v1 = fmaxf(v1, 0.f); }
          OT[(size_t)e0 * OSTR + m]     = v0;
          OT[(size_t)(e0+8) * OSTR + m] = v1;
        }
      }
    }
  }
}

// tf32 MMA GEMM, wide N: C^T[M][N] = As[M][KPAD] * W[KREAL][N]
template<int NTT,int NQ,int KPAD,int KREAL,int CH,int ASTR,int OSTR,int N,bool RELUF>
__device__ __forceinline__ void gemm_mmaW(
    const float* __restrict__ As, const float* __restrict__ Wg,
    const float* __restrict__ bias,
    float* __restrict__ OT, float* __restrict__ wbuf, const int tid)
{
  constexpr int WS  = N + 8;
  constexpr int NCH = KPAD / CH;
  constexpr int T   = N / 8;
  constexpr int JMAX = (T + NQ - 1) / NQ;
  static_assert(KPAD % CH == 0 && CH % 8 == 0 && N % 8 == 0, "pad");
  const int lane = tid & 31;
  const int warp = tid >> 5;
  const int g  = lane >> 2;
  const int tq = lane & 3;
  const int mt = warp / NQ;
  const int q  = warp % NQ;
  float acc[JMAX][4];
  #pragma unroll
  for (int j=0;j<JMAX;++j){acc[j][0]=0.f;acc[j][1]=0.f;acc[j][2]=0.f;acc[j][3]=0.f;}

  auto stage = [&](int ch){
    float* db = wbuf + (ch & 1) * (CH * WS);
    const int base = ch * CH;
    constexpr int Q4 = N / 4;
    for (int i = tid; i < CH*Q4; i += NTT) {
      int r = i / Q4, c4 = i - r*Q4;
      int kr = base + r;
      if (kr < KREAL) __pipeline_memcpy_async(db + r*WS + c4*4, Wg + (size_t)kr*N + c4*4, 16);
      else { float4 z = make_float4(0.f,0.f,0.f,0.f); *(float4*)(db + r*WS + c4*4) = z; }
    }
    __pipeline_commit();
  };
  stage(0);
  for (int ch = 0; ch < NCH; ++ch) {
    __pipeline_wait_prior(0);
    __syncthreads();
    if (ch + 1 < NCH) stage(ch + 1);
    const float* wb = wbuf + (ch & 1) * (CH * WS);
    const float* arow = As + (size_t)(mt*16 + g) * ASTR + ch*CH;
    #pragma unroll
    for (int k8 = 0; k8 < CH/8; ++k8) {
      const float* ar = arow + k8*8;
      uint32_t a0 = f2tf(ar[tq]);
      uint32_t a1 = f2tf(ar[8*ASTR + tq]);
      uint32_t a2 = f2tf(ar[tq + 4]);
      uint32_t a3 = f2tf(ar[8*ASTR + tq + 4]);
      const float* wrow = wb + (k8*8 + tq)*WS + g;
      #pragma unroll
      for (int j = 0; j < JMAX; ++j) {
        int tile = q + NQ*j;
        if (tile < T) {
          const float* wr = wrow + tile*8;
          uint32_t b0 = f2tf(wr[0]);
          uint32_t b1 = f2tf(wr[4*WS]);
          mma8(acc[j], a0,a1,a2,a3, b0,b1);
        }
      }
    }
  }
  const int e0 = mt*16 + g;
  #pragma unroll
  for (int j = 0; j < JMAX; ++j) {
    int tile = q + NQ*j;
    if (tile < T) {
      int mb = tile*8 + 2*tq;
      #pragma unroll
      for (int hf = 0; hf < 2; ++hf) {
        int m = mb + hf;
        float b = bias[m];
        float v0 = acc[j][hf]   + b;
        float v1 = acc[j][2+hf] + b;
        if (RELUF) { v0 = fmaxf(v0, 0.f); v1 = fmaxf(v1, 0.f); }
        OT[(size_t)e0 * OSTR + m]     = v0;
        OT[(size_t)(e0+8) * OSTR + m] = v1;
      }
    }
  }
}

// ------------------------------ K0: hoisted per-node partials --------------
__global__ __launch_bounds__(NT)
void k_pre(const float* __restrict__ hV,
           const float* __restrict__ ws1, const float* __restrict__ wh1)
{
  __shared__ float W[10000];
  __shared__ float WH[528];
  __shared__ float HSv[148];
  const int tid = threadIdx.x;
  for (int i = tid; i < 10000; i += NT) W[i]  = ws1[i];
  for (int i = tid; i < 528;   i += NT) WH[i] = wh1[i];
  __syncthreads();
  for (int node = blockIdx.x; node < NODES; node += gridDim.x) {
    for (int t = tid; t < 148; t += NT) HSv[t] = hV[node * 148 + t];
    __syncthreads();
    for (int t = tid; t < 208; t += NT) {
      if (t < 100) {
        float acc = 0.f;
        #pragma unroll 4
        for (int j = 0; j < 100; ++j) acc += HSv[48 + j] * W[j * 100 + t];
        g_sb[node * 100 + t] = acc;
      } else {
        int u = t - 100, c = u / 36, h = u - c * 36;
        float acc = 0.f;
        if (h < 33) {
          #pragma unroll
          for (int i = 0; i < 16; ++i) acc += HSv[c * 16 + i] * WH[i * 33 + h];
        }
        g_vb[node * 108 + u] = acc;
      }
    }
    __syncthreads();
  }
}

// ------------------------------ K1: edges + mean + LN1 ---------------------
#define O_WH1P 0
#define O_WV1  1188
#define O_BS1  1716
#define O_WH2  1816
#define O_WV2  2072
#define O_BS2  2328
#define O_WH3  2428
#define O_WV3  2684
#define O_BS3  2940
#define O_LG1  3040
#define O_LB1  3140
#define O_HS   3240
#define O_MK   3388
#define O_SB   3420
#define O_VB   3520
#define O_VC1  3628
#define O_SC1T 5260   /* [32][172] */
#define O_VHX  10764  /* [108][32]; EBV staging alias */
#define O_BFAT 14220  /* [32][124] */
#define O_VOA  18188  /* [48][32] */
#define O_DH   19724
#define O_MISC 19872
#define O_WBUF 19880  /* 2*24*104 = 4992 */
#define SM1_FLOATS 24872

__global__ __launch_bounds__(NT, 2)
void k_edge(const float* __restrict__ hV, const float* __restrict__ hM,
            const int* __restrict__ maskA,
            const float* __restrict__ wh1, const float* __restrict__ ws1,
            const float* __restrict__ bs1, const float* __restrict__ wv1,
            const float* __restrict__ wh2, const float* __restrict__ ws2,
            const float* __restrict__ bs2, const float* __restrict__ wv2,
            const float* __restrict__ wh3, const float* __restrict__ ws3,
            const float* __restrict__ bs3, const float* __restrict__ wv3,
            const float* __restrict__ ln1g, const float* __restrict__ ln1b)
{
  extern __shared__ float sm[];
  float* WH1P = sm + O_WH1P;
  float* WV1  = sm + O_WV1;
  float* BS1s = sm + O_BS1;
  float* WH2s = sm + O_WH2;
  float* WV2s = sm + O_WV2;
  float* BS2s = sm + O_BS2;
  float* WH3s = sm + O_WH3;
  float* WV3s = sm + O_WV3;
  float* BS3s = sm + O_BS3;
  float* LG1  = sm + O_LG1;
  float* LB1  = sm + O_LB1;
  float* HS   = sm + O_HS;
  float* MK   = sm + O_MK;
  float* SB   = sm + O_SB;
  float* VB   = sm + O_VB;
  float* VC1  = sm + O_VC1;
  float* SC1T = sm + O_SC1T;
  float* VHX  = sm + O_VHX;
  float* BFAT = sm + O_BFAT;
  float* BFBT = sm + O_SC1T;
  float* VOA  = sm + O_VOA;
  float* DH   = sm + O_DH;
  float* MISC = sm + O_MISC;
  float* WBUF = sm + O_WBUF;
  float* EBV  = sm + O_VHX;
  const int tid = threadIdx.x;

  for (int i = tid; i < 1188; i += NT) { int r = i / 36, c = i - r * 36; WH1P[i] = (c < 33) ? wh1[r * 33 + c] : 0.f; }
  for (int i = tid; i < 528;  i += NT) WV1[i]  = wv1[i];
  for (int i = tid; i < 100;  i += NT) { BS1s[i] = bs1[i]; BS2s[i] = bs2[i]; BS3s[i] = bs3[i]; LG1[i] = ln1g[i]; LB1[i] = ln1b[i]; }
  for (int i = tid; i < 256;  i += NT) { WH2s[i] = wh2[i]; WV2s[i] = wv2[i]; WH3s[i] = wh3[i]; WV3s[i] = wv3[i]; }
  for (int i = tid; i < 1632; i += NT) VC1[i]  = 0.f;
  for (int i = tid; i < 5504; i += NT) SC1T[i] = 0.f;
  for (int i = tid; i < 3968; i += NT) BFAT[i] = 0.f;
  for (int i = tid; i < 4992; i += NT) WBUF[i] = 0.f;
  __syncthreads();

  for (int node = blockIdx.x; node < NODES; node += gridDim.x) {
    const float* mp = hM + (size_t)node * 5490;
    for (int idx = tid; idx < 30 * 132; idx += NT) {
      int e = idx / 132, j = idx - e * 132;
      SC1T[e * 172 + j] = mp[e * 183 + 51 + j];
    }
    for (int idx = tid; idx < 30 * 51; idx += NT) {
      int e = idx / 51, j = idx - e * 51;
      EBV[e * 51 + j] = mp[e * 183 + j];
    }
    for (int t = tid; t < 148; t += NT) HS[t] = hV[node * 148 + t];
    for (int t = tid; t < 100; t += NT) SB[t] = g_sb[node * 100 + t];
    for (int t = tid; t < 108; t += NT) VB[t] = g_vb[node * 108 + t];
    for (int t = tid; t < 32;  t += NT) MK[t] = (t < 30) ? (float)maskA[node * 30 + t] : 0.f;
    __syncthreads();
    for (int idx = tid; idx < 51 * 32; idx += NT) {
      int j = idx >> 5, e = idx & 31;
      if (e < 30) VC1[j * 32 + e] = EBV[e * 51 + j];
    }
    __syncthreads();
    gemm_rt<NT,32,17,36,3,17,36,true,false,false>(VC1, WH1P + 16 * 36, VB, nullptr, VHX, tid);
    __syncthreads();
    for (int t = tid; t < 33 * 32; t += NT) {
      int h = t >> 5, e = t & 31;
      float a = VHX[h*32+e], b = VHX[(36+h)*32+e], c2 = VHX[(72+h)*32+e];
      SC1T[e * 172 + 132 + h] = sqrtf(fmaxf(a*a + b*b + c2*c2, 1e-8f));
    }
    gemm_rt<NT,32,33,16,3,36,16,false,false,false>(VHX, WV1, nullptr, nullptr, VOA, tid);
    gemm_mma<NT,4,168,165,24,172,124,100,true,true>(SC1T, ws1 + 10000, SB, BS1s, BFAT, WBUF, tid);
    for (int t = tid; t < 16 * 32; t += NT) {
      int o = t >> 5, e = t & 31;
      float a = VOA[o*32+e], b = VOA[(16+o)*32+e], c2 = VOA[(32+o)*32+e];
      float n = sqrtf(fmaxf(a*a + b*b + c2*c2, 1e-8f));
      float gt = 1.f / (1.f + expf(-n));
      VOA[o*32+e] = a*gt; VOA[(16+o)*32+e] = b*gt; VOA[(32+o)*32+e] = c2*gt;
    }
    __syncthreads();
    gemm_rt<NT,32,16,16,3,16,16,false,false,false>(VOA, WH2s, nullptr, nullptr, VHX, tid);
    __syncthreads();
    for (int t = tid; t < 16 * 32; t += NT) {
      int h = t >> 5, e = t & 31;
      float a = VHX[h*32+e], b = VHX[(16+h)*32+e], c2 = VHX[(32+h)*32+e];
      BFAT[e * 124 + 100 + h] = sqrtf(fmaxf(a*a + b*b + c2*c2, 1e-8f));
    }
    gemm_rt<NT,32,16,16,3,16,16,false,false,false>(VHX, WV2s, nullptr, nullptr, VOA, tid);
    gemm_mma<NT,4,120,116,24,124,124,100,false,true>(BFAT, ws2, nullptr, BS2s, BFBT, WBUF, tid);
    for (int t = tid; t < 16 * 32; t += NT) {
      int o = t >> 5, e = t & 31;
      float a = VOA[o*32+e], b = VOA[(16+o)*32+e], c2 = VOA[(32+o)*32+e];
      float n = sqrtf(fmaxf(a*a + b*b + c2*c2, 1e-8f));
      float gt = 1.f / (1.f + expf(-n));
      VOA[o*32+e] = a*gt; VOA[(16+o)*32+e] = b*gt; VOA[(32+o)*32+e] = c2*gt;
    }
    __syncthreads();
    gemm_rt<NT,32,16,16,3,16,16,false,false,false>(VOA, WH3s, nullptr, nullptr, VHX, tid);
    __syncthreads();
    for (int t = tid; t < 16 * 32; t += NT) {
      int h = t >> 5, e = t & 31;
      float a = VHX[h*32+e], b = VHX[(16+h)*32+e], c2 = VHX[(32+h)*32+e];
      BFBT[e * 124 + 100 + h] = sqrtf(fmaxf(a*a + b*b + c2*c2, 1e-8f));
    }
    gemm_rt<NT,32,16,16,3,16,16,false,false,false>(VHX, WV3s, nullptr, nullptr, VOA, tid);
    gemm_mma<NT,4,120,116,24,124,124,100,false,false>(BFBT, ws3, nullptr, BS3s, BFAT, WBUF, tid);
    __syncthreads();
    for (int t = tid; t < 148; t += NT) {
      float acc = 0.f;
      if (t < 48) {
        #pragma unroll
        for (int ee = 0; ee < 32; ++ee) {
          int e = (ee + t) & 31;
          acc += MK[e] * VOA[t * 32 + e];
        }
      } else {
        int r = t - 48;
        #pragma unroll 8
        for (int e = 0; e < 30; ++e) acc += MK[e] * BFAT[e * 124 + r];
      }
      DH[t] = HS[t] + acc * (1.f / 30.f);
    }
    __syncthreads();
    if (tid < 32) {
      float vm = 0.f;
      if (tid < 16) { float a = DH[tid], b = DH[16+tid], c2 = DH[32+tid]; vm = fmaxf(a*a + b*b + c2*c2, 1e-8f); }
      #pragma unroll
      for (int o = 16; o; o >>= 1) vm += __shfl_xor_sync(0xffffffffu, vm, o);
      float s0 = DH[48+tid], s1 = DH[80+tid], s2v = DH[112+tid];
      float s3v = (tid < 4) ? DH[144+tid] : 0.f;
      float p = s0 + s1 + s2v + s3v;
      #pragma unroll
      for (int o = 16; o; o >>= 1) p += __shfl_xor_sync(0xffffffffu, p, o);
      float mu = p * 0.01f;
      float d0 = s0-mu, d1 = s1-mu, d2 = s2v-mu;
      float q = d0*d0 + d1*d1 + d2*d2;
      if (tid < 4) { float d3 = s3v - mu; q += d3*d3; }
      #pragma unroll
      for (int o = 16; o; o >>= 1) q += __shfl_xor_sync(0xffffffffu, q, o);
      if (tid == 0) { MISC[0] = rsqrtf(vm * (1.f/16.f)); MISC[1] = mu; MISC[2] = rsqrtf(q * 0.01f + 1e-3f); }
    }
    __syncthreads();
    for (int t = tid; t < 148; t += NT) {
      float v;
      if (t < 48) v = DH[t] * MISC[0];
      else { int j = t - 48; v = (DH[t] - MISC[1]) * MISC[2] * LG1[j] + LB1[j]; }
      g_hv[node * 148 + t] = v;
    }
    __syncthreads();
  }
}

// -------------------- K2: fused dh1+dh2+LN2 (16-node tiles, 512 thr) -------
#define DHT 512
__global__ __launch_bounds__(DHT, 2)
void k_dh(const float* __restrict__ wh1, const float* __restrict__ ws1g,
          const float* __restrict__ bs1, const float* __restrict__ wv1,
          const float* __restrict__ wh2, const float* __restrict__ ws2g,
          const float* __restrict__ bs2, const float* __restrict__ wv2,
          const float* __restrict__ ln2g, const float* __restrict__ ln2b,
          const int* __restrict__ maskV, float* __restrict__ out)
{
  extern __shared__ float sm[];
  float* WHs1 = sm;             // 512
  float* WVs1 = WHs1 + 512;     // 1024
  float* BSs1 = WVs1 + 1024;    // 400
  float* WHs2 = BSs1 + 400;     // 1024
  float* WVs2 = WHs2 + 1024;    // 512
  float* BSs2 = WVs2 + 512;     // 100
  float* VC1  = BSs2 + 100;     // 48*16  = 768
  float* SC1T = VC1 + 768;      // 16*148 = 2368
  float* VH   = SC1T + 2368;    // 96*16  = 1536
  float* VOd1 = VH + 1536;      // 96*16  = 1536
  float* SCT  = VOd1 + 1536;    // 16*436 = 6976
  float* VO2  = SCT + 6976;     // 48*16  = 768
  float* OT   = VO2 + 768;      // 16*104 = 1664
  float* ST   = OT + 1664;      // 80
  float* WBUF = ST + 80;        // 6528 = max(dh1: 2*8*408, dh2: 2*24*104)
  float* RES  = WBUF;           // [148][17] = 2516 alias after MMAs done
  const int tid = threadIdx.x;
  const int n0 = blockIdx.x * 16;

  for (int i = tid; i < 512;  i += DHT) WHs1[i] = wh1[i];
  for (int i = tid; i < 1024; i += DHT) WVs1[i] = wv1[i];
  for (int i = tid; i < 400;  i += DHT) BSs1[i] = bs1[i];
  for (int i = tid; i < 1024; i += DHT) WHs2[i] = wh2[i];
  for (int i = tid; i < 512;  i += DHT) WVs2[i] = wv2[i];
  for (int i = tid; i < 100;  i += DHT) BSs2[i] = bs2[i];
  if (tid < 16) ST[48 + tid] = (float)maskV[n0 + tid];
  for (int idx = tid; idx < 48 * 16; idx += DHT) {
    int r = idx >> 4, e = idx & 15;
    VC1[r * 16 + e] = g_hv[(size_t)(n0 + e) * 148 + r];
  }
  for (int idx = tid; idx < 16 * 148; idx += DHT) {
    int e = idx / 148, j = idx - e * 148;
    SC1T[idx] = (j < 100) ? g_hv[(size_t)(n0 + e) * 148 + 48 + j] : 0.f;
  }
  __syncthreads();
  // dh1 vh
  gemm_rt<DHT,16,16,32,3,16,32,false,false,false>(VC1, WHs1, nullptr, nullptr, VH, tid);
  __syncthreads();
  // vn1 -> SC1T cols 100..131
  {
    int h = tid >> 4, e = tid & 15;   // 512 threads == 32*16 exactly
    float a = VH[h*16+e], b = VH[(32+h)*16+e], c2 = VH[(64+h)*16+e];
    SC1T[e * 148 + 100 + h] = sqrtf(fmaxf(a*a + b*b + c2*c2, 1e-8f));
  }
  gemm_rt<DHT,16,32,32,3,32,32,false,false,false>(VH, WVs1, nullptr, nullptr, VOd1, tid);
  gemm_mmaW<DHT,16,144,132,8,148,436,400,true>(SC1T, ws1g, BSs1, SCT, WBUF, tid);
  __syncthreads();
  // gate dh1
  {
    int o = tid >> 4, e = tid & 15;
    float a = VOd1[o*16+e], b = VOd1[(32+o)*16+e], c2 = VOd1[(64+o)*16+e];
    float n = sqrtf(fmaxf(a*a + b*b + c2*c2, 1e-8f));
    float gt = 1.f / (1.f + expf(-n));
    VOd1[o*16+e] = a*gt; VOd1[(32+o)*16+e] = b*gt; VOd1[(64+o)*16+e] = c2*gt;
  }
  __syncthreads();
  // dh2 vh
  gemm_rt<DHT,16,32,32,3,32,32,false,false,false>(VOd1, WHs2, nullptr, nullptr, VH, tid);
  __syncthreads();
  // vn2 -> SCT cols 400..431
  {
    int h = tid >> 4, e = tid & 15;
    float a = VH[h*16+e], b = VH[(32+h)*16+e], c2 = VH[(64+h)*16+e];
    SCT[e * 436 + 400 + h] = sqrtf(fmaxf(a*a + b*b + c2*c2, 1e-8f));
  }
  gemm_rt<DHT,16,32,16,3,32,16,false,false,false>(VH, WVs2, nullptr, nullptr, VO2, tid);
  gemm_mma<DHT,16,432,432,24,436,104,100,false,false>(SCT, ws2g, nullptr, BSs2, OT, WBUF, tid);
  __syncthreads();
  // residual into RES (aliases WBUF — MMA fully done)
  for (int idx = tid; idx < 148 * 16; idx += DHT) {
    int r = idx >> 4, e = idx & 15;
    float add = (r < 48) ? VO2[r * 16 + e] : OT[e * 104 + (r - 48)];
    RES[r * 17 + e] = g_hv[(size_t)(n0 + e) * 148 + r] + add;
  }
  __syncthreads();
  if (tid < 16) {
    const int e = tid;
    float vm = 0.f;
    #pragma unroll
    for (int i = 0; i < 16; ++i) {
      float a = RES[i*17+e], b = RES[(16+i)*17+e], c2 = RES[(32+i)*17+e];
      vm += fmaxf(a*a + b*b + c2*c2, 1e-8f);
    }
    float mu = 0.f;
    #pragma unroll 4
    for (int j = 0; j < 100; ++j) mu += RES[(48+j)*17+e];
    mu *= 0.01f;
    float var = 0.f;
    #pragma unroll 4
    for (int j = 0; j < 100; ++j) { float d = RES[(48+j)*17+e] - mu; var += d*d; }
    var *= 0.01f;
    ST[e]    = rsqrtf(vm * (1.f/16.f));
    ST[16+e] = mu;
    ST[32+e] = rsqrtf(var + 1e-3f);
  }
  __syncthreads();
  for (int idx = tid; idx < 16 * 148; idx += DHT) {
    int e = idx / 148, r = idx - e * 148;
    float v = RES[r * 17 + e];
    if (r < 48) v = v * ST[e];
    else { int j = r - 48; v = (v - ST[16+e]) * ST[32+e] * ln2g[j] + ln2b[j]; }
    out[(size_t)(n0 + e) * 148 + r] = ST[48 + e] * v;
  }
}

// ---------------------------------------------------------------------------
extern "C" void kernel_launch(void* const* d_in, const int* in_sizes, int n_in,
                              void* d_out, int out_size)
{
  const float* hV      = (const float*)d_in[0];
  const float* hM      = (const float*)d_in[1];
  const int*   maskV   = (const int*)  d_in[2];
  const int*   maskA   = (const int*)  d_in[3];
  const float* wev1_wh = (const float*)d_in[4];
  const float* wev1_ws = (const float*)d_in[5];
  const float* wev1_bs = (const float*)d_in[6];
  const float* wev1_wv = (const float*)d_in[7];
  const float* wev2_wh = (const float*)d_in[8];
  const float* wev2_ws = (const float*)d_in[9];
  const float* wev2_bs = (const float*)d_in[10];
  const float* wev2_wv = (const float*)d_in[11];
  const float* wev3_wh = (const float*)d_in[12];
  const float* wev3_ws = (const float*)d_in[13];
  const float* wev3_bs = (const float*)d_in[14];
  const float* wev3_wv = (const float*)d_in[15];
  const float* wdh1_wh = (const float*)d_in[16];
  const float* wdh1_ws = (const float*)d_in[17];
  const float* wdh1_bs = (const float*)d_in[18];
  const float* wdh1_wv = (const float*)d_in[19];
  const float* wdh2_wh = (const float*)d_in[20];
  const float* wdh2_ws = (const float*)d_in[21];
  const float* wdh2_bs = (const float*)d_in[22];
  const float* wdh2_wv = (const float*)d_in[23];
  const float* ln1g = (const float*)d_in[24];
  const float* ln1b = (const float*)d_in[25];
  const float* ln2g = (const float*)d_in[26];
  const float* ln2b = (const float*)d_in[27];
  float* out = (float*)d_out;

  int dev = 0; cudaGetDevice(&dev);
  int sms = 148;
  cudaDeviceGetAttribute(&sms, cudaDevAttrMultiProcessorCount, dev);

  const size_t SM1 = (size_t)SM1_FLOATS * sizeof(float);   // ~97.2 KB
  const size_t SMDH = (size_t)(512+1024+400+1024+512+100+768+2368+1536+1536+6976+768+1664+80+6528) * sizeof(float); // ~100.8 KB

  cudaFuncSetAttribute(k_edge, cudaFuncAttributeMaxDynamicSharedMemorySize, (int)SM1);
  cudaFuncSetAttribute(k_dh,   cudaFuncAttributeMaxDynamicSharedMemorySize, (int)SMDH);

  k_pre <<<sms, NT>>>(hV, wev1_ws, wev1_wh);
  k_edge<<<2 * sms, NT, SM1>>>(hV, hM, maskA,
                               wev1_wh, wev1_ws, wev1_bs, wev1_wv,
                               wev2_wh, wev2_ws, wev2_bs, wev2_wv,
                               wev3_wh, wev3_ws, wev3_bs, wev3_wv,
                               ln1g, ln1b);
  k_dh<<<NODES / 16, DHT, SMDH>>>(wdh1_wh, wdh1_ws, wdh1_bs, wdh1_wv,
                                  wdh2_wh, wdh2_ws, wdh2_bs, wdh2_wv,
                                  ln2g, ln2b, maskV, out);
}

// round 10
// speedup vs baseline: 10.6550x; 1.0756x over previous
#include <cuda_runtime.h>
#include <cuda_pipeline.h>
#include <math.h>
#include <stdint.h>

#define NT 256
constexpr int NODES = 4 * 2048;

__device__ float g_hv[NODES * 148];
__device__ float g_sb[NODES * 100];
__device__ float g_vb[NODES * 108];

// ---------------- register-tiled GEMM, weights in SMEM ----------------------
template<int NTT,int COLS,int KD,int NROW,int NC,int ARS,int WSTR,bool INITF,bool BIASF,bool RELUF>
__device__ __forceinline__ void gemm_rt(
    const float* __restrict__ A, const float* __restrict__ W,
    const float* __restrict__ initv, const float* __restrict__ bias,
    float* __restrict__ O, const int tid)
{
  constexpr int GPC = NROW / 4;
  constexpr int G   = NC * GPC;
  constexpr int TPG = COLS / 4;
  const int eg = (tid & (TPG - 1)) * 4;
  for (int g = tid / TPG; g < G; g += NTT / TPG) {
    const int c  = g / GPC;
    const int rg = (g - c * GPC) * 4;
    float4 a0, a1, a2, a3;
    if (INITF) {
      const float* iv = initv + c * NROW + rg;
      a0 = make_float4(iv[0], iv[0], iv[0], iv[0]);
      a1 = make_float4(iv[1], iv[1], iv[1], iv[1]);
      a2 = make_float4(iv[2], iv[2], iv[2], iv[2]);
      a3 = make_float4(iv[3], iv[3], iv[3], iv[3]);
    } else {
      a0 = make_float4(0.f,0.f,0.f,0.f); a1 = a0; a2 = a0; a3 = a0;
    }
    const float* ap = A + (size_t)(c * ARS) * COLS + eg;
    const float* wp = W + rg;
    #pragma unroll 4
    for (int k = 0; k < KD; ++k) {
      const float4 av = *(const float4*)(ap + (size_t)k * COLS);
      const float4 wv4 = *(const float4*)(wp + (size_t)k * WSTR);
      a0.x += wv4.x*av.x; a0.y += wv4.x*av.y; a0.z += wv4.x*av.z; a0.w += wv4.x*av.w;
      a1.x += wv4.y*av.x; a1.y += wv4.y*av.y; a1.z += wv4.y*av.z; a1.w += wv4.y*av.w;
      a2.x += wv4.z*av.x; a2.y += wv4.z*av.y; a2.z += wv4.z*av.z; a2.w += wv4.z*av.w;
      a3.x += wv4.w*av.x; a3.y += wv4.w*av.y; a3.z += wv4.w*av.z; a3.w += wv4.w*av.w;
    }
    if (BIASF) {
      const float* bp = bias + c * NROW + rg;
      float b0=bp[0], b1=bp[1], b2=bp[2], b3=bp[3];
      a0.x+=b0; a0.y+=b0; a0.z+=b0; a0.w+=b0;
      a1.x+=b1; a1.y+=b1; a1.z+=b1; a1.w+=b1;
      a2.x+=b2; a2.y+=b2; a2.z+=b2; a2.w+=b2;
      a3.x+=b3; a3.y+=b3; a3.z+=b3; a3.w+=b3;
    }
    if (RELUF) {
      a0.x=fmaxf(a0.x,0.f); a0.y=fmaxf(a0.y,0.f); a0.z=fmaxf(a0.z,0.f); a0.w=fmaxf(a0.w,0.f);
      a1.x=fmaxf(a1.x,0.f); a1.y=fmaxf(a1.y,0.f); a1.z=fmaxf(a1.z,0.f); a1.w=fmaxf(a1.w,0.f);
      a2.x=fmaxf(a2.x,0.f); a2.y=fmaxf(a2.y,0.f); a2.z=fmaxf(a2.z,0.f); a2.w=fmaxf(a2.w,0.f);
      a3.x=fmaxf(a3.x,0.f); a3.y=fmaxf(a3.y,0.f); a3.z=fmaxf(a3.z,0.f); a3.w=fmaxf(a3.w,0.f);
    }
    float* op = O + (size_t)(c * NROW + rg) * COLS + eg;
    *(float4*)(op)          = a0;
    *(float4*)(op + COLS)   = a1;
    *(float4*)(op + 2*COLS) = a2;
    *(float4*)(op + 3*COLS) = a3;
  }
}

// -------------------- tf32 mma helpers -------------------------------------
__device__ __forceinline__ uint32_t f2tf(float x){
  uint32_t r; asm("cvt.rna.tf32.f32 %0, %1;" : "=r"(r) : "f"(x)); return r;
}
__device__ __forceinline__ void mma8(float* c, uint32_t a0,uint32_t a1,uint32_t a2,uint32_t a3,
                                     uint32_t b0,uint32_t b1){
  asm volatile("mma.sync.aligned.m16n8k8.row.col.f32.tf32.tf32.f32 "
    "{%0,%1,%2,%3}, {%4,%5,%6,%7}, {%8,%9}, {%0,%1,%2,%3};"
    : "+f"(c[0]),"+f"(c[1]),"+f"(c[2]),"+f"(c[3])
    : "r"(a0),"r"(a1),"r"(a2),"r"(a3),"r"(b0),"r"(b1));
}

// tf32 MMA GEMM, N=100: C^T[M][100] = As[M][KPAD] * W[KREAL][100]
// NQ warps per m-tile; M = 16 * (warps/NQ). One __syncthreads per chunk.
// OT may be SMEM or GLOBAL (epilogue writes are plain stores).
template<int NTT,int NQ,int KPAD,int KREAL,int CH,int ASTR,int OSTR,int WSRC,bool INITF,bool RELUF>
__device__ __forceinline__ void gemm_mma(
    const float* __restrict__ As, const float* __restrict__ Wg,
    const float* __restrict__ initv, const float* __restrict__ bias,
    float* __restrict__ OT, float* __restrict__ wbuf, const int tid)
{
  constexpr int WS  = 104;
  constexpr int NCH = KPAD / CH;
  constexpr int T   = 13;
  constexpr int JMAX = (T + NQ - 1) / NQ;
  static_assert(KPAD % CH == 0 && CH % 8 == 0, "pad");
  const int lane = tid & 31;
  const int warp = tid >> 5;
  const int g  = lane >> 2;
  const int tq = lane & 3;
  const int mt = warp / NQ;
  const int q  = warp % NQ;
  float acc[JMAX][4];
  #pragma unroll
  for (int j=0;j<JMAX;++j){acc[j][0]=0.f;acc[j][1]=0.f;acc[j][2]=0.f;acc[j][3]=0.f;}

  auto stage = [&](int ch){
    float* db = wbuf + (ch & 1) * (CH * WS);
    const int base = ch * CH;
    for (int i = tid; i < CH*25; i += NTT) {
      int r = i / 25, c4 = i - r*25;
      int kr = base + r;
      if (kr < KREAL) __pipeline_memcpy_async(db + r*WS + c4*4, Wg + (size_t)kr*WSRC + c4*4, 16);
      else { float4 z = make_float4(0.f,0.f,0.f,0.f); *(float4*)(db + r*WS + c4*4) = z; }
    }
    __pipeline_commit();
  };
  stage(0);
  for (int ch = 0; ch < NCH; ++ch) {
    __pipeline_wait_prior(0);
    __syncthreads();
    if (ch + 1 < NCH) stage(ch + 1);
    const float* wb = wbuf + (ch & 1) * (CH * WS);
    const float* arow = As + (size_t)(mt*16 + g) * ASTR + ch*CH;
    #pragma unroll
    for (int k8 = 0; k8 < CH/8; ++k8) {
      const float* ar = arow + k8*8;
      uint32_t a0 = f2tf(ar[tq]);
      uint32_t a1 = f2tf(ar[8*ASTR + tq]);
      uint32_t a2 = f2tf(ar[tq + 4]);
      uint32_t a3 = f2tf(ar[8*ASTR + tq + 4]);
      const float* wrow = wb + (k8*8 + tq)*WS + g;
      #pragma unroll
      for (int j = 0; j < JMAX; ++j) {
        int tile = q + NQ*j;
        if (tile < T) {
          const float* wr = wrow + tile*8;
          uint32_t b0 = f2tf(wr[0]);
          uint32_t b1 = f2tf(wr[4*WS]);
          mma8(acc[j], a0,a1,a2,a3, b0,b1);
        }
      }
    }
  }
  const int e0 = mt*16 + g;
  #pragma unroll
  for (int j = 0; j < JMAX; ++j) {
    int tile = q + NQ*j;
    if (tile < T) {
      int mb = tile*8 + 2*tq;
      #pragma unroll
      for (int hf = 0; hf < 2; ++hf) {
        int m = mb + hf;
        if (m < 100) {
          float add = (INITF ? initv[m] : 0.f) + bias[m];
          float v0 = acc[j][hf]   + add;
          float v1 = acc[j][2+hf] + add;
          if (RELUF) { v0 = fmaxf(v0, 0.f); v1 = fmaxf(v1, 0.f); }
          OT[(size_t)e0 * OSTR + m]     = v0;
          OT[(size_t)(e0+8) * OSTR + m] = v1;
        }
      }
    }
  }
}

// tf32 MMA GEMM, wide N: C^T[M][N] = As[M][KPAD] * W[KREAL][N]
template<int NTT,int NQ,int KPAD,int KREAL,int CH,int ASTR,int OSTR,int N,bool RELUF>
__device__ __forceinline__ void gemm_mmaW(
    const float* __restrict__ As, const float* __restrict__ Wg,
    const float* __restrict__ bias,
    float* __restrict__ OT, float* __restrict__ wbuf, const int tid)
{
  constexpr int WS  = N + 8;
  constexpr int NCH = KPAD / CH;
  constexpr int T   = N / 8;
  constexpr int JMAX = (T + NQ - 1) / NQ;
  static_assert(KPAD % CH == 0 && CH % 8 == 0 && N % 8 == 0, "pad");
  const int lane = tid & 31;
  const int warp = tid >> 5;
  const int g  = lane >> 2;
  const int tq = lane & 3;
  const int mt = warp / NQ;
  const int q  = warp % NQ;
  float acc[JMAX][4];
  #pragma unroll
  for (int j=0;j<JMAX;++j){acc[j][0]=0.f;acc[j][1]=0.f;acc[j][2]=0.f;acc[j][3]=0.f;}

  auto stage = [&](int ch){
    float* db = wbuf + (ch & 1) * (CH * WS);
    const int base = ch * CH;
    constexpr int Q4 = N / 4;
    for (int i = tid; i < CH*Q4; i += NTT) {
      int r = i / Q4, c4 = i - r*Q4;
      int kr = base + r;
      if (kr < KREAL) __pipeline_memcpy_async(db + r*WS + c4*4, Wg + (size_t)kr*N + c4*4, 16);
      else { float4 z = make_float4(0.f,0.f,0.f,0.f); *(float4*)(db + r*WS + c4*4) = z; }
    }
    __pipeline_commit();
  };
  stage(0);
  for (int ch = 0; ch < NCH; ++ch) {
    __pipeline_wait_prior(0);
    __syncthreads();
    if (ch + 1 < NCH) stage(ch + 1);
    const float* wb = wbuf + (ch & 1) * (CH * WS);
    const float* arow = As + (size_t)(mt*16 + g) * ASTR + ch*CH;
    #pragma unroll
    for (int k8 = 0; k8 < CH/8; ++k8) {
      const float* ar = arow + k8*8;
      uint32_t a0 = f2tf(ar[tq]);
      uint32_t a1 = f2tf(ar[8*ASTR + tq]);
      uint32_t a2 = f2tf(ar[tq + 4]);
      uint32_t a3 = f2tf(ar[8*ASTR + tq + 4]);
      const float* wrow = wb + (k8*8 + tq)*WS + g;
      #pragma unroll
      for (int j = 0; j < JMAX; ++j) {
        int tile = q + NQ*j;
        if (tile < T) {
          const float* wr = wrow + tile*8;
          uint32_t b0 = f2tf(wr[0]);
          uint32_t b1 = f2tf(wr[4*WS]);
          mma8(acc[j], a0,a1,a2,a3, b0,b1);
        }
      }
    }
  }
  const int e0 = mt*16 + g;
  #pragma unroll
  for (int j = 0; j < JMAX; ++j) {
    int tile = q + NQ*j;
    if (tile < T) {
      int mb = tile*8 + 2*tq;
      #pragma unroll
      for (int hf = 0; hf < 2; ++hf) {
        int m = mb + hf;
        float b = bias[m];
        float v0 = acc[j][hf]   + b;
        float v1 = acc[j][2+hf] + b;
        if (RELUF) { v0 = fmaxf(v0, 0.f); v1 = fmaxf(v1, 0.f); }
        OT[(size_t)e0 * OSTR + m]     = v0;
        OT[(size_t)(e0+8) * OSTR + m] = v1;
      }
    }
  }
}

// ------------ K0: hoisted per-node partials (32-node MMA tiles) -------------
// g_sb[node] = hV_s[node] @ ws1[0:100]  (tf32 MMA, direct global epilogue)
// g_vb[node] = hV_v[node] @ wh1[0:16]   (scalar, K=16)
__global__ __launch_bounds__(NT)
void k_pre(const float* __restrict__ hV,
           const float* __restrict__ ws1, const float* __restrict__ wh1)
{
  extern __shared__ float sm[];
  float* As  = sm;            // [32][108]  node-major scalars (pad 100..107 = 0)
  float* WB  = As + 3456;     // [104][104] ws1 rows 0..99 staging (gemm_mma wbuf)
  float* WH  = WB + 10816;    // 528 = wh1 rows 0..15
  float* HVv = WH + 528;      // [32][48]  node-major vectors
  float* ZB  = HVv + 1536;    // 104 zero bias
  const int tid = threadIdx.x;
  const int n0 = blockIdx.x * 32;

  for (int i = tid; i < 528; i += NT) WH[i] = wh1[i];
  for (int i = tid; i < 104; i += NT) ZB[i] = 0.f;
  for (int idx = tid; idx < 32 * 8; idx += NT) {
    int e = idx >> 3, j = idx & 7;
    As[e * 108 + 100 + j] = 0.f;
  }
  for (int idx = tid; idx < 32 * 148; idx += NT) {
    int e = idx / 148, r = idx - e * 148;
    float v = hV[(size_t)(n0 + e) * 148 + r];
    if (r < 48) HVv[e * 48 + r] = v;
    else        As[e * 108 + (r - 48)] = v;
  }
  __syncthreads();
  // SB: [32][100] = As[32][100] @ ws1[0:100][100], epilogue direct to global
  gemm_mma<NT,4,104,100,104,108,100,100,false,false>(
      As, ws1, nullptr, ZB, g_sb + (size_t)n0 * 100, WB, tid);
  // VB (independent of MMA output; reads HVv/WH staged before the sync)
  for (int t = tid; t < 32 * 108; t += NT) {
    int e = t / 108, u = t - e * 108;
    int c = u / 36, h = u - c * 36;
    float acc = 0.f;
    if (h < 33) {
      #pragma unroll
      for (int i = 0; i < 16; ++i) acc += HVv[e * 48 + c * 16 + i] * WH[i * 33 + h];
    }
    g_vb[(size_t)(n0 + e) * 108 + u] = acc;
  }
}

// ------------------------------ K1: edges + mean + LN1 ---------------------
#define O_WH1P 0
#define O_WV1  1188
#define O_BS1  1716
#define O_WH2  1816
#define O_WV2  2072
#define O_BS2  2328
#define O_WH3  2428
#define O_WV3  2684
#define O_BS3  2940
#define O_LG1  3040
#define O_LB1  3140
#define O_HS   3240
#define O_MK   3388
#define O_SB   3420
#define O_VB   3520
#define O_VC1  3628
#define O_SC1T 5260   /* [32][172] */
#define O_VHX  10764  /* [108][32]; EBV staging alias */
#define O_BFAT 14220  /* [32][124] */
#define O_VOA  18188  /* [48][32] */
#define O_DH   19724
#define O_MISC 19872
#define O_WBUF 19880  /* 2*24*104 = 4992 */
#define SM1_FLOATS 24872

__global__ __launch_bounds__(NT, 2)
void k_edge(const float* __restrict__ hV, const float* __restrict__ hM,
            const int* __restrict__ maskA,
            const float* __restrict__ wh1, const float* __restrict__ ws1,
            const float* __restrict__ bs1, const float* __restrict__ wv1,
            const float* __restrict__ wh2, const float* __restrict__ ws2,
            const float* __restrict__ bs2, const float* __restrict__ wv2,
            const float* __restrict__ wh3, const float* __restrict__ ws3,
            const float* __restrict__ bs3, const float* __restrict__ wv3,
            const float* __restrict__ ln1g, const float* __restrict__ ln1b)
{
  extern __shared__ float sm[];
  float* WH1P = sm + O_WH1P;
  float* WV1  = sm + O_WV1;
  float* BS1s = sm + O_BS1;
  float* WH2s = sm + O_WH2;
  float* WV2s = sm + O_WV2;
  float* BS2s = sm + O_BS2;
  float* WH3s = sm + O_WH3;
  float* WV3s = sm + O_WV3;
  float* BS3s = sm + O_BS3;
  float* LG1  = sm + O_LG1;
  float* LB1  = sm + O_LB1;
  float* HS   = sm + O_HS;
  float* MK   = sm + O_MK;
  float* SB   = sm + O_SB;
  float* VB   = sm + O_VB;
  float* VC1  = sm + O_VC1;
  float* SC1T = sm + O_SC1T;
  float* VHX  = sm + O_VHX;
  float* BFAT = sm + O_BFAT;
  float* BFBT = sm + O_SC1T;
  float* VOA  = sm + O_VOA;
  float* DH   = sm + O_DH;
  float* MISC = sm + O_MISC;
  float* WBUF = sm + O_WBUF;
  float* EBV  = sm + O_VHX;
  const int tid = threadIdx.x;

  for (int i = tid; i < 1188; i += NT) { int r = i / 36, c = i - r * 36; WH1P[i] = (c < 33) ? wh1[r * 33 + c] : 0.f; }
  for (int i = tid; i < 528;  i += NT) WV1[i]  = wv1[i];
  for (int i = tid; i < 100;  i += NT) { BS1s[i] = bs1[i]; BS2s[i] = bs2[i]; BS3s[i] = bs3[i]; LG1[i] = ln1g[i]; LB1[i] = ln1b[i]; }
  for (int i = tid; i < 256;  i += NT) { WH2s[i] = wh2[i]; WV2s[i] = wv2[i]; WH3s[i] = wh3[i]; WV3s[i] = wv3[i]; }
  for (int i = tid; i < 1632; i += NT) VC1[i]  = 0.f;
  for (int i = tid; i < 5504; i += NT) SC1T[i] = 0.f;
  for (int i = tid; i < 3968; i += NT) BFAT[i] = 0.f;
  for (int i = tid; i < 4992; i += NT) WBUF[i] = 0.f;
  __syncthreads();

  for (int node = blockIdx.x; node < NODES; node += gridDim.x) {
    const float* mp = hM + (size_t)node * 5490;
    for (int idx = tid; idx < 30 * 132; idx += NT) {
      int e = idx / 132, j = idx - e * 132;
      SC1T[e * 172 + j] = mp[e * 183 + 51 + j];
    }
    for (int idx = tid; idx < 30 * 51; idx += NT) {
      int e = idx / 51, j = idx - e * 51;
      EBV[e * 51 + j] = mp[e * 183 + j];
    }
    for (int t = tid; t < 148; t += NT) HS[t] = hV[node * 148 + t];
    for (int t = tid; t < 100; t += NT) SB[t] = g_sb[node * 100 + t];
    for (int t = tid; t < 108; t += NT) VB[t] = g_vb[node * 108 + t];
    for (int t = tid; t < 32;  t += NT) MK[t] = (t < 30) ? (float)maskA[node * 30 + t] : 0.f;
    __syncthreads();
    for (int idx = tid; idx < 51 * 32; idx += NT) {
      int j = idx >> 5, e = idx & 31;
      if (e < 30) VC1[j * 32 + e] = EBV[e * 51 + j];
    }
    __syncthreads();
    gemm_rt<NT,32,17,36,3,17,36,true,false,false>(VC1, WH1P + 16 * 36, VB, nullptr, VHX, tid);
    __syncthreads();
    for (int t = tid; t < 33 * 32; t += NT) {
      int h = t >> 5, e = t & 31;
      float a = VHX[h*32+e], b = VHX[(36+h)*32+e], c2 = VHX[(72+h)*32+e];
      SC1T[e * 172 + 132 + h] = sqrtf(fmaxf(a*a + b*b + c2*c2, 1e-8f));
    }
    gemm_rt<NT,32,33,16,3,36,16,false,false,false>(VHX, WV1, nullptr, nullptr, VOA, tid);
    gemm_mma<NT,4,168,165,24,172,124,100,true,true>(SC1T, ws1 + 10000, SB, BS1s, BFAT, WBUF, tid);
    for (int t = tid; t < 16 * 32; t += NT) {
      int o = t >> 5, e = t & 31;
      float a = VOA[o*32+e], b = VOA[(16+o)*32+e], c2 = VOA[(32+o)*32+e];
      float n = sqrtf(fmaxf(a*a + b*b + c2*c2, 1e-8f));
      float gt = 1.f / (1.f + expf(-n));
      VOA[o*32+e] = a*gt; VOA[(16+o)*32+e] = b*gt; VOA[(32+o)*32+e] = c2*gt;
    }
    __syncthreads();
    gemm_rt<NT,32,16,16,3,16,16,false,false,false>(VOA, WH2s, nullptr, nullptr, VHX, tid);
    __syncthreads();
    for (int t = tid; t < 16 * 32; t += NT) {
      int h = t >> 5, e = t & 31;
      float a = VHX[h*32+e], b = VHX[(16+h)*32+e], c2 = VHX[(32+h)*32+e];
      BFAT[e * 124 + 100 + h] = sqrtf(fmaxf(a*a + b*b + c2*c2, 1e-8f));
    }
    gemm_rt<NT,32,16,16,3,16,16,false,false,false>(VHX, WV2s, nullptr, nullptr, VOA, tid);
    gemm_mma<NT,4,120,116,24,124,124,100,false,true>(BFAT, ws2, nullptr, BS2s, BFBT, WBUF, tid);
    for (int t = tid; t < 16 * 32; t += NT) {
      int o = t >> 5, e = t & 31;
      float a = VOA[o*32+e], b = VOA[(16+o)*32+e], c2 = VOA[(32+o)*32+e];
      float n = sqrtf(fmaxf(a*a + b*b + c2*c2, 1e-8f));
      float gt = 1.f / (1.f + expf(-n));
      VOA[o*32+e] = a*gt; VOA[(16+o)*32+e] = b*gt; VOA[(32+o)*32+e] = c2*gt;
    }
    __syncthreads();
    gemm_rt<NT,32,16,16,3,16,16,false,false,false>(VOA, WH3s, nullptr, nullptr, VHX, tid);
    __syncthreads();
    for (int t = tid; t < 16 * 32; t += NT) {
      int h = t >> 5, e = t & 31;
      float a = VHX[h*32+e], b = VHX[(16+h)*32+e], c2 = VHX[(32+h)*32+e];
      BFBT[e * 124 + 100 + h] = sqrtf(fmaxf(a*a + b*b + c2*c2, 1e-8f));
    }
    gemm_rt<NT,32,16,16,3,16,16,false,false,false>(VHX, WV3s, nullptr, nullptr, VOA, tid);
    gemm_mma<NT,4,120,116,24,124,124,100,false,false>(BFBT, ws3, nullptr, BS3s, BFAT, WBUF, tid);
    __syncthreads();
    for (int t = tid; t < 148; t += NT) {
      float acc = 0.f;
      if (t < 48) {
        #pragma unroll
        for (int ee = 0; ee < 32; ++ee) {
          int e = (ee + t) & 31;
          acc += MK[e] * VOA[t * 32 + e];
        }
      } else {
        int r = t - 48;
        #pragma unroll 8
        for (int e = 0; e < 30; ++e) acc += MK[e] * BFAT[e * 124 + r];
      }
      DH[t] = HS[t] + acc * (1.f / 30.f);
    }
    __syncthreads();
    if (tid < 32) {
      float vm = 0.f;
      if (tid < 16) { float a = DH[tid], b = DH[16+tid], c2 = DH[32+tid]; vm = fmaxf(a*a + b*b + c2*c2, 1e-8f); }
      #pragma unroll
      for (int o = 16; o; o >>= 1) vm += __shfl_xor_sync(0xffffffffu, vm, o);
      float s0 = DH[48+tid], s1 = DH[80+tid], s2v = DH[112+tid];
      float s3v = (tid < 4) ? DH[144+tid] : 0.f;
      float p = s0 + s1 + s2v + s3v;
      #pragma unroll
      for (int o = 16; o; o >>= 1) p += __shfl_xor_sync(0xffffffffu, p, o);
      float mu = p * 0.01f;
      float d0 = s0-mu, d1 = s1-mu, d2 = s2v-mu;
      float q = d0*d0 + d1*d1 + d2*d2;
      if (tid < 4) { float d3 = s3v - mu; q += d3*d3; }
      #pragma unroll
      for (int o = 16; o; o >>= 1) q += __shfl_xor_sync(0xffffffffu, q, o);
      if (tid == 0) { MISC[0] = rsqrtf(vm * (1.f/16.f)); MISC[1] = mu; MISC[2] = rsqrtf(q * 0.01f + 1e-3f); }
    }
    __syncthreads();
    for (int t = tid; t < 148; t += NT) {
      float v;
      if (t < 48) v = DH[t] * MISC[0];
      else { int j = t - 48; v = (DH[t] - MISC[1]) * MISC[2] * LG1[j] + LB1[j]; }
      g_hv[node * 148 + t] = v;
    }
    __syncthreads();
  }
}

// -------------------- K2: fused dh1+dh2+LN2 (16-node tiles, 512 thr) -------
#define DHT 512
__global__ __launch_bounds__(DHT, 2)
void k_dh(const float* __restrict__ wh1, const float* __restrict__ ws1g,
          const float* __restrict__ bs1, const float* __restrict__ wv1,
          const float* __restrict__ wh2, const float* __restrict__ ws2g,
          const float* __restrict__ bs2, const float* __restrict__ wv2,
          const float* __restrict__ ln2g, const float* __restrict__ ln2b,
          const int* __restrict__ maskV, float* __restrict__ out)
{
  extern __shared__ float sm[];
  float* WHs1 = sm;             // 512
  float* WVs1 = WHs1 + 512;     // 1024
  float* BSs1 = WVs1 + 1024;    // 400
  float* WHs2 = BSs1 + 400;     // 1024
  float* WVs2 = WHs2 + 1024;    // 512
  float* BSs2 = WVs2 + 512;     // 100
  float* VC1  = BSs2 + 100;     // 768
  float* SC1T = VC1 + 768;      // 2368
  float* VH   = SC1T + 2368;    // 1536
  float* VOd1 = VH + 1536;      // 1536
  float* SCT  = VOd1 + 1536;    // 6976
  float* VO2  = SCT + 6976;     // 768
  float* OT   = VO2 + 768;      // 1664
  float* ST   = OT + 1664;      // 80
  float* WBUF = ST + 80;        // 6528
  float* RES  = WBUF;           // [148][17] alias after MMAs done
  const int tid = threadIdx.x;
  const int n0 = blockIdx.x * 16;

  for (int i = tid; i < 512;  i += DHT) WHs1[i] = wh1[i];
  for (int i = tid; i < 1024; i += DHT) WVs1[i] = wv1[i];
  for (int i = tid; i < 400;  i += DHT) BSs1[i] = bs1[i];
  for (int i = tid; i < 1024; i += DHT) WHs2[i] = wh2[i];
  for (int i = tid; i < 512;  i += DHT) WVs2[i] = wv2[i];
  for (int i = tid; i < 100;  i += DHT) BSs2[i] = bs2[i];
  if (tid < 16) ST[48 + tid] = (float)maskV[n0 + tid];
  for (int idx = tid; idx < 48 * 16; idx += DHT) {
    int r = idx >> 4, e = idx & 15;
    VC1[r * 16 + e] = g_hv[(size_t)(n0 + e) * 148 + r];
  }
  for (int idx = tid; idx < 16 * 148; idx += DHT) {
    int e = idx / 148, j = idx - e * 148;
    SC1T[idx] = (j < 100) ? g_hv[(size_t)(n0 + e) * 148 + 48 + j] : 0.f;
  }
  __syncthreads();
  gemm_rt<DHT,16,16,32,3,16,32,false,false,false>(VC1, WHs1, nullptr, nullptr, VH, tid);
  __syncthreads();
  {
    int h = tid >> 4, e = tid & 15;
    float a = VH[h*16+e], b = VH[(32+h)*16+e], c2 = VH[(64+h)*16+e];
    SC1T[e * 148 + 100 + h] = sqrtf(fmaxf(a*a + b*b + c2*c2, 1e-8f));
  }
  gemm_rt<DHT,16,32,32,3,32,32,false,false,false>(VH, WVs1, nullptr, nullptr, VOd1, tid);
  gemm_mmaW<DHT,16,144,132,8,148,436,400,true>(SC1T, ws1g, BSs1, SCT, WBUF, tid);
  __syncthreads();
  {
    int o = tid >> 4, e = tid & 15;
    float a = VOd1[o*16+e], b = VOd1[(32+o)*16+e], c2 = VOd1[(64+o)*16+e];
    float n = sqrtf(fmaxf(a*a + b*b + c2*c2, 1e-8f));
    float gt = 1.f / (1.f + expf(-n));
    VOd1[o*16+e] = a*gt; VOd1[(32+o)*16+e] = b*gt; VOd1[(64+o)*16+e] = c2*gt;
  }
  __syncthreads();
  gemm_rt<DHT,16,32,32,3,32,32,false,false,false>(VOd1, WHs2, nullptr, nullptr, VH, tid);
  __syncthreads();
  {
    int h = tid >> 4, e = tid & 15;
    float a = VH[h*16+e], b = VH[(32+h)*16+e], c2 = VH[(64+h)*16+e];
    SCT[e * 436 + 400 + h] = sqrtf(fmaxf(a*a + b*b + c2*c2, 1e-8f));
  }
  gemm_rt<DHT,16,32,16,3,32,16,false,false,false>(VH, WVs2, nullptr, nullptr, VO2, tid);
  gemm_mma<DHT,16,432,432,24,436,104,100,false,false>(SCT, ws2g, nullptr, BSs2, OT, WBUF, tid);
  __syncthreads();
  for (int idx = tid; idx < 148 * 16; idx += DHT) {
    int r = idx >> 4, e = idx & 15;
    float add = (r < 48) ? VO2[r * 16 + e] : OT[e * 104 + (r - 48)];
    RES[r * 17 + e] = g_hv[(size_t)(n0 + e) * 148 + r] + add;
  }
  __syncthreads();
  if (tid < 16) {
    const int e = tid;
    float vm = 0.f;
    #pragma unroll
    for (int i = 0; i < 16; ++i) {
      float a = RES[i*17+e], b = RES[(16+i)*17+e], c2 = RES[(32+i)*17+e];
      vm += fmaxf(a*a + b*b + c2*c2, 1e-8f);
    }
    float mu = 0.f;
    #pragma unroll 4
    for (int j = 0; j < 100; ++j) mu += RES[(48+j)*17+e];
    mu *= 0.01f;
    float var = 0.f;
    #pragma unroll 4
    for (int j = 0; j < 100; ++j) { float d = RES[(48+j)*17+e] - mu; var += d*d; }
    var *= 0.01f;
    ST[e]    = rsqrtf(vm * (1.f/16.f));
    ST[16+e] = mu;
    ST[32+e] = rsqrtf(var + 1e-3f);
  }
  __syncthreads();
  for (int idx = tid; idx < 16 * 148; idx += DHT) {
    int e = idx / 148, r = idx - e * 148;
    float v = RES[r * 17 + e];
    if (r < 48) v = v * ST[e];
    else { int j = r - 48; v = (v - ST[16+e]) * ST[32+e] * ln2g[j] + ln2b[j]; }
    out[(size_t)(n0 + e) * 148 + r] = ST[48 + e] * v;
  }
}

// ---------------------------------------------------------------------------
extern "C" void kernel_launch(void* const* d_in, const int* in_sizes, int n_in,
                              void* d_out, int out_size)
{
  const float* hV      = (const float*)d_in[0];
  const float* hM      = (const float*)d_in[1];
  const int*   maskV   = (const int*)  d_in[2];
  const int*   maskA   = (const int*)  d_in[3];
  const float* wev1_wh = (const float*)d_in[4];
  const float* wev1_ws = (const float*)d_in[5];
  const float* wev1_bs = (const float*)d_in[6];
  const float* wev1_wv = (const float*)d_in[7];
  const float* wev2_wh = (const float*)d_in[8];
  const float* wev2_ws = (const float*)d_in[9];
  const float* wev2_bs = (const float*)d_in[10];
  const float* wev2_wv = (const float*)d_in[11];
  const float* wev3_wh = (const float*)d_in[12];
  const float* wev3_ws = (const float*)d_in[13];
  const float* wev3_bs = (const float*)d_in[14];
  const float* wev3_wv = (const float*)d_in[15];
  const float* wdh1_wh = (const float*)d_in[16];
  const float* wdh1_ws = (const float*)d_in[17];
  const float* wdh1_bs = (const float*)d_in[18];
  const float* wdh1_wv = (const float*)d_in[19];
  const float* wdh2_wh = (const float*)d_in[20];
  const float* wdh2_ws = (const float*)d_in[21];
  const float* wdh2_bs = (const float*)d_in[22];
  const float* wdh2_wv = (const float*)d_in[23];
  const float* ln1g = (const float*)d_in[24];
  const float* ln1b = (const float*)d_in[25];
  const float* ln2g = (const float*)d_in[26];
  const float* ln2b = (const float*)d_in[27];
  float* out = (float*)d_out;

  int dev = 0; cudaGetDevice(&dev);
  int sms = 148;
  cudaDeviceGetAttribute(&sms, cudaDevAttrMultiProcessorCount, dev);

  const size_t SMPRE = (size_t)(3456 + 10816 + 528 + 1536 + 104) * sizeof(float); // ~65.8 KB
  const size_t SM1   = (size_t)SM1_FLOATS * sizeof(float);                        // ~97.2 KB
  const size_t SMDH  = (size_t)(512+1024+400+1024+512+100+768+2368+1536+1536+6976+768+1664+80+6528) * sizeof(float); // ~100.8 KB

  cudaFuncSetAttribute(k_pre,  cudaFuncAttributeMaxDynamicSharedMemorySize, (int)SMPRE);
  cudaFuncSetAttribute(k_edge, cudaFuncAttributeMaxDynamicSharedMemorySize, (int)SM1);
  cudaFuncSetAttribute(k_dh,   cudaFuncAttributeMaxDynamicSharedMemorySize, (int)SMDH);

  k_pre <<<NODES / 32, NT, SMPRE>>>(hV, wev1_ws, wev1_wh);
  k_edge<<<2 * sms, NT, SM1>>>(hV, hM, maskA,
                               wev1_wh, wev1_ws, wev1_bs, wev1_wv,
                               wev2_wh, wev2_ws, wev2_bs, wev2_wv,
                               wev3_wh, wev3_ws, wev3_bs, wev3_wv,
                               ln1g, ln1b);
  k_dh<<<NODES / 16, DHT, SMDH>>>(wdh1_wh, wdh1_ws, wdh1_bs, wdh1_wv,
                                  wdh2_wh, wdh2_ws, wdh2_bs, wdh2_wv,
                                  ln2g, ln2b, maskV, out);
}

// round 11
// speedup vs baseline: 10.9644x; 1.0290x over previous
#include <cuda_runtime.h>
#include <cuda_pipeline.h>
#include <math.h>
#include <stdint.h>

#define NT 256
#define NTE 512
constexpr int NODES = 4 * 2048;

__device__ float g_hv[NODES * 148];
__device__ float g_sb[NODES * 100];
__device__ float g_vb[NODES * 108];

// ---------------- register-tiled GEMM, weights in SMEM ----------------------
template<int NTT,int COLS,int KD,int NROW,int NC,int ARS,int WSTR,bool INITF,bool BIASF,bool RELUF>
__device__ __forceinline__ void gemm_rt(
    const float* __restrict__ A, const float* __restrict__ W,
    const float* __restrict__ initv, const float* __restrict__ bias,
    float* __restrict__ O, const int tid)
{
  constexpr int GPC = NROW / 4;
  constexpr int G   = NC * GPC;
  constexpr int TPG = COLS / 4;
  const int eg = (tid & (TPG - 1)) * 4;
  for (int g = tid / TPG; g < G; g += NTT / TPG) {
    const int c  = g / GPC;
    const int rg = (g - c * GPC) * 4;
    float4 a0, a1, a2, a3;
    if (INITF) {
      const float* iv = initv + c * NROW + rg;
      a0 = make_float4(iv[0], iv[0], iv[0], iv[0]);
      a1 = make_float4(iv[1], iv[1], iv[1], iv[1]);
      a2 = make_float4(iv[2], iv[2], iv[2], iv[2]);
      a3 = make_float4(iv[3], iv[3], iv[3], iv[3]);
    } else {
      a0 = make_float4(0.f,0.f,0.f,0.f); a1 = a0; a2 = a0; a3 = a0;
    }
    const float* ap = A + (size_t)(c * ARS) * COLS + eg;
    const float* wp = W + rg;
    #pragma unroll 4
    for (int k = 0; k < KD; ++k) {
      const float4 av = *(const float4*)(ap + (size_t)k * COLS);
      const float4 wv4 = *(const float4*)(wp + (size_t)k * WSTR);
      a0.x += wv4.x*av.x; a0.y += wv4.x*av.y; a0.z += wv4.x*av.z; a0.w += wv4.x*av.w;
      a1.x += wv4.y*av.x; a1.y += wv4.y*av.y; a1.z += wv4.y*av.z; a1.w += wv4.y*av.w;
      a2.x += wv4.z*av.x; a2.y += wv4.z*av.y; a2.z += wv4.z*av.z; a2.w += wv4.z*av.w;
      a3.x += wv4.w*av.x; a3.y += wv4.w*av.y; a3.z += wv4.w*av.z; a3.w += wv4.w*av.w;
    }
    if (BIASF) {
      const float* bp = bias + c * NROW + rg;
      float b0=bp[0], b1=bp[1], b2=bp[2], b3=bp[3];
      a0.x+=b0; a0.y+=b0; a0.z+=b0; a0.w+=b0;
      a1.x+=b1; a1.y+=b1; a1.z+=b1; a1.w+=b1;
      a2.x+=b2; a2.y+=b2; a2.z+=b2; a2.w+=b2;
      a3.x+=b3; a3.y+=b3; a3.z+=b3; a3.w+=b3;
    }
    if (RELUF) {
      a0.x=fmaxf(a0.x,0.f); a0.y=fmaxf(a0.y,0.f); a0.z=fmaxf(a0.z,0.f); a0.w=fmaxf(a0.w,0.f);
      a1.x=fmaxf(a1.x,0.f); a1.y=fmaxf(a1.y,0.f); a1.z=fmaxf(a1.z,0.f); a1.w=fmaxf(a1.w,0.f);
      a2.x=fmaxf(a2.x,0.f); a2.y=fmaxf(a2.y,0.f); a2.z=fmaxf(a2.z,0.f); a2.w=fmaxf(a2.w,0.f);
      a3.x=fmaxf(a3.x,0.f); a3.y=fmaxf(a3.y,0.f); a3.z=fmaxf(a3.z,0.f); a3.w=fmaxf(a3.w,0.f);
    }
    float* op = O + (size_t)(c * NROW + rg) * COLS + eg;
    *(float4*)(op)          = a0;
    *(float4*)(op + COLS)   = a1;
    *(float4*)(op + 2*COLS) = a2;
    *(float4*)(op + 3*COLS) = a3;
  }
}

// -------------------- tf32 mma helpers -------------------------------------
__device__ __forceinline__ uint32_t f2tf(float x){
  uint32_t r; asm("cvt.rna.tf32.f32 %0, %1;" : "=r"(r) : "f"(x)); return r;
}
__device__ __forceinline__ void mma8(float* c, uint32_t a0,uint32_t a1,uint32_t a2,uint32_t a3,
                                     uint32_t b0,uint32_t b1){
  asm volatile("mma.sync.aligned.m16n8k8.row.col.f32.tf32.tf32.f32 "
    "{%0,%1,%2,%3}, {%4,%5,%6,%7}, {%8,%9}, {%0,%1,%2,%3};"
    : "+f"(c[0]),"+f"(c[1]),"+f"(c[2]),"+f"(c[3])
    : "r"(a0),"r"(a1),"r"(a2),"r"(a3),"r"(b0),"r"(b1));
}

// tf32 MMA GEMM, N=100: C^T[M][100] = As[M][KPAD] * W[KREAL][100]
// NQ warps per m-tile; M = 16*(warps/NQ). init indexed initv[(e0>>5)*ISTR + m].
template<int NTT,int NQ,int KPAD,int KREAL,int CH,int ASTR,int OSTR,int WSRC,int ISTR,bool INITF,bool RELUF>
__device__ __forceinline__ void gemm_mma(
    const float* __restrict__ As, const float* __restrict__ Wg,
    const float* __restrict__ initv, const float* __restrict__ bias,
    float* __restrict__ OT, float* __restrict__ wbuf, const int tid)
{
  constexpr int WS  = 104;
  constexpr int NCH = KPAD / CH;
  constexpr int T   = 13;
  constexpr int JMAX = (T + NQ - 1) / NQ;
  static_assert(KPAD % CH == 0 && CH % 8 == 0, "pad");
  const int lane = tid & 31;
  const int warp = tid >> 5;
  const int g  = lane >> 2;
  const int tq = lane & 3;
  const int mt = warp / NQ;
  const int q  = warp % NQ;
  float acc[JMAX][4];
  #pragma unroll
  for (int j=0;j<JMAX;++j){acc[j][0]=0.f;acc[j][1]=0.f;acc[j][2]=0.f;acc[j][3]=0.f;}

  auto stage = [&](int ch){
    float* db = wbuf + (ch & 1) * (CH * WS);
    const int base = ch * CH;
    for (int i = tid; i < CH*25; i += NTT) {
      int r = i / 25, c4 = i - r*25;
      int kr = base + r;
      if (kr < KREAL) __pipeline_memcpy_async(db + r*WS + c4*4, Wg + (size_t)kr*WSRC + c4*4, 16);
      else { float4 z = make_float4(0.f,0.f,0.f,0.f); *(float4*)(db + r*WS + c4*4) = z; }
    }
    __pipeline_commit();
  };
  stage(0);
  for (int ch = 0; ch < NCH; ++ch) {
    __pipeline_wait_prior(0);
    __syncthreads();
    if (ch + 1 < NCH) stage(ch + 1);
    const float* wb = wbuf + (ch & 1) * (CH * WS);
    const float* arow = As + (size_t)(mt*16 + g) * ASTR + ch*CH;
    #pragma unroll
    for (int k8 = 0; k8 < CH/8; ++k8) {
      const float* ar = arow + k8*8;
      uint32_t a0 = f2tf(ar[tq]);
      uint32_t a1 = f2tf(ar[8*ASTR + tq]);
      uint32_t a2 = f2tf(ar[tq + 4]);
      uint32_t a3 = f2tf(ar[8*ASTR + tq + 4]);
      const float* wrow = wb + (k8*8 + tq)*WS + g;
      #pragma unroll
      for (int j = 0; j < JMAX; ++j) {
        int tile = q + NQ*j;
        if (tile < T) {
          const float* wr = wrow + tile*8;
          uint32_t b0 = f2tf(wr[0]);
          uint32_t b1 = f2tf(wr[4*WS]);
          mma8(acc[j], a0,a1,a2,a3, b0,b1);
        }
      }
    }
  }
  const int e0 = mt*16 + g;
  const float* iv = INITF ? (initv + (e0 >> 5) * ISTR) : nullptr;
  #pragma unroll
  for (int j = 0; j < JMAX; ++j) {
    int tile = q + NQ*j;
    if (tile < T) {
      int mb = tile*8 + 2*tq;
      #pragma unroll
      for (int hf = 0; hf < 2; ++hf) {
        int m = mb + hf;
        if (m < 100) {
          float add = (INITF ? iv[m] : 0.f) + bias[m];
          float v0 = acc[j][hf]   + add;
          float v1 = acc[j][2+hf] + add;
          if (RELUF) { v0 = fmaxf(v0, 0.f); v1 = fmaxf(v1, 0.f); }
          OT[(size_t)e0 * OSTR + m]     = v0;
          OT[(size_t)(e0+8) * OSTR + m] = v1;
        }
      }
    }
  }
}

// tf32 MMA GEMM, wide N: C^T[M][N] = As[M][KPAD] * W[KREAL][N]
template<int NTT,int NQ,int KPAD,int KREAL,int CH,int ASTR,int OSTR,int N,bool RELUF>
__device__ __forceinline__ void gemm_mmaW(
    const float* __restrict__ As, const float* __restrict__ Wg,
    const float* __restrict__ bias,
    float* __restrict__ OT, float* __restrict__ wbuf, const int tid)
{
  constexpr int WS  = N + 8;
  constexpr int NCH = KPAD / CH;
  constexpr int T   = N / 8;
  constexpr int JMAX = (T + NQ - 1) / NQ;
  static_assert(KPAD % CH == 0 && CH % 8 == 0 && N % 8 == 0, "pad");
  const int lane = tid & 31;
  const int warp = tid >> 5;
  const int g  = lane >> 2;
  const int tq = lane & 3;
  const int mt = warp / NQ;
  const int q  = warp % NQ;
  float acc[JMAX][4];
  #pragma unroll
  for (int j=0;j<JMAX;++j){acc[j][0]=0.f;acc[j][1]=0.f;acc[j][2]=0.f;acc[j][3]=0.f;}

  auto stage = [&](int ch){
    float* db = wbuf + (ch & 1) * (CH * WS);
    const int base = ch * CH;
    constexpr int Q4 = N / 4;
    for (int i = tid; i < CH*Q4; i += NTT) {
      int r = i / Q4, c4 = i - r*Q4;
      int kr = base + r;
      if (kr < KREAL) __pipeline_memcpy_async(db + r*WS + c4*4, Wg + (size_t)kr*N + c4*4, 16);
      else { float4 z = make_float4(0.f,0.f,0.f,0.f); *(float4*)(db + r*WS + c4*4) = z; }
    }
    __pipeline_commit();
  };
  stage(0);
  for (int ch = 0; ch < NCH; ++ch) {
    __pipeline_wait_prior(0);
    __syncthreads();
    if (ch + 1 < NCH) stage(ch + 1);
    const float* wb = wbuf + (ch & 1) * (CH * WS);
    const float* arow = As + (size_t)(mt*16 + g) * ASTR + ch*CH;
    #pragma unroll
    for (int k8 = 0; k8 < CH/8; ++k8) {
      const float* ar = arow + k8*8;
      uint32_t a0 = f2tf(ar[tq]);
      uint32_t a1 = f2tf(ar[8*ASTR + tq]);
      uint32_t a2 = f2tf(ar[tq + 4]);
      uint32_t a3 = f2tf(ar[8*ASTR + tq + 4]);
      const float* wrow = wb + (k8*8 + tq)*WS + g;
      #pragma unroll
      for (int j = 0; j < JMAX; ++j) {
        int tile = q + NQ*j;
        if (tile < T) {
          const float* wr = wrow + tile*8;
          uint32_t b0 = f2tf(wr[0]);
          uint32_t b1 = f2tf(wr[4*WS]);
          mma8(acc[j], a0,a1,a2,a3, b0,b1);
        }
      }
    }
  }
  const int e0 = mt*16 + g;
  #pragma unroll
  for (int j = 0; j < JMAX; ++j) {
    int tile = q + NQ*j;
    if (tile < T) {
      int mb = tile*8 + 2*tq;
      #pragma unroll
      for (int hf = 0; hf < 2; ++hf) {
        int m = mb + hf;
        float b = bias[m];
        float v0 = acc[j][hf]   + b;
        float v1 = acc[j][2+hf] + b;
        if (RELUF) { v0 = fmaxf(v0, 0.f); v1 = fmaxf(v1, 0.f); }
        OT[(size_t)e0 * OSTR + m]     = v0;
        OT[(size_t)(e0+8) * OSTR + m] = v1;
      }
    }
  }
}

// ------------ K0: hoisted per-node partials (32-node MMA tiles) -------------
__global__ __launch_bounds__(NT)
void k_pre(const float* __restrict__ hV,
           const float* __restrict__ ws1, const float* __restrict__ wh1)
{
  extern __shared__ float sm[];
  float* As  = sm;            // [32][108]
  float* WB  = As + 3456;     // wbuf
  float* WH  = WB + 10816;    // 528
  float* HVv = WH + 528;      // [32][48]
  float* ZB  = HVv + 1536;    // 104
  const int tid = threadIdx.x;
  const int n0 = blockIdx.x * 32;

  for (int i = tid; i < 528; i += NT) WH[i] = wh1[i];
  for (int i = tid; i < 104; i += NT) ZB[i] = 0.f;
  for (int idx = tid; idx < 32 * 8; idx += NT) {
    int e = idx >> 3, j = idx & 7;
    As[e * 108 + 100 + j] = 0.f;
  }
  for (int idx = tid; idx < 32 * 148; idx += NT) {
    int e = idx / 148, r = idx - e * 148;
    float v = hV[(size_t)(n0 + e) * 148 + r];
    if (r < 48) HVv[e * 48 + r] = v;
    else        As[e * 108 + (r - 48)] = v;
  }
  __syncthreads();
  gemm_mma<NT,4,104,100,104,108,100,100,0,false,false>(
      As, ws1, nullptr, ZB, g_sb + (size_t)n0 * 100, WB, tid);
  for (int t = tid; t < 32 * 108; t += NT) {
    int e = t / 108, u = t - e * 108;
    int c = u / 36, h = u - c * 36;
    float acc = 0.f;
    if (h < 33) {
      #pragma unroll
      for (int i = 0; i < 16; ++i) acc += HVv[e * 48 + c * 16 + i] * WH[i * 33 + h];
    }
    g_vb[(size_t)(n0 + e) * 108 + u] = acc;
  }
}

// --------------- K1: edges + mean + LN1 (node PAIRS, 64-edge tiles) --------
#define O_WH1P 0
#define O_WV1  1188
#define O_BS1  1716
#define O_WH2  1816
#define O_WV2  2072
#define O_BS2  2328
#define O_WH3  2428
#define O_WV3  2684
#define O_BS3  2940
#define O_LG1  3040
#define O_LB1  3140
#define O_HS   3240   /* 296 */
#define O_MK   3536   /* 64 */
#define O_SB   3600   /* 200 */
#define O_VB   3800   /* 216 */
#define O_VC1  4016   /* 51*64 = 3264 */
#define O_SC1T 7280   /* [64][172] = 11008 */
#define O_VHX  18288  /* [108][64] = 6912 ; EBV alias */
#define O_BFAT 25200  /* [64][124] = 7936 */
#define O_VOA  33136  /* [48][64] = 3072 */
#define O_DH   36208  /* 296 */
#define O_MISC 36504  /* 16 */
#define O_WBUF 36520  /* 2*56*104 = 11648 */
#define SM1_FLOATS 48168

__global__ __launch_bounds__(NTE, 1)
void k_edge(const float* __restrict__ hV, const float* __restrict__ hM,
            const int* __restrict__ maskA,
            const float* __restrict__ wh1, const float* __restrict__ ws1,
            const float* __restrict__ bs1, const float* __restrict__ wv1,
            const float* __restrict__ wh2, const float* __restrict__ ws2,
            const float* __restrict__ bs2, const float* __restrict__ wv2,
            const float* __restrict__ wh3, const float* __restrict__ ws3,
            const float* __restrict__ bs3, const float* __restrict__ wv3,
            const float* __restrict__ ln1g, const float* __restrict__ ln1b)
{
  extern __shared__ float sm[];
  float* WH1P = sm + O_WH1P;
  float* WV1  = sm + O_WV1;
  float* BS1s = sm + O_BS1;
  float* WH2s = sm + O_WH2;
  float* WV2s = sm + O_WV2;
  float* BS2s = sm + O_BS2;
  float* WH3s = sm + O_WH3;
  float* WV3s = sm + O_WV3;
  float* BS3s = sm + O_BS3;
  float* LG1  = sm + O_LG1;
  float* LB1  = sm + O_LB1;
  float* HS   = sm + O_HS;
  float* MK   = sm + O_MK;
  float* SB   = sm + O_SB;
  float* VB   = sm + O_VB;
  float* VC1  = sm + O_VC1;
  float* SC1T = sm + O_SC1T;
  float* VHX  = sm + O_VHX;
  float* BFAT = sm + O_BFAT;
  float* BFBT = sm + O_SC1T;   // alias
  float* VOA  = sm + O_VOA;
  float* DH   = sm + O_DH;
  float* MISC = sm + O_MISC;
  float* WBUF = sm + O_WBUF;
  float* EBV  = sm + O_VHX;    // vector staging [2][30][51] = 3060 (fits VHX)
  const int tid = threadIdx.x;

  for (int i = tid; i < 1188; i += NTE) { int r = i / 36, c = i - r * 36; WH1P[i] = (c < 33) ? wh1[r * 33 + c] : 0.f; }
  for (int i = tid; i < 528;  i += NTE) WV1[i]  = wv1[i];
  for (int i = tid; i < 100;  i += NTE) { BS1s[i] = bs1[i]; BS2s[i] = bs2[i]; BS3s[i] = bs3[i]; LG1[i] = ln1g[i]; LB1[i] = ln1b[i]; }
  for (int i = tid; i < 256;  i += NTE) { WH2s[i] = wh2[i]; WV2s[i] = wv2[i]; WH3s[i] = wh3[i]; WV3s[i] = wv3[i]; }
  for (int i = tid; i < 3264;  i += NTE) VC1[i]  = 0.f;
  for (int i = tid; i < 11008; i += NTE) SC1T[i] = 0.f;
  for (int i = tid; i < 7936;  i += NTE) BFAT[i] = 0.f;
  for (int i = tid; i < 11648; i += NTE) WBUF[i] = 0.f;
  __syncthreads();

  for (int pair = blockIdx.x; pair < NODES / 2; pair += gridDim.x) {
    const float* mp = hM + (size_t)pair * 10980;
    // scalars direct -> SC1T (coalesced 132-runs)
    for (int idx = tid; idx < 2 * 30 * 132; idx += NTE) {
      int n = idx / 3960, rem = idx - n * 3960;
      int e = rem / 132, j = rem - e * 132;
      SC1T[(size_t)(n * 32 + e) * 172 + j] = mp[n * 5490 + e * 183 + 51 + j];
    }
    // vectors staged
    for (int idx = tid; idx < 2 * 30 * 51; idx += NTE) {
      int n = idx / 1530, rem = idx - n * 1530;
      EBV[idx] = mp[n * 5490 + (rem / 51) * 183 + (rem % 51)];
    }
    for (int t = tid; t < 296; t += NTE) HS[t] = hV[(size_t)pair * 296 + t];
    for (int t = tid; t < 200; t += NTE) SB[t] = g_sb[(size_t)pair * 200 + t];
    for (int t = tid; t < 216; t += NTE) VB[t] = g_vb[(size_t)pair * 216 + t];
    for (int t = tid; t < 64;  t += NTE) {
      int el = t & 31;
      MK[t] = (el < 30) ? (float)maskA[(size_t)(2 * pair + (t >> 5)) * 30 + el] : 0.f;
    }
    __syncthreads();
    // transpose vectors -> VC1 [51][64]
    for (int idx = tid; idx < 51 * 64; idx += NTE) {
      int j = idx >> 6, e = idx & 63;
      int n = e >> 5, el = e & 31;
      if (el < 30) VC1[j * 64 + e] = EBV[n * 1530 + el * 51 + j];
    }
    __syncthreads();
    // GVP1 vh (no init) then per-node VB add
    gemm_rt<NTE,64,17,36,3,17,36,false,false,false>(VC1, WH1P + 16 * 36, nullptr, nullptr, VHX, tid);
    __syncthreads();
    for (int idx = tid; idx < 108 * 64; idx += NTE) {
      int r = idx >> 6, e = idx & 63;
      VHX[idx] += VB[(e >> 5) * 108 + r];
    }
    __syncthreads();
    for (int t = tid; t < 33 * 64; t += NTE) {
      int h = t >> 6, e = t & 63;
      float a = VHX[h*64+e], b = VHX[(36+h)*64+e], c2 = VHX[(72+h)*64+e];
      SC1T[(size_t)e * 172 + 132 + h] = sqrtf(fmaxf(a*a + b*b + c2*c2, 1e-8f));
    }
    gemm_rt<NTE,64,33,16,3,36,16,false,false,false>(VHX, WV1, nullptr, nullptr, VOA, tid);
    gemm_mma<NTE,4,168,165,56,172,124,100,100,true,true>(SC1T, ws1 + 10000, SB, BS1s, BFAT, WBUF, tid);
    for (int t = tid; t < 16 * 64; t += NTE) {
      int o = t >> 6, e = t & 63;
      float a = VOA[o*64+e], b = VOA[(16+o)*64+e], c2 = VOA[(32+o)*64+e];
      float n = sqrtf(fmaxf(a*a + b*b + c2*c2, 1e-8f));
      float gt = 1.f / (1.f + expf(-n));
      VOA[o*64+e] = a*gt; VOA[(16+o)*64+e] = b*gt; VOA[(32+o)*64+e] = c2*gt;
    }
    __syncthreads();
    // GVP2
    gemm_rt<NTE,64,16,16,3,16,16,false,false,false>(VOA, WH2s, nullptr, nullptr, VHX, tid);
    __syncthreads();
    for (int t = tid; t < 16 * 64; t += NTE) {
      int h = t >> 6, e = t & 63;
      float a = VHX[h*64+e], b = VHX[(16+h)*64+e], c2 = VHX[(32+h)*64+e];
      BFAT[(size_t)e * 124 + 100 + h] = sqrtf(fmaxf(a*a + b*b + c2*c2, 1e-8f));
    }
    gemm_rt<NTE,64,16,16,3,16,16,false,false,false>(VHX, WV2s, nullptr, nullptr, VOA, tid);
    gemm_mma<NTE,4,120,116,40,124,124,100,0,false,true>(BFAT, ws2, nullptr, BS2s, BFBT, WBUF, tid);
    for (int t = tid; t < 16 * 64; t += NTE) {
      int o = t >> 6, e = t & 63;
      float a = VOA[o*64+e], b = VOA[(16+o)*64+e], c2 = VOA[(32+o)*64+e];
      float n = sqrtf(fmaxf(a*a + b*b + c2*c2, 1e-8f));
      float gt = 1.f / (1.f + expf(-n));
      VOA[o*64+e] = a*gt; VOA[(16+o)*64+e] = b*gt; VOA[(32+o)*64+e] = c2*gt;
    }
    __syncthreads();
    // GVP3
    gemm_rt<NTE,64,16,16,3,16,16,false,false,false>(VOA, WH3s, nullptr, nullptr, VHX, tid);
    __syncthreads();
    for (int t = tid; t < 16 * 64; t += NTE) {
      int h = t >> 6, e = t & 63;
      float a = VHX[h*64+e], b = VHX[(16+h)*64+e], c2 = VHX[(32+h)*64+e];
      BFBT[(size_t)e * 124 + 100 + h] = sqrtf(fmaxf(a*a + b*b + c2*c2, 1e-8f));
    }
    gemm_rt<NTE,64,16,16,3,16,16,false,false,false>(VHX, WV3s, nullptr, nullptr, VOA, tid);
    gemm_mma<NTE,4,120,116,40,124,124,100,0,false,false>(BFBT, ws3, nullptr, BS3s, BFAT, WBUF, tid);
    __syncthreads();
    // masked mean + residual (per node)
    for (int t = tid; t < 296; t += NTE) {
      int n = t / 148, r = t - n * 148;
      float acc = 0.f;
      if (r < 48) {
        #pragma unroll
        for (int ee = 0; ee < 32; ++ee) {
          int e = n * 32 + ((ee + r) & 31);
          acc += MK[e] * VOA[r * 64 + e];
        }
      } else {
        int rr = r - 48;
        #pragma unroll 6
        for (int e = 0; e < 30; ++e) acc += MK[n * 32 + e] * BFAT[(size_t)(n * 32 + e) * 124 + rr];
      }
      DH[t] = HS[t] + acc * (1.f / 30.f);
    }
    __syncthreads();
    if (tid < 64) {
      const int w = tid >> 5, lane = tid & 31;
      const float* D = DH + w * 148;
      float vm = 0.f;
      if (lane < 16) { float a = D[lane], b = D[16+lane], c2 = D[32+lane]; vm = fmaxf(a*a + b*b + c2*c2, 1e-8f); }
      #pragma unroll
      for (int o = 16; o; o >>= 1) vm += __shfl_xor_sync(0xffffffffu, vm, o);
      float s0 = D[48+lane], s1 = D[80+lane], s2v = D[112+lane];
      float s3v = (lane < 4) ? D[144+lane] : 0.f;
      float p = s0 + s1 + s2v + s3v;
      #pragma unroll
      for (int o = 16; o; o >>= 1) p += __shfl_xor_sync(0xffffffffu, p, o);
      float mu = p * 0.01f;
      float d0 = s0-mu, d1 = s1-mu, d2 = s2v-mu;
      float q = d0*d0 + d1*d1 + d2*d2;
      if (lane < 4) { float d3 = s3v - mu; q += d3*d3; }
      #pragma unroll
      for (int o = 16; o; o >>= 1) q += __shfl_xor_sync(0xffffffffu, q, o);
      if (lane == 0) {
        MISC[w*4+0] = rsqrtf(vm * (1.f/16.f));
        MISC[w*4+1] = mu;
        MISC[w*4+2] = rsqrtf(q * 0.01f + 1e-3f);
      }
    }
    __syncthreads();
    for (int t = tid; t < 296; t += NTE) {
      int n = t / 148, r = t - n * 148;
      float v = DH[t];
      if (r < 48) v = v * MISC[n*4];
      else { int j = r - 48; v = (v - MISC[n*4+1]) * MISC[n*4+2] * LG1[j] + LB1[j]; }
      g_hv[(size_t)pair * 296 + t] = v;
    }
    __syncthreads();
  }
}

// -------------------- K2: fused dh1+dh2+LN2 (16-node tiles, 512 thr) -------
#define DHT 512
__global__ __launch_bounds__(DHT, 2)
void k_dh(const float* __restrict__ wh1, const float* __restrict__ ws1g,
          const float* __restrict__ bs1, const float* __restrict__ wv1,
          const float* __restrict__ wh2, const float* __restrict__ ws2g,
          const float* __restrict__ bs2, const float* __restrict__ wv2,
          const float* __restrict__ ln2g, const float* __restrict__ ln2b,
          const int* __restrict__ maskV, float* __restrict__ out)
{
  extern __shared__ float sm[];
  float* WHs1 = sm;             // 512
  float* WVs1 = WHs1 + 512;     // 1024
  float* BSs1 = WVs1 + 1024;    // 400
  float* WHs2 = BSs1 + 400;     // 1024
  float* WVs2 = WHs2 + 1024;    // 512
  float* BSs2 = WVs2 + 512;     // 100
  float* VC1  = BSs2 + 100;     // 768
  float* SC1T = VC1 + 768;      // 2368
  float* VH   = SC1T + 2368;    // 1536
  float* VOd1 = VH + 1536;      // 1536
  float* SCT  = VOd1 + 1536;    // 6976
  float* VO2  = SCT + 6976;     // 768
  float* OT   = VO2 + 768;      // 1664
  float* ST   = OT + 1664;      // 80
  float* WBUF = ST + 80;        // 6528
  float* RES  = WBUF;           // [148][17] alias after MMAs done
  const int tid = threadIdx.x;
  const int n0 = blockIdx.x * 16;

  for (int i = tid; i < 512;  i += DHT) WHs1[i] = wh1[i];
  for (int i = tid; i < 1024; i += DHT) WVs1[i] = wv1[i];
  for (int i = tid; i < 400;  i += DHT) BSs1[i] = bs1[i];
  for (int i = tid; i < 1024; i += DHT) WHs2[i] = wh2[i];
  for (int i = tid; i < 512;  i += DHT) WVs2[i] = wv2[i];
  for (int i = tid; i < 100;  i += DHT) BSs2[i] = bs2[i];
  if (tid < 16) ST[48 + tid] = (float)maskV[n0 + tid];
  for (int idx = tid; idx < 48 * 16; idx += DHT) {
    int r = idx >> 4, e = idx & 15;
    VC1[r * 16 + e] = g_hv[(size_t)(n0 + e) * 148 + r];
  }
  for (int idx = tid; idx < 16 * 148; idx += DHT) {
    int e = idx / 148, j = idx - e * 148;
    SC1T[idx] = (j < 100) ? g_hv[(size_t)(n0 + e) * 148 + 48 + j] : 0.f;
  }
  __syncthreads();
  gemm_rt<DHT,16,16,32,3,16,32,false,false,false>(VC1, WHs1, nullptr, nullptr, VH, tid);
  __syncthreads();
  {
    int h = tid >> 4, e = tid & 15;
    float a = VH[h*16+e], b = VH[(32+h)*16+e], c2 = VH[(64+h)*16+e];
    SC1T[e * 148 + 100 + h] = sqrtf(fmaxf(a*a + b*b + c2*c2, 1e-8f));
  }
  gemm_rt<DHT,16,32,32,3,32,32,false,false,false>(VH, WVs1, nullptr, nullptr, VOd1, tid);
  gemm_mmaW<DHT,16,144,132,8,148,436,400,true>(SC1T, ws1g, BSs1, SCT, WBUF, tid);
  __syncthreads();
  {
    int o = tid >> 4, e = tid & 15;
    float a = VOd1[o*16+e], b = VOd1[(32+o)*16+e], c2 = VOd1[(64+o)*16+e];
    float n = sqrtf(fmaxf(a*a + b*b + c2*c2, 1e-8f));
    float gt = 1.f / (1.f + expf(-n));
    VOd1[o*16+e] = a*gt; VOd1[(32+o)*16+e] = b*gt; VOd1[(64+o)*16+e] = c2*gt;
  }
  __syncthreads();
  gemm_rt<DHT,16,32,32,3,32,32,false,false,false>(VOd1, WHs2, nullptr, nullptr, VH, tid);
  __syncthreads();
  {
    int h = tid >> 4, e = tid & 15;
    float a = VH[h*16+e], b = VH[(32+h)*16+e], c2 = VH[(64+h)*16+e];
    SCT[e * 436 + 400 + h] = sqrtf(fmaxf(a*a + b*b + c2*c2, 1e-8f));
  }
  gemm_rt<DHT,16,32,16,3,32,16,false,false,false>(VH, WVs2, nullptr, nullptr, VO2, tid);
  gemm_mma<DHT,16,432,432,24,436,104,100,0,false,false>(SCT, ws2g, nullptr, BSs2, OT, WBUF, tid);
  __syncthreads();
  for (int idx = tid; idx < 148 * 16; idx += DHT) {
    int r = idx >> 4, e = idx & 15;
    float add = (r < 48) ? VO2[r * 16 + e] : OT[e * 104 + (r - 48)];
    RES[r * 17 + e] = g_hv[(size_t)(n0 + e) * 148 + r] + add;
  }
  __syncthreads();
  if (tid < 16) {
    const int e = tid;
    float vm = 0.f;
    #pragma unroll
    for (int i = 0; i < 16; ++i) {
      float a = RES[i*17+e], b = RES[(16+i)*17+e], c2 = RES[(32+i)*17+e];
      vm += fmaxf(a*a + b*b + c2*c2, 1e-8f);
    }
    float mu = 0.f;
    #pragma unroll 4
    for (int j = 0; j < 100; ++j) mu += RES[(48+j)*17+e];
    mu *= 0.01f;
    float var = 0.f;
    #pragma unroll 4
    for (int j = 0; j < 100; ++j) { float d = RES[(48+j)*17+e] - mu; var += d*d; }
    var *= 0.01f;
    ST[e]    = rsqrtf(vm * (1.f/16.f));
    ST[16+e] = mu;
    ST[32+e] = rsqrtf(var + 1e-3f);
  }
  __syncthreads();
  for (int idx = tid; idx < 16 * 148; idx += DHT) {
    int e = idx / 148, r = idx - e * 148;
    float v = RES[r * 17 + e];
    if (r < 48) v = v * ST[e];
    else { int j = r - 48; v = (v - ST[16+e]) * ST[32+e] * ln2g[j] + ln2b[j]; }
    out[(size_t)(n0 + e) * 148 + r] = ST[48 + e] * v;
  }
}

// ---------------------------------------------------------------------------
extern "C" void kernel_launch(void* const* d_in, const int* in_sizes, int n_in,
                              void* d_out, int out_size)
{
  const float* hV      = (const float*)d_in[0];
  const float* hM      = (const float*)d_in[1];
  const int*   maskV   = (const int*)  d_in[2];
  const int*   maskA   = (const int*)  d_in[3];
  const float* wev1_wh = (const float*)d_in[4];
  const float* wev1_ws = (const float*)d_in[5];
  const float* wev1_bs = (const float*)d_in[6];
  const float* wev1_wv = (const float*)d_in[7];
  const float* wev2_wh = (const float*)d_in[8];
  const float* wev2_ws = (const float*)d_in[9];
  const float* wev2_bs = (const float*)d_in[10];
  const float* wev2_wv = (const float*)d_in[11];
  const float* wev3_wh = (const float*)d_in[12];
  const float* wev3_ws = (const float*)d_in[13];
  const float* wev3_bs = (const float*)d_in[14];
  const float* wev3_wv = (const float*)d_in[15];
  const float* wdh1_wh = (const float*)d_in[16];
  const float* wdh1_ws = (const float*)d_in[17];
  const float* wdh1_bs = (const float*)d_in[18];
  const float* wdh1_wv = (const float*)d_in[19];
  const float* wdh2_wh = (const float*)d_in[20];
  const float* wdh2_ws = (const float*)d_in[21];
  const float* wdh2_bs = (const float*)d_in[22];
  const float* wdh2_wv = (const float*)d_in[23];
  const float* ln1g = (const float*)d_in[24];
  const float* ln1b = (const float*)d_in[25];
  const float* ln2g = (const float*)d_in[26];
  const float* ln2b = (const float*)d_in[27];
  float* out = (float*)d_out;

  int dev = 0; cudaGetDevice(&dev);
  int sms = 148;
  cudaDeviceGetAttribute(&sms, cudaDevAttrMultiProcessorCount, dev);

  const size_t SMPRE = (size_t)(3456 + 10816 + 528 + 1536 + 104) * sizeof(float); // ~65.8 KB
  const size_t SM1   = (size_t)SM1_FLOATS * sizeof(float);                        // ~192.7 KB
  const size_t SMDH  = (size_t)(512+1024+400+1024+512+100+768+2368+1536+1536+6976+768+1664+80+6528) * sizeof(float); // ~100.8 KB

  cudaFuncSetAttribute(k_pre,  cudaFuncAttributeMaxDynamicSharedMemorySize, (int)SMPRE);
  cudaFuncSetAttribute(k_edge, cudaFuncAttributeMaxDynamicSharedMemorySize, (int)SM1);
  cudaFuncSetAttribute(k_dh,   cudaFuncAttributeMaxDynamicSharedMemorySize, (int)SMDH);

  k_pre <<<NODES / 32, NT, SMPRE>>>(hV, wev1_ws, wev1_wh);
  k_edge<<<sms, NTE, SM1>>>(hV, hM, maskA,
                            wev1_wh, wev1_ws, wev1_bs, wev1_wv,
                            wev2_wh, wev2_ws, wev2_bs, wev2_wv,
                            wev3_wh, wev3_ws, wev3_bs, wev3_wv,
                            ln1g, ln1b);
  k_dh<<<NODES / 16, DHT, SMDH>>>(wdh1_wh, wdh1_ws, wdh1_bs, wdh1_wv,
                                  wdh2_wh, wdh2_ws, wdh2_bs, wdh2_wv,
                                  ln2g, ln2b, maskV, out);
}